// round 12
// baseline (speedup 1.0000x reference)
#include <cuda_runtime.h>
#include <cuda_bf16.h>
#include <cstdint>
#include <math.h>

typedef unsigned long long ull;

__device__ float g_A1[64*64];
__device__ float g_A2[64*64];
__device__ __nv_bfloat16 g_hencH[4096UL*256*32];
__device__ __nv_bfloat16 g_hencL[4096UL*256*32];
__device__ __nv_bfloat16 g_h0H[4096UL*256*128];
__device__ __nv_bfloat16 g_h0L[4096UL*256*128];
__device__ __nv_bfloat16 g_W1hi[192*128];
__device__ __nv_bfloat16 g_W1lo[192*128];
__device__ __nv_bfloat16 g_W0hi[384*32];
__device__ __nv_bfloat16 g_W0lo[384*32];
__device__ float g_xg0[2UL*4096*256*192];
__device__ float g_xg1[4096UL*256*192];
__device__ float g_last[4096*128];
__device__ float g_dxg[64*256];
__device__ float g_h1d[64UL*256*64];

__device__ __forceinline__ void fma2(ull &acc, ull a, ull b){
    asm("fma.rn.f32x2 %0, %1, %2, %0;" : "+l"(acc) : "l"(a), "l"(b));
}
__device__ __forceinline__ float hsum2(ull a){
    float lo, hi; asm("mov.b64 {%0,%1}, %2;" : "=f"(lo), "=f"(hi) : "l"(a));
    return lo + hi;
}
__device__ __forceinline__ float sigf(float x){
    return __fdividef(1.f, 1.f + __expf(-x));
}
__device__ __forceinline__ float tanf_(float x){
    return __fmaf_rn(2.f, __fdividef(1.f, 1.f + __expf(-2.f*x)), -1.f);
}

__global__ void k_softmax(const float* __restrict__ adj1, const float* __restrict__ adj2){
    int i = threadIdx.x;
    for (int w = 0; w < 2; w++){
        const float* a = w ? adj2 : adj1;
        float* o = w ? g_A2 : g_A1;
        float mx = -1e30f;
        for (int j = 0; j < 64; j++) mx = fmaxf(mx, a[i*64+j]);
        float s = 0.f;
        for (int j = 0; j < 64; j++) s += expf(a[i*64+j] - mx);
        float inv = 1.f / s;
        for (int j = 0; j < 64; j++) o[i*64+j] = expf(a[i*64+j] - mx) * inv;
    }
}

__global__ void k_prepW(const float* __restrict__ W1, const float* __restrict__ W0){
    for (int i = threadIdx.x; i < 24576; i += 256){
        float v = W1[i];
        __nv_bfloat16 hi = __float2bfloat16(v);
        g_W1hi[i] = hi; g_W1lo[i] = __float2bfloat16(v - __bfloat162float(hi));
    }
    for (int i = threadIdx.x; i < 12288; i += 256){
        float v = W0[i];
        __nv_bfloat16 hi = __float2bfloat16(v);
        g_W0hi[i] = hi; g_W0lo[i] = __float2bfloat16(v - __bfloat162float(hi));
    }
}

__global__ __launch_bounds__(256) void k_gnn(
    const float* __restrict__ x,
    const float* __restrict__ W1, const float* __restrict__ b1,
    const float* __restrict__ W2, const float* __restrict__ b2,
    const float* __restrict__ lng, const float* __restrict__ lnb)
{
    int bt = blockIdx.x;
    int b = bt >> 8, t = bt & 255;
    int tid = threadIdx.x;

    __shared__ float sA2[64*65];
    __shared__ float sW2t[1024];
    __shared__ __align__(16) float sx[64];
    __shared__ float s1[64];
    __shared__ __align__(16) float sh1[2048];
    __shared__ __align__(16) float sagg[2048];
    __shared__ float sh2[64*33];
    __shared__ float sW1[32], sb1[32], sb2[32], slg[32], slb[32];
    __shared__ float smean[64], srstd[64];

    for (int i = tid; i < 4096; i += 256) sA2[(i>>6)*65 + (i&63)] = g_A2[i];
    for (int i = tid; i < 1024; i += 256){ int gp = i>>5, k = i&31; sW2t[k*32+gp] = W2[i]; }
    if (tid < 64) sx[tid] = x[(size_t)bt*64 + tid];
    if (tid < 32){ sW1[tid]=W1[tid]; sb1[tid]=b1[tid]; sb2[tid]=b2[tid]; slg[tid]=lng[tid]; slb[tid]=lnb[tid]; }
    __syncthreads();

    if (tid < 64){
        float s = 0.f; const float* a = g_A1 + tid*64;
        #pragma unroll 8
        for (int j = 0; j < 64; j++) s += a[j]*sx[j];
        s1[tid] = s;
    }
    __syncthreads();
    for (int i = tid; i < 2048; i += 256){ int j = i>>5, g = i&31; sh1[i] = fmaxf(sW1[g]*s1[j] + sb1[g], 0.f); }
    __syncthreads();
    {
        int i = tid >> 2, g0 = (tid & 3) * 8;
        float4 a0 = {0,0,0,0}, a1 = {0,0,0,0};
        #pragma unroll 4
        for (int j = 0; j < 64; j++){
            float a = sA2[i*65 + j];
            float4 h0 = *(const float4*)(sh1 + j*32 + g0);
            float4 h1 = *(const float4*)(sh1 + j*32 + g0 + 4);
            a0.x += a*h0.x; a0.y += a*h0.y; a0.z += a*h0.z; a0.w += a*h0.w;
            a1.x += a*h1.x; a1.y += a*h1.y; a1.z += a*h1.z; a1.w += a*h1.w;
        }
        *(float4*)(sagg + i*32 + g0)     = a0;
        *(float4*)(sagg + i*32 + g0 + 4) = a1;
    }
    __syncthreads();
    #pragma unroll
    for (int q = 0; q < 8; q++){
        int idx = tid + (q << 8);
        int i = idx >> 5, gp = idx & 31;
        float acc = sb2[gp];
        #pragma unroll 8
        for (int k = 0; k < 32; k++) acc += sagg[i*32 + k] * sW2t[k*32 + gp];
        sh2[i*33 + gp] = fmaxf(acc, 0.f);
    }
    __syncthreads();
    if (tid < 64){
        float m = 0.f;
        for (int g = 0; g < 32; g++) m += sh2[tid*33 + g];
        m *= (1.f/32.f);
        float v = 0.f;
        for (int g = 0; g < 32; g++){ float d = sh2[tid*33 + g] - m; v += d*d; }
        v *= (1.f/32.f);
        smean[tid] = m; srstd[tid] = rsqrtf(v + 1e-5f);
    }
    __syncthreads();
    for (int idx = tid; idx < 2048; idx += 256){
        int i = idx >> 5, g = idx & 31;
        float val = (sh2[i*33 + g] - smean[i]) * srstd[i] * slg[g] + slb[g];
        size_t o = (((size_t)b*64 + i)*256 + t)*32 + g;
        __nv_bfloat16 hi = __float2bfloat16(val);
        g_hencH[o] = hi;
        g_hencL[o] = __float2bfloat16(val - __bfloat162float(hi));
    }
}

// ---- mma GEMM: xg0 = henc @ Wih0^T ----
__global__ __launch_bounds__(256,2) void k_xproj0(){
    __shared__ uint32_t sA[2][16*20];
    int tid = threadIdx.x;
    int w = tid >> 5, lane = tid & 31;
    int g = lane >> 2, tig = lane & 3;
    size_t Rbase = (size_t)blockIdx.x * 1024;

    uint32_t bh[6][2][2];
    #pragma unroll
    for (int nt = 0; nt < 6; nt++){
        int n = w*48 + nt*8 + g;
        const uint32_t* wp = (const uint32_t*)g_W0hi + n*16;
        #pragma unroll
        for (int ks = 0; ks < 2; ks++){
            bh[nt][ks][0] = wp[ks*8 + tig];
            bh[nt][ks][1] = wp[ks*8 + 4 + tig];
        }
    }
    const uint32_t* blo = (const uint32_t*)g_W0lo;
    const uint32_t* hH = (const uint32_t*)g_hencH;
    const uint32_t* hL = (const uint32_t*)g_hencL;

    for (int mt = 0; mt < 64; mt++){
        size_t R = Rbase + mt*16;
        __syncthreads();
        for (int i = tid; i < 256; i += 256){
            int row = i >> 4, c = i & 15;
            sA[0][row*20 + c] = hH[(R+row)*16 + c];
            sA[1][row*20 + c] = hL[(R+row)*16 + c];
        }
        __syncthreads();
        float acc[6][4];
        #pragma unroll
        for (int nt=0;nt<6;nt++){ acc[nt][0]=0.f; acc[nt][1]=0.f; acc[nt][2]=0.f; acc[nt][3]=0.f; }
        #pragma unroll
        for (int term = 0; term < 3; term++){
            const uint32_t* As = sA[term == 1 ? 1 : 0];
            #pragma unroll
            for (int ks = 0; ks < 2; ks++){
                uint32_t a0 = As[g*20 + ks*8 + tig];
                uint32_t a1 = As[(g+8)*20 + ks*8 + tig];
                uint32_t a2 = As[g*20 + ks*8 + 4 + tig];
                uint32_t a3 = As[(g+8)*20 + ks*8 + 4 + tig];
                #pragma unroll
                for (int nt = 0; nt < 6; nt++){
                    uint32_t b0, b1;
                    if (term < 2){ b0 = bh[nt][ks][0]; b1 = bh[nt][ks][1]; }
                    else {
                        int n = w*48 + nt*8 + g;
                        b0 = __ldg(blo + n*16 + ks*8 + tig);
                        b1 = __ldg(blo + n*16 + ks*8 + 4 + tig);
                    }
                    asm volatile(
                        "mma.sync.aligned.m16n8k16.row.col.f32.bf16.bf16.f32 "
                        "{%0,%1,%2,%3}, {%4,%5,%6,%7}, {%8,%9}, {%0,%1,%2,%3};"
                        : "+f"(acc[nt][0]), "+f"(acc[nt][1]), "+f"(acc[nt][2]), "+f"(acc[nt][3])
                        : "r"(a0), "r"(a1), "r"(a2), "r"(a3), "r"(b0), "r"(b1));
                }
            }
        }
        #pragma unroll
        for (int nt = 0; nt < 6; nt++){
            int col = w*48 + nt*8 + tig*2;
            int dir = col >= 192;
            int lc = col - dir*192;
            float* base = g_xg0 + (size_t)dir*201326592;
            *(float2*)(base + (R+g)*192 + lc)   = make_float2(acc[nt][0], acc[nt][1]);
            *(float2*)(base + (R+g+8)*192 + lc) = make_float2(acc[nt][2], acc[nt][3]);
        }
    }
}

// ---- BiGRU layer 0: hidden recurrence only, 8 seqs per CTA, 3 CTAs/SM ----
__global__ __launch_bounds__(192,3) void k_gru0h(
    const float* __restrict__ Whh, const float* __restrict__ bih, const float* __restrict__ bhh)
{
    int n0 = blockIdx.x * 8, dir = blockIdx.y;
    int g = threadIdx.x;
    __shared__ __align__(16) float sh[8][64];
    __shared__ float sgi[8][192], sgh[8][192];

    ull wh[32];
    const ull* p = (const ull*)(Whh + ((size_t)dir*192 + g)*64);
    #pragma unroll
    for (int k = 0; k < 32; k++) wh[k] = p[k];
    float bi = bih[dir*192 + g], bh = bhh[dir*192 + g];

    for (int u = g; u < 512; u += 192) sh[u>>6][u&63] = 0.f;
    __syncthreads();

    const float* xgb = g_xg0 + (size_t)dir*201326592;
    int t0 = dir ? 255 : 0;
    float xr[8];
    #pragma unroll
    for (int q = 0; q < 8; q++) xr[q] = xgb[((size_t)(n0+q)*256 + t0)*192 + g];

    for (int s = 0; s < 256; s++){
        int t = dir ? 255 - s : s;
        #pragma unroll
        for (int q = 0; q < 8; q++) sgi[q][g] = xr[q] + bi;
        if (s < 255){
            int tn = dir ? 254 - s : s + 1;
            #pragma unroll
            for (int q = 0; q < 8; q++) xr[q] = xgb[((size_t)(n0+q)*256 + tn)*192 + g];
        }
        #pragma unroll
        for (int q = 0; q < 8; q++){
            const ulonglong2* h4 = (const ulonglong2*)sh[q];
            ull b0 = 0, b1 = 0;
            #pragma unroll
            for (int k = 0; k < 16; k++){ ulonglong2 v = h4[k]; fma2(b0, wh[2*k], v.x); fma2(b1, wh[2*k+1], v.y); }
            sgh[q][g] = hsum2(b0) + hsum2(b1) + bh;
        }
        __syncthreads();
        for (int u = g; u < 512; u += 192){
            int q = u >> 6, hh = u & 63;
            float r  = sigf(sgi[q][hh] + sgh[q][hh]);
            float z  = sigf(sgi[q][64+hh] + sgh[q][64+hh]);
            float nn = tanf_(sgi[q][128+hh] + r*sgh[q][128+hh]);
            float h  = (1.f - z)*nn + z*sh[q][hh];
            sh[q][hh] = h;
            __nv_bfloat16 hi = __float2bfloat16(h);
            __nv_bfloat16 lo = __float2bfloat16(h - __bfloat162float(hi));
            size_t idx = ((size_t)(n0+q)*256 + t)*128 + dir*64 + hh;
            g_h0H[idx] = hi; g_h0L[idx] = lo;
        }
        __syncthreads();
    }
}

// ---- mma GEMM: xg1 = h0 @ Wih1^T ----
__global__ __launch_bounds__(256,2) void k_xproj1(){
    __shared__ uint32_t sA[2][16*68];
    int tid = threadIdx.x;
    int w = tid >> 5, lane = tid & 31;
    int g = lane >> 2, tig = lane & 3;
    size_t Rbase = (size_t)blockIdx.x * 1024;

    uint32_t bh[3][8][2];
    #pragma unroll
    for (int nt = 0; nt < 3; nt++){
        int n = w*24 + nt*8 + g;
        const uint32_t* wp = (const uint32_t*)g_W1hi + n*64;
        #pragma unroll
        for (int ks = 0; ks < 8; ks++){
            bh[nt][ks][0] = wp[ks*8 + tig];
            bh[nt][ks][1] = wp[ks*8 + 4 + tig];
        }
    }
    const uint32_t* blo = (const uint32_t*)g_W1lo;
    const uint32_t* h0Hu = (const uint32_t*)g_h0H;
    const uint32_t* h0Lu = (const uint32_t*)g_h0L;

    for (int mt = 0; mt < 64; mt++){
        size_t R = Rbase + mt*16;
        __syncthreads();
        for (int i = tid; i < 1024; i += 256){
            int row = i >> 6, c = i & 63;
            sA[0][row*68 + c] = h0Hu[(R+row)*64 + c];
            sA[1][row*68 + c] = h0Lu[(R+row)*64 + c];
        }
        __syncthreads();
        float acc[3][4];
        #pragma unroll
        for (int nt=0;nt<3;nt++){ acc[nt][0]=0.f; acc[nt][1]=0.f; acc[nt][2]=0.f; acc[nt][3]=0.f; }
        #pragma unroll
        for (int term = 0; term < 3; term++){
            const uint32_t* As = sA[term == 1 ? 1 : 0];
            #pragma unroll
            for (int ks = 0; ks < 8; ks++){
                uint32_t a0 = As[g*68 + ks*8 + tig];
                uint32_t a1 = As[(g+8)*68 + ks*8 + tig];
                uint32_t a2 = As[g*68 + ks*8 + 4 + tig];
                uint32_t a3 = As[(g+8)*68 + ks*8 + 4 + tig];
                #pragma unroll
                for (int nt = 0; nt < 3; nt++){
                    uint32_t b0, b1;
                    if (term < 2){ b0 = bh[nt][ks][0]; b1 = bh[nt][ks][1]; }
                    else {
                        int n = w*24 + nt*8 + g;
                        b0 = __ldg(blo + n*64 + ks*8 + tig);
                        b1 = __ldg(blo + n*64 + ks*8 + 4 + tig);
                    }
                    asm volatile(
                        "mma.sync.aligned.m16n8k16.row.col.f32.bf16.bf16.f32 "
                        "{%0,%1,%2,%3}, {%4,%5,%6,%7}, {%8,%9}, {%0,%1,%2,%3};"
                        : "+f"(acc[nt][0]), "+f"(acc[nt][1]), "+f"(acc[nt][2]), "+f"(acc[nt][3])
                        : "r"(a0), "r"(a1), "r"(a2), "r"(a3), "r"(b0), "r"(b1));
                }
            }
        }
        #pragma unroll
        for (int nt = 0; nt < 3; nt++){
            int col = w*24 + nt*8 + tig*2;
            *(float2*)(g_xg1 + (R+g)*192 + col)   = make_float2(acc[nt][0], acc[nt][1]);
            *(float2*)(g_xg1 + (R+g+8)*192 + col) = make_float2(acc[nt][2], acc[nt][3]);
        }
    }
}

// ---- GRU layer 1 fwd, hidden recurrence only, 8 seqs per CTA, 3 CTAs/SM ----
__global__ __launch_bounds__(192,3) void k_gru1h(
    const float* __restrict__ Whh, const float* __restrict__ bih, const float* __restrict__ bhh)
{
    int n0 = blockIdx.x * 8;
    int g = threadIdx.x;
    __shared__ __align__(16) float sh[8][64];
    __shared__ float sgi[8][192], sgh[8][192];

    ull wh[32];
    const ull* p = (const ull*)(Whh + (size_t)g*64);
    #pragma unroll
    for (int k = 0; k < 32; k++) wh[k] = p[k];
    float bi = bih[g], bh = bhh[g];

    for (int u = g; u < 512; u += 192) sh[u>>6][u&63] = 0.f;
    __syncthreads();

    float xr[8];
    #pragma unroll
    for (int q = 0; q < 8; q++) xr[q] = g_xg1[((size_t)(n0+q)*256)*192 + g];

    for (int t = 0; t < 256; t++){
        #pragma unroll
        for (int q = 0; q < 8; q++) sgi[q][g] = xr[q] + bi;
        if (t < 255){
            #pragma unroll
            for (int q = 0; q < 8; q++) xr[q] = g_xg1[((size_t)(n0+q)*256 + t + 1)*192 + g];
        }
        #pragma unroll
        for (int q = 0; q < 8; q++){
            const ulonglong2* h4 = (const ulonglong2*)sh[q];
            ull b0 = 0, b1 = 0;
            #pragma unroll
            for (int k = 0; k < 16; k++){ ulonglong2 v = h4[k]; fma2(b0, wh[2*k], v.x); fma2(b1, wh[2*k+1], v.y); }
            sgh[q][g] = hsum2(b0) + hsum2(b1) + bh;
        }
        __syncthreads();
        for (int u = g; u < 512; u += 192){
            int q = u >> 6, hh = u & 63;
            float r  = sigf(sgi[q][hh] + sgh[q][hh]);
            float z  = sigf(sgi[q][64+hh] + sgh[q][64+hh]);
            float nn = tanf_(sgi[q][128+hh] + r*sgh[q][128+hh]);
            float h  = (1.f - z)*nn + z*sh[q][hh];
            sh[q][hh] = h;
            if (t == 255) g_last[(n0+q)*128 + hh] = h;
        }
        __syncthreads();
    }
}

__global__ __launch_bounds__(192,2) void k_gru1b(
    const float* __restrict__ Wih, const float* __restrict__ Whh,
    const float* __restrict__ bih, const float* __restrict__ bhh)
{
    int tid = threadIdx.x;
    __shared__ __align__(16) float sx[128];
    __shared__ float sgi[192];
    ull w[64];
    const ull* p = (const ull*)(Wih + 192UL*128 + (size_t)tid*128);
    #pragma unroll
    for (int k = 0; k < 64; k++) w[k] = p[k];
    float bias = bih[192 + tid];

    for (int it = 0; it < 64; it++){
        int n = blockIdx.x*64 + it;
        if (tid < 128){
            size_t idx = ((size_t)n*256 + 255)*128 + tid;
            sx[tid] = __bfloat162float(g_h0H[idx]) + __bfloat162float(g_h0L[idx]);
        }
        __syncthreads();
        ull a0 = 0, a1 = 0;
        const ulonglong2* v4 = (const ulonglong2*)sx;
        #pragma unroll
        for (int k = 0; k < 32; k++){ ulonglong2 v = v4[k]; fma2(a0, w[2*k], v.x); fma2(a1, w[2*k+1], v.y); }
        sgi[tid] = hsum2(a0) + hsum2(a1) + bias;
        __syncthreads();
        if (tid < 64){
            float r  = sigf(sgi[tid]      + bhh[192 + tid]);
            float z  = sigf(sgi[64 + tid] + bhh[192 + 64 + tid]);
            float nn = tanf_(sgi[128+tid] + r * bhh[192 + 128 + tid]);
            g_last[n*128 + 64 + tid] = (1.f - z)*nn;
        }
    }
}

__global__ __launch_bounds__(128) void k_head(
    const float* __restrict__ pool_W, const float* __restrict__ pool_b,
    const float* __restrict__ mu_W, const float* __restrict__ mu_b,
    const float* __restrict__ logv_W, const float* __restrict__ logv_b,
    const float* __restrict__ dec_W, const float* __restrict__ dec_b,
    const float* __restrict__ lstm_Wih, const float* __restrict__ lstm_bih,
    const float* __restrict__ lstm_bhh,
    float* __restrict__ out)
{
    int b = blockIdx.x, tid = threadIdx.x;
    __shared__ float slast[128], shp[32], smu[32], sdh[64];
    float s = 0.f;
    for (int c = 0; c < 64; c++) s += g_last[(b*64 + c)*128 + tid];
    slast[tid] = s * (1.f/64.f);
    __syncthreads();
    if (tid < 32){
        float acc = pool_b[tid];
        for (int k = 0; k < 128; k++) acc += pool_W[tid*128 + k] * slast[k];
        shp[tid] = fmaxf(acc, 0.f);
    }
    __syncthreads();
    if (tid < 32){
        float acc = mu_b[tid];
        for (int k = 0; k < 32; k++) acc += mu_W[tid*32 + k] * shp[k];
        smu[tid] = acc;
        out[64UL*256*64 + b*32 + tid] = acc;
    } else if (tid < 64){
        int j = tid - 32;
        float acc = logv_b[j];
        for (int k = 0; k < 32; k++) acc += logv_W[j*32 + k] * shp[k];
        out[64UL*256*64 + 2048 + b*32 + j] = acc;
    }
    __syncthreads();
    if (tid < 64){
        float acc = dec_b[tid];
        for (int k = 0; k < 32; k++) acc += dec_W[tid*32 + k] * smu[k];
        sdh[tid] = fmaxf(acc, 0.f);
    }
    __syncthreads();
    for (int gate = tid; gate < 256; gate += 128){
        float acc = lstm_bih[gate] + lstm_bhh[gate];
        for (int k = 0; k < 64; k++) acc += lstm_Wih[gate*64 + k] * sdh[k];
        g_dxg[b*256 + gate] = acc;
    }
}

__global__ __launch_bounds__(256,1) void k_lstm1(const float* __restrict__ Whh)
{
    int b = blockIdx.x, tid = threadIdx.x;
    __shared__ __align__(16) float sh[64];
    __shared__ float sg[256];
    ull w[32];
    const ull* p = (const ull*)(Whh + (size_t)tid*64);
    #pragma unroll
    for (int k = 0; k < 32; k++) w[k] = p[k];
    float dxg = g_dxg[b*256 + tid];
    if (tid < 64) sh[tid] = 0.f;
    float c = 0.f;
    for (int t = 0; t < 256; t++){
        __syncthreads();
        ull a0 = 0, a1 = 0;
        const ulonglong2* v4 = (const ulonglong2*)sh;
        #pragma unroll
        for (int k = 0; k < 16; k++){ ulonglong2 v = v4[k]; fma2(a0, w[2*k], v.x); fma2(a1, w[2*k+1], v.y); }
        sg[tid] = hsum2(a0) + hsum2(a1) + dxg;
        __syncthreads();
        if (tid < 64){
            float i_ = sigf(sg[tid]), f_ = sigf(sg[64+tid]);
            float gg = tanf_(sg[128+tid]), o_ = sigf(sg[192+tid]);
            c = f_*c + i_*gg;
            float h = o_*tanf_(c);
            sh[tid] = h;
            g_h1d[((size_t)b*256 + t)*64 + tid] = h;
        }
    }
}

__global__ __launch_bounds__(256,1) void k_lstm2(
    const float* __restrict__ Wih, const float* __restrict__ Whh,
    const float* __restrict__ bih, const float* __restrict__ bhh,
    const float* __restrict__ out_W, const float* __restrict__ out_b,
    float* __restrict__ out)
{
    int b = blockIdx.x, tid = threadIdx.x;
    __shared__ __align__(16) float sx[64];
    __shared__ __align__(16) float sh[64];
    __shared__ float sg[256];
    __shared__ float soW[64*64];
    for (int i = tid; i < 4096; i += 256){ int c = i >> 6, k = i & 63; soW[k*64 + c] = out_W[i]; }
    ull wi[32], wh[32];
    const ull* p = (const ull*)(Wih + 256UL*64 + (size_t)tid*64);
    const ull* q = (const ull*)(Whh + 256UL*64 + (size_t)tid*64);
    #pragma unroll
    for (int k = 0; k < 32; k++){ wi[k] = p[k]; wh[k] = q[k]; }
    float bias = bih[256 + tid] + bhh[256 + tid];
    if (tid < 64) sh[tid] = 0.f;
    float c = 0.f;
    float ob = (tid >= 64 && tid < 128) ? out_b[tid - 64] : 0.f;
    const float* xb = g_h1d + (size_t)b*256*64;
    for (int t = 0; t < 256; t++){
        if (tid < 64) sx[tid] = xb[t*64 + tid];
        __syncthreads();
        ull a0 = 0, a1 = 0;
        const ulonglong2* x4 = (const ulonglong2*)sx;
        const ulonglong2* h4 = (const ulonglong2*)sh;
        #pragma unroll
        for (int k = 0; k < 16; k++){ ulonglong2 v = x4[k]; fma2(a0, wi[2*k], v.x); fma2(a1, wi[2*k+1], v.y); }
        #pragma unroll
        for (int k = 0; k < 16; k++){ ulonglong2 v = h4[k]; fma2(a0, wh[2*k], v.x); fma2(a1, wh[2*k+1], v.y); }
        sg[tid] = hsum2(a0) + hsum2(a1) + bias;
        __syncthreads();
        if (tid < 64){
            float i_ = sigf(sg[tid]), f_ = sigf(sg[64+tid]);
            float gg = tanf_(sg[128+tid]), o_ = sigf(sg[192+tid]);
            c = f_*c + i_*gg;
            sh[tid] = o_*tanf_(c);
        }
        __syncthreads();
        if (tid >= 64 && tid < 128){
            int cc = tid - 64;
            float acc = ob;
            #pragma unroll 8
            for (int k = 0; k < 64; k++) acc += soW[k*64 + cc] * sh[k];
            out[((size_t)b*256 + t)*64 + cc] = acc;
        }
    }
}

extern "C" void kernel_launch(void* const* d_in, const int* in_sizes, int n_in,
                              void* d_out, int out_size)
{
    const float* x      = (const float*)d_in[0];
    const float* adj1   = (const float*)d_in[1];
    const float* W1     = (const float*)d_in[2];
    const float* b1     = (const float*)d_in[3];
    const float* adj2   = (const float*)d_in[4];
    const float* W2     = (const float*)d_in[5];
    const float* b2     = (const float*)d_in[6];
    const float* ln_g   = (const float*)d_in[7];
    const float* ln_b   = (const float*)d_in[8];
    const float* g0Wih  = (const float*)d_in[9];
    const float* g0Whh  = (const float*)d_in[10];
    const float* g0bih  = (const float*)d_in[11];
    const float* g0bhh  = (const float*)d_in[12];
    const float* g1Wih  = (const float*)d_in[13];
    const float* g1Whh  = (const float*)d_in[14];
    const float* g1bih  = (const float*)d_in[15];
    const float* g1bhh  = (const float*)d_in[16];
    const float* pool_W = (const float*)d_in[17];
    const float* pool_b = (const float*)d_in[18];
    const float* mu_W   = (const float*)d_in[19];
    const float* mu_b   = (const float*)d_in[20];
    const float* logv_W = (const float*)d_in[21];
    const float* logv_b = (const float*)d_in[22];
    const float* dec_W  = (const float*)d_in[23];
    const float* dec_b  = (const float*)d_in[24];
    const float* lWih   = (const float*)d_in[25];
    const float* lWhh   = (const float*)d_in[26];
    const float* lbih   = (const float*)d_in[27];
    const float* lbhh   = (const float*)d_in[28];
    const float* out_W  = (const float*)d_in[29];
    const float* out_b  = (const float*)d_in[30];
    float* out = (float*)d_out;

    k_softmax<<<1, 64>>>(adj1, adj2);
    k_prepW<<<1, 256>>>(g1Wih, g0Wih);
    k_gnn<<<16384, 256>>>(x, W1, b1, W2, b2, ln_g, ln_b);
    k_xproj0<<<1024, 256>>>();
    k_gru0h<<<dim3(512, 2), 192>>>(g0Whh, g0bih, g0bhh);
    k_xproj1<<<1024, 256>>>();
    k_gru1h<<<512, 192>>>(g1Whh, g1bih, g1bhh);
    k_gru1b<<<64, 192>>>(g1Wih, g1Whh, g1bih, g1bhh);
    k_head<<<64, 128>>>(pool_W, pool_b, mu_W, mu_b, logv_W, logv_b,
                        dec_W, dec_b, lWih, lbih, lbhh, out);
    k_lstm1<<<64, 256>>>(lWhh);
    k_lstm2<<<64, 256>>>(lWih, lWhh, lbih, lbhh, out_W, out_b, out);
}

// round 13
// speedup vs baseline: 1.1646x; 1.1646x over previous
#include <cuda_runtime.h>
#include <cuda_bf16.h>
#include <cstdint>
#include <math.h>

typedef unsigned long long ull;

__device__ float g_A1[64*64];
__device__ float g_A2[64*64];
__device__ __nv_bfloat16 g_hencH[4096UL*256*32];
__device__ __nv_bfloat16 g_hencL[4096UL*256*32];
__device__ __nv_bfloat16 g_h0H[4096UL*256*128];
__device__ __nv_bfloat16 g_h0L[4096UL*256*128];
__device__ __nv_bfloat16 g_W1hi[192*128];
__device__ __nv_bfloat16 g_W1lo[192*128];
__device__ __nv_bfloat16 g_W0hi[384*32];
__device__ __nv_bfloat16 g_W0lo[384*32];
__device__ float g_xg0[2UL*4096*256*192];
__device__ float g_xg1[4096UL*256*192];
__device__ float g_last[4096*128];
__device__ float g_dxg[64*256];
__device__ float g_h1d[64UL*256*64];

__device__ __forceinline__ void fma2(ull &acc, ull a, ull b){
    asm("fma.rn.f32x2 %0, %1, %2, %0;" : "+l"(acc) : "l"(a), "l"(b));
}
__device__ __forceinline__ float hsum2(ull a){
    float lo, hi; asm("mov.b64 {%0,%1}, %2;" : "=f"(lo), "=f"(hi) : "l"(a));
    return lo + hi;
}
__device__ __forceinline__ float sigf(float x){
    return __fdividef(1.f, 1.f + __expf(-x));
}
__device__ __forceinline__ float tanf_(float x){
    return __fmaf_rn(2.f, __fdividef(1.f, 1.f + __expf(-2.f*x)), -1.f);
}

__global__ void k_softmax(const float* __restrict__ adj1, const float* __restrict__ adj2){
    int i = threadIdx.x;
    for (int w = 0; w < 2; w++){
        const float* a = w ? adj2 : adj1;
        float* o = w ? g_A2 : g_A1;
        float mx = -1e30f;
        for (int j = 0; j < 64; j++) mx = fmaxf(mx, a[i*64+j]);
        float s = 0.f;
        for (int j = 0; j < 64; j++) s += expf(a[i*64+j] - mx);
        float inv = 1.f / s;
        for (int j = 0; j < 64; j++) o[i*64+j] = expf(a[i*64+j] - mx) * inv;
    }
}

__global__ void k_prepW(const float* __restrict__ W1, const float* __restrict__ W0){
    for (int i = threadIdx.x; i < 24576; i += 256){
        float v = W1[i];
        __nv_bfloat16 hi = __float2bfloat16(v);
        g_W1hi[i] = hi; g_W1lo[i] = __float2bfloat16(v - __bfloat162float(hi));
    }
    for (int i = threadIdx.x; i < 12288; i += 256){
        float v = W0[i];
        __nv_bfloat16 hi = __float2bfloat16(v);
        g_W0hi[i] = hi; g_W0lo[i] = __float2bfloat16(v - __bfloat162float(hi));
    }
}

__global__ __launch_bounds__(256) void k_gnn(
    const float* __restrict__ x,
    const float* __restrict__ W1, const float* __restrict__ b1,
    const float* __restrict__ W2, const float* __restrict__ b2,
    const float* __restrict__ lng, const float* __restrict__ lnb)
{
    int bt = blockIdx.x;
    int b = bt >> 8, t = bt & 255;
    int tid = threadIdx.x;

    __shared__ float sA2[64*65];
    __shared__ float sW2t[1024];
    __shared__ __align__(16) float sx[64];
    __shared__ float s1[64];
    __shared__ __align__(16) float sh1[2048];
    __shared__ __align__(16) float sagg[2048];
    __shared__ float sh2[64*33];
    __shared__ float sW1[32], sb1[32], sb2[32], slg[32], slb[32];
    __shared__ float smean[64], srstd[64];

    for (int i = tid; i < 4096; i += 256) sA2[(i>>6)*65 + (i&63)] = g_A2[i];
    for (int i = tid; i < 1024; i += 256){ int gp = i>>5, k = i&31; sW2t[k*32+gp] = W2[i]; }
    if (tid < 64) sx[tid] = x[(size_t)bt*64 + tid];
    if (tid < 32){ sW1[tid]=W1[tid]; sb1[tid]=b1[tid]; sb2[tid]=b2[tid]; slg[tid]=lng[tid]; slb[tid]=lnb[tid]; }
    __syncthreads();

    if (tid < 64){
        float s = 0.f; const float* a = g_A1 + tid*64;
        #pragma unroll 8
        for (int j = 0; j < 64; j++) s += a[j]*sx[j];
        s1[tid] = s;
    }
    __syncthreads();
    for (int i = tid; i < 2048; i += 256){ int j = i>>5, g = i&31; sh1[i] = fmaxf(sW1[g]*s1[j] + sb1[g], 0.f); }
    __syncthreads();
    {
        int i = tid >> 2, g0 = (tid & 3) * 8;
        float4 a0 = {0,0,0,0}, a1 = {0,0,0,0};
        #pragma unroll 4
        for (int j = 0; j < 64; j++){
            float a = sA2[i*65 + j];
            float4 h0 = *(const float4*)(sh1 + j*32 + g0);
            float4 h1 = *(const float4*)(sh1 + j*32 + g0 + 4);
            a0.x += a*h0.x; a0.y += a*h0.y; a0.z += a*h0.z; a0.w += a*h0.w;
            a1.x += a*h1.x; a1.y += a*h1.y; a1.z += a*h1.z; a1.w += a*h1.w;
        }
        *(float4*)(sagg + i*32 + g0)     = a0;
        *(float4*)(sagg + i*32 + g0 + 4) = a1;
    }
    __syncthreads();
    #pragma unroll
    for (int q = 0; q < 8; q++){
        int idx = tid + (q << 8);
        int i = idx >> 5, gp = idx & 31;
        float acc = sb2[gp];
        #pragma unroll 8
        for (int k = 0; k < 32; k++) acc += sagg[i*32 + k] * sW2t[k*32 + gp];
        sh2[i*33 + gp] = fmaxf(acc, 0.f);
    }
    __syncthreads();
    if (tid < 64){
        float m = 0.f;
        for (int g = 0; g < 32; g++) m += sh2[tid*33 + g];
        m *= (1.f/32.f);
        float v = 0.f;
        for (int g = 0; g < 32; g++){ float d = sh2[tid*33 + g] - m; v += d*d; }
        v *= (1.f/32.f);
        smean[tid] = m; srstd[tid] = rsqrtf(v + 1e-5f);
    }
    __syncthreads();
    for (int idx = tid; idx < 2048; idx += 256){
        int i = idx >> 5, g = idx & 31;
        float val = (sh2[i*33 + g] - smean[i]) * srstd[i] * slg[g] + slb[g];
        size_t o = (((size_t)b*64 + i)*256 + t)*32 + g;
        __nv_bfloat16 hi = __float2bfloat16(val);
        g_hencH[o] = hi;
        g_hencL[o] = __float2bfloat16(val - __bfloat162float(hi));
    }
}

// ---- mma GEMM: xg0 = henc @ Wih0^T, double-buffered A staging ----
__global__ __launch_bounds__(256,2) void k_xproj0(){
    __shared__ uint32_t sA[2][16*20];
    int tid = threadIdx.x;
    int w = tid >> 5, lane = tid & 31;
    int g = lane >> 2, tig = lane & 3;
    size_t Rbase = (size_t)blockIdx.x * 1024;

    uint32_t bh[6][2][2];
    #pragma unroll
    for (int nt = 0; nt < 6; nt++){
        int n = w*48 + nt*8 + g;
        const uint32_t* wp = (const uint32_t*)g_W0hi + n*16;
        #pragma unroll
        for (int ks = 0; ks < 2; ks++){
            bh[nt][ks][0] = wp[ks*8 + tig];
            bh[nt][ks][1] = wp[ks*8 + 4 + tig];
        }
    }
    const uint32_t* blo = (const uint32_t*)g_W0lo;
    const uint32_t* hH = (const uint32_t*)g_hencH;
    const uint32_t* hL = (const uint32_t*)g_hencL;

    int prow = tid >> 4, pc = tid & 15;
    uint32_t rh = hH[(Rbase + prow)*16 + pc];
    uint32_t rl = hL[(Rbase + prow)*16 + pc];

    for (int mt = 0; mt < 64; mt++){
        size_t R = Rbase + mt*16;
        __syncthreads();
        sA[0][prow*20 + pc] = rh;
        sA[1][prow*20 + pc] = rl;
        __syncthreads();
        if (mt < 63){
            size_t Rn = R + 16;
            rh = hH[(Rn + prow)*16 + pc];
            rl = hL[(Rn + prow)*16 + pc];
        }
        float acc[6][4];
        #pragma unroll
        for (int nt=0;nt<6;nt++){ acc[nt][0]=0.f; acc[nt][1]=0.f; acc[nt][2]=0.f; acc[nt][3]=0.f; }
        #pragma unroll
        for (int term = 0; term < 3; term++){
            const uint32_t* As = sA[term == 1 ? 1 : 0];
            #pragma unroll
            for (int ks = 0; ks < 2; ks++){
                uint32_t a0 = As[g*20 + ks*8 + tig];
                uint32_t a1 = As[(g+8)*20 + ks*8 + tig];
                uint32_t a2 = As[g*20 + ks*8 + 4 + tig];
                uint32_t a3 = As[(g+8)*20 + ks*8 + 4 + tig];
                #pragma unroll
                for (int nt = 0; nt < 6; nt++){
                    uint32_t b0, b1;
                    if (term < 2){ b0 = bh[nt][ks][0]; b1 = bh[nt][ks][1]; }
                    else {
                        int n = w*48 + nt*8 + g;
                        b0 = __ldg(blo + n*16 + ks*8 + tig);
                        b1 = __ldg(blo + n*16 + ks*8 + 4 + tig);
                    }
                    asm volatile(
                        "mma.sync.aligned.m16n8k16.row.col.f32.bf16.bf16.f32 "
                        "{%0,%1,%2,%3}, {%4,%5,%6,%7}, {%8,%9}, {%0,%1,%2,%3};"
                        : "+f"(acc[nt][0]), "+f"(acc[nt][1]), "+f"(acc[nt][2]), "+f"(acc[nt][3])
                        : "r"(a0), "r"(a1), "r"(a2), "r"(a3), "r"(b0), "r"(b1));
                }
            }
        }
        #pragma unroll
        for (int nt = 0; nt < 6; nt++){
            int col = w*48 + nt*8 + tig*2;
            int dir = col >= 192;
            int lc = col - dir*192;
            float* base = g_xg0 + (size_t)dir*201326592;
            *(float2*)(base + (R+g)*192 + lc)   = make_float2(acc[nt][0], acc[nt][1]);
            *(float2*)(base + (R+g+8)*192 + lc) = make_float2(acc[nt][2], acc[nt][3]);
        }
    }
}

// ---- BiGRU layer 0: hidden recurrence only, 8 seqs per CTA ----
__global__ __launch_bounds__(192,2) void k_gru0h(
    const float* __restrict__ Whh, const float* __restrict__ bih, const float* __restrict__ bhh)
{
    int n0 = blockIdx.x * 8, dir = blockIdx.y;
    int g = threadIdx.x;
    __shared__ __align__(16) float sh[8][64];
    __shared__ float sgi[8][192], sgh[8][192];

    ull wh[32];
    const ull* p = (const ull*)(Whh + ((size_t)dir*192 + g)*64);
    #pragma unroll
    for (int k = 0; k < 32; k++) wh[k] = p[k];
    float bi = bih[dir*192 + g], bh = bhh[dir*192 + g];

    for (int u = g; u < 512; u += 192) sh[u>>6][u&63] = 0.f;
    __syncthreads();

    const float* xgb = g_xg0 + (size_t)dir*201326592;
    int t0 = dir ? 255 : 0;
    float xr[8];
    #pragma unroll
    for (int q = 0; q < 8; q++) xr[q] = xgb[((size_t)(n0+q)*256 + t0)*192 + g];

    for (int s = 0; s < 256; s++){
        int t = dir ? 255 - s : s;
        #pragma unroll
        for (int q = 0; q < 8; q++) sgi[q][g] = xr[q] + bi;
        if (s < 255){
            int tn = dir ? 254 - s : s + 1;
            #pragma unroll
            for (int q = 0; q < 8; q++) xr[q] = xgb[((size_t)(n0+q)*256 + tn)*192 + g];
        }
        #pragma unroll
        for (int q = 0; q < 8; q++){
            const ulonglong2* h4 = (const ulonglong2*)sh[q];
            ull b0 = 0, b1 = 0;
            #pragma unroll
            for (int k = 0; k < 16; k++){ ulonglong2 v = h4[k]; fma2(b0, wh[2*k], v.x); fma2(b1, wh[2*k+1], v.y); }
            sgh[q][g] = hsum2(b0) + hsum2(b1) + bh;
        }
        __syncthreads();
        for (int u = g; u < 512; u += 192){
            int q = u >> 6, hh = u & 63;
            float r  = sigf(sgi[q][hh] + sgh[q][hh]);
            float z  = sigf(sgi[q][64+hh] + sgh[q][64+hh]);
            float nn = tanf_(sgi[q][128+hh] + r*sgh[q][128+hh]);
            float h  = (1.f - z)*nn + z*sh[q][hh];
            sh[q][hh] = h;
            __nv_bfloat16 hi = __float2bfloat16(h);
            __nv_bfloat16 lo = __float2bfloat16(h - __bfloat162float(hi));
            size_t idx = ((size_t)(n0+q)*256 + t)*128 + dir*64 + hh;
            g_h0H[idx] = hi; g_h0L[idx] = lo;
        }
        __syncthreads();
    }
}

// ---- mma GEMM: xg1 = h0 @ Wih1^T, double-buffered A staging ----
__global__ __launch_bounds__(256,2) void k_xproj1(){
    __shared__ uint32_t sA[2][16*68];
    int tid = threadIdx.x;
    int w = tid >> 5, lane = tid & 31;
    int g = lane >> 2, tig = lane & 3;
    size_t Rbase = (size_t)blockIdx.x * 1024;

    uint32_t bh[3][8][2];
    #pragma unroll
    for (int nt = 0; nt < 3; nt++){
        int n = w*24 + nt*8 + g;
        const uint32_t* wp = (const uint32_t*)g_W1hi + n*64;
        #pragma unroll
        for (int ks = 0; ks < 8; ks++){
            bh[nt][ks][0] = wp[ks*8 + tig];
            bh[nt][ks][1] = wp[ks*8 + 4 + tig];
        }
    }
    const uint32_t* blo = (const uint32_t*)g_W1lo;
    const uint4* h0Hu = (const uint4*)g_h0H;
    const uint4* h0Lu = (const uint4*)g_h0L;

    // per-tile staging: 16 rows x 64 uint32 per plane; thread -> row=tid>>4, 4 cols at (tid&15)*4
    int prow = tid >> 4, pc4 = tid & 15;     // uint4 index within row (16 per row)
    uint4 rh = h0Hu[(Rbase + prow)*16 + pc4];
    uint4 rl = h0Lu[(Rbase + prow)*16 + pc4];

    for (int mt = 0; mt < 64; mt++){
        size_t R = Rbase + mt*16;
        __syncthreads();
        {
            int c0 = pc4*4;
            sA[0][prow*68 + c0]   = rh.x; sA[0][prow*68 + c0+1] = rh.y;
            sA[0][prow*68 + c0+2] = rh.z; sA[0][prow*68 + c0+3] = rh.w;
            sA[1][prow*68 + c0]   = rl.x; sA[1][prow*68 + c0+1] = rl.y;
            sA[1][prow*68 + c0+2] = rl.z; sA[1][prow*68 + c0+3] = rl.w;
        }
        __syncthreads();
        if (mt < 63){
            size_t Rn = R + 16;
            rh = h0Hu[(Rn + prow)*16 + pc4];
            rl = h0Lu[(Rn + prow)*16 + pc4];
        }
        float acc[3][4];
        #pragma unroll
        for (int nt=0;nt<3;nt++){ acc[nt][0]=0.f; acc[nt][1]=0.f; acc[nt][2]=0.f; acc[nt][3]=0.f; }
        #pragma unroll
        for (int term = 0; term < 3; term++){
            const uint32_t* As = sA[term == 1 ? 1 : 0];
            #pragma unroll
            for (int ks = 0; ks < 8; ks++){
                uint32_t a0 = As[g*68 + ks*8 + tig];
                uint32_t a1 = As[(g+8)*68 + ks*8 + tig];
                uint32_t a2 = As[g*68 + ks*8 + 4 + tig];
                uint32_t a3 = As[(g+8)*68 + ks*8 + 4 + tig];
                #pragma unroll
                for (int nt = 0; nt < 3; nt++){
                    uint32_t b0, b1;
                    if (term < 2){ b0 = bh[nt][ks][0]; b1 = bh[nt][ks][1]; }
                    else {
                        int n = w*24 + nt*8 + g;
                        b0 = __ldg(blo + n*64 + ks*8 + tig);
                        b1 = __ldg(blo + n*64 + ks*8 + 4 + tig);
                    }
                    asm volatile(
                        "mma.sync.aligned.m16n8k16.row.col.f32.bf16.bf16.f32 "
                        "{%0,%1,%2,%3}, {%4,%5,%6,%7}, {%8,%9}, {%0,%1,%2,%3};"
                        : "+f"(acc[nt][0]), "+f"(acc[nt][1]), "+f"(acc[nt][2]), "+f"(acc[nt][3])
                        : "r"(a0), "r"(a1), "r"(a2), "r"(a3), "r"(b0), "r"(b1));
                }
            }
        }
        #pragma unroll
        for (int nt = 0; nt < 3; nt++){
            int col = w*24 + nt*8 + tig*2;
            *(float2*)(g_xg1 + (R+g)*192 + col)   = make_float2(acc[nt][0], acc[nt][1]);
            *(float2*)(g_xg1 + (R+g+8)*192 + col) = make_float2(acc[nt][2], acc[nt][3]);
        }
    }
}

// ---- GRU layer 1 fwd, hidden recurrence only, 8 seqs per CTA ----
__global__ __launch_bounds__(192,2) void k_gru1h(
    const float* __restrict__ Whh, const float* __restrict__ bih, const float* __restrict__ bhh)
{
    int n0 = blockIdx.x * 8;
    int g = threadIdx.x;
    __shared__ __align__(16) float sh[8][64];
    __shared__ float sgi[8][192], sgh[8][192];

    ull wh[32];
    const ull* p = (const ull*)(Whh + (size_t)g*64);
    #pragma unroll
    for (int k = 0; k < 32; k++) wh[k] = p[k];
    float bi = bih[g], bh = bhh[g];

    for (int u = g; u < 512; u += 192) sh[u>>6][u&63] = 0.f;
    __syncthreads();

    float xr[8];
    #pragma unroll
    for (int q = 0; q < 8; q++) xr[q] = g_xg1[((size_t)(n0+q)*256)*192 + g];

    for (int t = 0; t < 256; t++){
        #pragma unroll
        for (int q = 0; q < 8; q++) sgi[q][g] = xr[q] + bi;
        if (t < 255){
            #pragma unroll
            for (int q = 0; q < 8; q++) xr[q] = g_xg1[((size_t)(n0+q)*256 + t + 1)*192 + g];
        }
        #pragma unroll
        for (int q = 0; q < 8; q++){
            const ulonglong2* h4 = (const ulonglong2*)sh[q];
            ull b0 = 0, b1 = 0;
            #pragma unroll
            for (int k = 0; k < 16; k++){ ulonglong2 v = h4[k]; fma2(b0, wh[2*k], v.x); fma2(b1, wh[2*k+1], v.y); }
            sgh[q][g] = hsum2(b0) + hsum2(b1) + bh;
        }
        __syncthreads();
        for (int u = g; u < 512; u += 192){
            int q = u >> 6, hh = u & 63;
            float r  = sigf(sgi[q][hh] + sgh[q][hh]);
            float z  = sigf(sgi[q][64+hh] + sgh[q][64+hh]);
            float nn = tanf_(sgi[q][128+hh] + r*sgh[q][128+hh]);
            float h  = (1.f - z)*nn + z*sh[q][hh];
            sh[q][hh] = h;
            if (t == 255) g_last[(n0+q)*128 + hh] = h;
        }
        __syncthreads();
    }
}

__global__ __launch_bounds__(192,2) void k_gru1b(
    const float* __restrict__ Wih, const float* __restrict__ Whh,
    const float* __restrict__ bih, const float* __restrict__ bhh)
{
    int tid = threadIdx.x;
    __shared__ __align__(16) float sx[128];
    __shared__ float sgi[192];
    ull w[64];
    const ull* p = (const ull*)(Wih + 192UL*128 + (size_t)tid*128);
    #pragma unroll
    for (int k = 0; k < 64; k++) w[k] = p[k];
    float bias = bih[192 + tid];

    for (int it = 0; it < 64; it++){
        int n = blockIdx.x*64 + it;
        if (tid < 128){
            size_t idx = ((size_t)n*256 + 255)*128 + tid;
            sx[tid] = __bfloat162float(g_h0H[idx]) + __bfloat162float(g_h0L[idx]);
        }
        __syncthreads();
        ull a0 = 0, a1 = 0;
        const ulonglong2* v4 = (const ulonglong2*)sx;
        #pragma unroll
        for (int k = 0; k < 32; k++){ ulonglong2 v = v4[k]; fma2(a0, w[2*k], v.x); fma2(a1, w[2*k+1], v.y); }
        sgi[tid] = hsum2(a0) + hsum2(a1) + bias;
        __syncthreads();
        if (tid < 64){
            float r  = sigf(sgi[tid]      + bhh[192 + tid]);
            float z  = sigf(sgi[64 + tid] + bhh[192 + 64 + tid]);
            float nn = tanf_(sgi[128+tid] + r * bhh[192 + 128 + tid]);
            g_last[n*128 + 64 + tid] = (1.f - z)*nn;
        }
    }
}

__global__ __launch_bounds__(128) void k_head(
    const float* __restrict__ pool_W, const float* __restrict__ pool_b,
    const float* __restrict__ mu_W, const float* __restrict__ mu_b,
    const float* __restrict__ logv_W, const float* __restrict__ logv_b,
    const float* __restrict__ dec_W, const float* __restrict__ dec_b,
    const float* __restrict__ lstm_Wih, const float* __restrict__ lstm_bih,
    const float* __restrict__ lstm_bhh,
    float* __restrict__ out)
{
    int b = blockIdx.x, tid = threadIdx.x;
    __shared__ float slast[128], shp[32], smu[32], sdh[64];
    float s = 0.f;
    for (int c = 0; c < 64; c++) s += g_last[(b*64 + c)*128 + tid];
    slast[tid] = s * (1.f/64.f);
    __syncthreads();
    if (tid < 32){
        float acc = pool_b[tid];
        for (int k = 0; k < 128; k++) acc += pool_W[tid*128 + k] * slast[k];
        shp[tid] = fmaxf(acc, 0.f);
    }
    __syncthreads();
    if (tid < 32){
        float acc = mu_b[tid];
        for (int k = 0; k < 32; k++) acc += mu_W[tid*32 + k] * shp[k];
        smu[tid] = acc;
        out[64UL*256*64 + b*32 + tid] = acc;
    } else if (tid < 64){
        int j = tid - 32;
        float acc = logv_b[j];
        for (int k = 0; k < 32; k++) acc += logv_W[j*32 + k] * shp[k];
        out[64UL*256*64 + 2048 + b*32 + j] = acc;
    }
    __syncthreads();
    if (tid < 64){
        float acc = dec_b[tid];
        for (int k = 0; k < 32; k++) acc += dec_W[tid*32 + k] * smu[k];
        sdh[tid] = fmaxf(acc, 0.f);
    }
    __syncthreads();
    for (int gate = tid; gate < 256; gate += 128){
        float acc = lstm_bih[gate] + lstm_bhh[gate];
        for (int k = 0; k < 64; k++) acc += lstm_Wih[gate*64 + k] * sdh[k];
        g_dxg[b*256 + gate] = acc;
    }
}

__global__ __launch_bounds__(256,1) void k_lstm1(const float* __restrict__ Whh)
{
    int b = blockIdx.x, tid = threadIdx.x;
    __shared__ __align__(16) float sh[64];
    __shared__ float sg[256];
    ull w[32];
    const ull* p = (const ull*)(Whh + (size_t)tid*64);
    #pragma unroll
    for (int k = 0; k < 32; k++) w[k] = p[k];
    float dxg = g_dxg[b*256 + tid];
    if (tid < 64) sh[tid] = 0.f;
    float c = 0.f;
    for (int t = 0; t < 256; t++){
        __syncthreads();
        ull a0 = 0, a1 = 0;
        const ulonglong2* v4 = (const ulonglong2*)sh;
        #pragma unroll
        for (int k = 0; k < 16; k++){ ulonglong2 v = v4[k]; fma2(a0, w[2*k], v.x); fma2(a1, w[2*k+1], v.y); }
        sg[tid] = hsum2(a0) + hsum2(a1) + dxg;
        __syncthreads();
        if (tid < 64){
            float i_ = sigf(sg[tid]), f_ = sigf(sg[64+tid]);
            float gg = tanf_(sg[128+tid]), o_ = sigf(sg[192+tid]);
            c = f_*c + i_*gg;
            float h = o_*tanf_(c);
            sh[tid] = h;
            g_h1d[((size_t)b*256 + t)*64 + tid] = h;
        }
    }
}

__global__ __launch_bounds__(256,1) void k_lstm2(
    const float* __restrict__ Wih, const float* __restrict__ Whh,
    const float* __restrict__ bih, const float* __restrict__ bhh,
    const float* __restrict__ out_W, const float* __restrict__ out_b,
    float* __restrict__ out)
{
    int b = blockIdx.x, tid = threadIdx.x;
    __shared__ __align__(16) float sx[64];
    __shared__ __align__(16) float sh[64];
    __shared__ float sg[256];
    __shared__ float soW[64*64];
    for (int i = tid; i < 4096; i += 256){ int c = i >> 6, k = i & 63; soW[k*64 + c] = out_W[i]; }
    ull wi[32], wh[32];
    const ull* p = (const ull*)(Wih + 256UL*64 + (size_t)tid*64);
    const ull* q = (const ull*)(Whh + 256UL*64 + (size_t)tid*64);
    #pragma unroll
    for (int k = 0; k < 32; k++){ wi[k] = p[k]; wh[k] = q[k]; }
    float bias = bih[256 + tid] + bhh[256 + tid];
    if (tid < 64) sh[tid] = 0.f;
    float c = 0.f;
    float ob = (tid >= 64 && tid < 128) ? out_b[tid - 64] : 0.f;
    const float* xb = g_h1d + (size_t)b*256*64;
    for (int t = 0; t < 256; t++){
        if (tid < 64) sx[tid] = xb[t*64 + tid];
        __syncthreads();
        ull a0 = 0, a1 = 0;
        const ulonglong2* x4 = (const ulonglong2*)sx;
        const ulonglong2* h4 = (const ulonglong2*)sh;
        #pragma unroll
        for (int k = 0; k < 16; k++){ ulonglong2 v = x4[k]; fma2(a0, wi[2*k], v.x); fma2(a1, wi[2*k+1], v.y); }
        #pragma unroll
        for (int k = 0; k < 16; k++){ ulonglong2 v = h4[k]; fma2(a0, wh[2*k], v.x); fma2(a1, wh[2*k+1], v.y); }
        sg[tid] = hsum2(a0) + hsum2(a1) + bias;
        __syncthreads();
        if (tid < 64){
            float i_ = sigf(sg[tid]), f_ = sigf(sg[64+tid]);
            float gg = tanf_(sg[128+tid]), o_ = sigf(sg[192+tid]);
            c = f_*c + i_*gg;
            sh[tid] = o_*tanf_(c);
        }
        __syncthreads();
        if (tid >= 64 && tid < 128){
            int cc = tid - 64;
            float acc = ob;
            #pragma unroll 8
            for (int k = 0; k < 64; k++) acc += soW[k*64 + cc] * sh[k];
            out[((size_t)b*256 + t)*64 + cc] = acc;
        }
    }
}

extern "C" void kernel_launch(void* const* d_in, const int* in_sizes, int n_in,
                              void* d_out, int out_size)
{
    const float* x      = (const float*)d_in[0];
    const float* adj1   = (const float*)d_in[1];
    const float* W1     = (const float*)d_in[2];
    const float* b1     = (const float*)d_in[3];
    const float* adj2   = (const float*)d_in[4];
    const float* W2     = (const float*)d_in[5];
    const float* b2     = (const float*)d_in[6];
    const float* ln_g   = (const float*)d_in[7];
    const float* ln_b   = (const float*)d_in[8];
    const float* g0Wih  = (const float*)d_in[9];
    const float* g0Whh  = (const float*)d_in[10];
    const float* g0bih  = (const float*)d_in[11];
    const float* g0bhh  = (const float*)d_in[12];
    const float* g1Wih  = (const float*)d_in[13];
    const float* g1Whh  = (const float*)d_in[14];
    const float* g1bih  = (const float*)d_in[15];
    const float* g1bhh  = (const float*)d_in[16];
    const float* pool_W = (const float*)d_in[17];
    const float* pool_b = (const float*)d_in[18];
    const float* mu_W   = (const float*)d_in[19];
    const float* mu_b   = (const float*)d_in[20];
    const float* logv_W = (const float*)d_in[21];
    const float* logv_b = (const float*)d_in[22];
    const float* dec_W  = (const float*)d_in[23];
    const float* dec_b  = (const float*)d_in[24];
    const float* lWih   = (const float*)d_in[25];
    const float* lWhh   = (const float*)d_in[26];
    const float* lbih   = (const float*)d_in[27];
    const float* lbhh   = (const float*)d_in[28];
    const float* out_W  = (const float*)d_in[29];
    const float* out_b  = (const float*)d_in[30];
    float* out = (float*)d_out;

    k_softmax<<<1, 64>>>(adj1, adj2);
    k_prepW<<<1, 256>>>(g1Wih, g0Wih);
    k_gnn<<<16384, 256>>>(x, W1, b1, W2, b2, ln_g, ln_b);
    k_xproj0<<<1024, 256>>>();
    k_gru0h<<<dim3(512, 2), 192>>>(g0Whh, g0bih, g0bhh);
    k_xproj1<<<1024, 256>>>();
    k_gru1h<<<512, 192>>>(g1Whh, g1bih, g1bhh);
    k_gru1b<<<64, 192>>>(g1Wih, g1Whh, g1bih, g1bhh);
    k_head<<<64, 128>>>(pool_W, pool_b, mu_W, mu_b, logv_W, logv_b,
                        dec_W, dec_b, lWih, lbih, lbhh, out);
    k_lstm1<<<64, 256>>>(lWhh);
    k_lstm2<<<64, 256>>>(lWih, lWhh, lbih, lbhh, out_W, out_b, out);
}

// round 14
// speedup vs baseline: 1.7257x; 1.4817x over previous
#include <cuda_runtime.h>
#include <cuda_bf16.h>
#include <cstdint>
#include <math.h>

typedef unsigned long long ull;

__device__ float g_A1[64*64];
__device__ float g_A2[64*64];
__device__ __nv_bfloat16 g_hencH[4096UL*256*32];
__device__ __nv_bfloat16 g_hencL[4096UL*256*32];
__device__ __nv_bfloat16 g_h0H[4096UL*256*128];
__device__ __nv_bfloat16 g_h0L[4096UL*256*128];
__device__ __nv_bfloat16 g_W1hi[192*128];
__device__ __nv_bfloat16 g_W1lo[192*128];
__device__ __nv_bfloat16 g_W0hi[384*32];
__device__ __nv_bfloat16 g_W0lo[384*32];
__device__ __nv_bfloat16 g_Wh0hi[384*64];
__device__ __nv_bfloat16 g_Wh0lo[384*64];
__device__ __nv_bfloat16 g_Wh1hi[192*64];
__device__ __nv_bfloat16 g_Wh1lo[192*64];
__device__ float g_xg0[2UL*4096*256*192];
__device__ float g_xg1[4096UL*256*192];
__device__ float g_last[4096*128];
__device__ float g_dxg[64*256];
__device__ float g_h1d[64UL*256*64];

__device__ __forceinline__ void fma2(ull &acc, ull a, ull b){
    asm("fma.rn.f32x2 %0, %1, %2, %0;" : "+l"(acc) : "l"(a), "l"(b));
}
__device__ __forceinline__ float hsum2(ull a){
    float lo, hi; asm("mov.b64 {%0,%1}, %2;" : "=f"(lo), "=f"(hi) : "l"(a));
    return lo + hi;
}
__device__ __forceinline__ float sigf(float x){
    return __fdividef(1.f, 1.f + __expf(-x));
}
__device__ __forceinline__ float tanf_(float x){
    return __fmaf_rn(2.f, __fdividef(1.f, 1.f + __expf(-2.f*x)), -1.f);
}
#define MMA16816(acc, A0,A1,A2,A3, B0,B1) \
    asm volatile("mma.sync.aligned.m16n8k16.row.col.f32.bf16.bf16.f32 " \
        "{%0,%1,%2,%3}, {%4,%5,%6,%7}, {%8,%9}, {%0,%1,%2,%3};" \
        : "+f"(acc[0]), "+f"(acc[1]), "+f"(acc[2]), "+f"(acc[3]) \
        : "r"(A0), "r"(A1), "r"(A2), "r"(A3), "r"(B0), "r"(B1))

__global__ void k_softmax(const float* __restrict__ adj1, const float* __restrict__ adj2){
    int i = threadIdx.x;
    for (int w = 0; w < 2; w++){
        const float* a = w ? adj2 : adj1;
        float* o = w ? g_A2 : g_A1;
        float mx = -1e30f;
        for (int j = 0; j < 64; j++) mx = fmaxf(mx, a[i*64+j]);
        float s = 0.f;
        for (int j = 0; j < 64; j++) s += expf(a[i*64+j] - mx);
        float inv = 1.f / s;
        for (int j = 0; j < 64; j++) o[i*64+j] = expf(a[i*64+j] - mx) * inv;
    }
}

__global__ void k_prepW(const float* __restrict__ W1, const float* __restrict__ W0,
                        const float* __restrict__ Wh0, const float* __restrict__ Wh1){
    for (int i = threadIdx.x; i < 24576; i += 256){
        float v = W1[i];
        __nv_bfloat16 hi = __float2bfloat16(v);
        g_W1hi[i] = hi; g_W1lo[i] = __float2bfloat16(v - __bfloat162float(hi));
    }
    for (int i = threadIdx.x; i < 12288; i += 256){
        float v = W0[i];
        __nv_bfloat16 hi = __float2bfloat16(v);
        g_W0hi[i] = hi; g_W0lo[i] = __float2bfloat16(v - __bfloat162float(hi));
    }
    for (int i = threadIdx.x; i < 24576; i += 256){
        float v = Wh0[i];
        __nv_bfloat16 hi = __float2bfloat16(v);
        g_Wh0hi[i] = hi; g_Wh0lo[i] = __float2bfloat16(v - __bfloat162float(hi));
    }
    for (int i = threadIdx.x; i < 12288; i += 256){
        float v = Wh1[i];
        __nv_bfloat16 hi = __float2bfloat16(v);
        g_Wh1hi[i] = hi; g_Wh1lo[i] = __float2bfloat16(v - __bfloat162float(hi));
    }
}

__global__ __launch_bounds__(256) void k_gnn(
    const float* __restrict__ x,
    const float* __restrict__ W1, const float* __restrict__ b1,
    const float* __restrict__ W2, const float* __restrict__ b2,
    const float* __restrict__ lng, const float* __restrict__ lnb)
{
    int bt = blockIdx.x;
    int b = bt >> 8, t = bt & 255;
    int tid = threadIdx.x;

    __shared__ float sA2[64*65];
    __shared__ float sW2t[1024];
    __shared__ __align__(16) float sx[64];
    __shared__ float s1[64];
    __shared__ __align__(16) float sh1[2048];
    __shared__ __align__(16) float sagg[2048];
    __shared__ float sh2[64*33];
    __shared__ float sW1[32], sb1[32], sb2[32], slg[32], slb[32];
    __shared__ float smean[64], srstd[64];

    for (int i = tid; i < 4096; i += 256) sA2[(i>>6)*65 + (i&63)] = g_A2[i];
    for (int i = tid; i < 1024; i += 256){ int gp = i>>5, k = i&31; sW2t[k*32+gp] = W2[i]; }
    if (tid < 64) sx[tid] = x[(size_t)bt*64 + tid];
    if (tid < 32){ sW1[tid]=W1[tid]; sb1[tid]=b1[tid]; sb2[tid]=b2[tid]; slg[tid]=lng[tid]; slb[tid]=lnb[tid]; }
    __syncthreads();

    if (tid < 64){
        float s = 0.f; const float* a = g_A1 + tid*64;
        #pragma unroll 8
        for (int j = 0; j < 64; j++) s += a[j]*sx[j];
        s1[tid] = s;
    }
    __syncthreads();
    for (int i = tid; i < 2048; i += 256){ int j = i>>5, g = i&31; sh1[i] = fmaxf(sW1[g]*s1[j] + sb1[g], 0.f); }
    __syncthreads();
    {
        int i = tid >> 2, g0 = (tid & 3) * 8;
        float4 a0 = {0,0,0,0}, a1 = {0,0,0,0};
        #pragma unroll 4
        for (int j = 0; j < 64; j++){
            float a = sA2[i*65 + j];
            float4 h0 = *(const float4*)(sh1 + j*32 + g0);
            float4 h1 = *(const float4*)(sh1 + j*32 + g0 + 4);
            a0.x += a*h0.x; a0.y += a*h0.y; a0.z += a*h0.z; a0.w += a*h0.w;
            a1.x += a*h1.x; a1.y += a*h1.y; a1.z += a*h1.z; a1.w += a*h1.w;
        }
        *(float4*)(sagg + i*32 + g0)     = a0;
        *(float4*)(sagg + i*32 + g0 + 4) = a1;
    }
    __syncthreads();
    #pragma unroll
    for (int q = 0; q < 8; q++){
        int idx = tid + (q << 8);
        int i = idx >> 5, gp = idx & 31;
        float acc = sb2[gp];
        #pragma unroll 8
        for (int k = 0; k < 32; k++) acc += sagg[i*32 + k] * sW2t[k*32 + gp];
        sh2[i*33 + gp] = fmaxf(acc, 0.f);
    }
    __syncthreads();
    if (tid < 64){
        float m = 0.f;
        for (int g = 0; g < 32; g++) m += sh2[tid*33 + g];
        m *= (1.f/32.f);
        float v = 0.f;
        for (int g = 0; g < 32; g++){ float d = sh2[tid*33 + g] - m; v += d*d; }
        v *= (1.f/32.f);
        smean[tid] = m; srstd[tid] = rsqrtf(v + 1e-5f);
    }
    __syncthreads();
    for (int idx = tid; idx < 2048; idx += 256){
        int i = idx >> 5, g = idx & 31;
        float val = (sh2[i*33 + g] - smean[i]) * srstd[i] * slg[g] + slb[g];
        size_t o = (((size_t)b*64 + i)*256 + t)*32 + g;
        __nv_bfloat16 hi = __float2bfloat16(val);
        g_hencH[o] = hi;
        g_hencL[o] = __float2bfloat16(val - __bfloat162float(hi));
    }
}

// ---- mma GEMM: xg0 = henc @ Wih0^T, double-buffered ----
__global__ __launch_bounds__(256,2) void k_xproj0(){
    __shared__ uint32_t sA[2][16*20];
    int tid = threadIdx.x;
    int w = tid >> 5, lane = tid & 31;
    int g = lane >> 2, tig = lane & 3;
    size_t Rbase = (size_t)blockIdx.x * 1024;

    uint32_t bh[6][2][2];
    #pragma unroll
    for (int nt = 0; nt < 6; nt++){
        int n = w*48 + nt*8 + g;
        const uint32_t* wp = (const uint32_t*)g_W0hi + n*16;
        #pragma unroll
        for (int ks = 0; ks < 2; ks++){
            bh[nt][ks][0] = wp[ks*8 + tig];
            bh[nt][ks][1] = wp[ks*8 + 4 + tig];
        }
    }
    const uint32_t* blo = (const uint32_t*)g_W0lo;
    const uint32_t* hH = (const uint32_t*)g_hencH;
    const uint32_t* hL = (const uint32_t*)g_hencL;

    int prow = tid >> 4, pc = tid & 15;
    uint32_t rh = hH[(Rbase + prow)*16 + pc];
    uint32_t rl = hL[(Rbase + prow)*16 + pc];

    for (int mt = 0; mt < 64; mt++){
        size_t R = Rbase + mt*16;
        __syncthreads();
        sA[0][prow*20 + pc] = rh;
        sA[1][prow*20 + pc] = rl;
        __syncthreads();
        if (mt < 63){
            rh = hH[(R + 16 + prow)*16 + pc];
            rl = hL[(R + 16 + prow)*16 + pc];
        }
        float acc[6][4];
        #pragma unroll
        for (int nt=0;nt<6;nt++){ acc[nt][0]=0.f; acc[nt][1]=0.f; acc[nt][2]=0.f; acc[nt][3]=0.f; }
        #pragma unroll
        for (int term = 0; term < 3; term++){
            const uint32_t* As = sA[term == 1 ? 1 : 0];
            #pragma unroll
            for (int ks = 0; ks < 2; ks++){
                uint32_t a0 = As[g*20 + ks*8 + tig];
                uint32_t a1 = As[(g+8)*20 + ks*8 + tig];
                uint32_t a2 = As[g*20 + ks*8 + 4 + tig];
                uint32_t a3 = As[(g+8)*20 + ks*8 + 4 + tig];
                #pragma unroll
                for (int nt = 0; nt < 6; nt++){
                    uint32_t b0, b1;
                    if (term < 2){ b0 = bh[nt][ks][0]; b1 = bh[nt][ks][1]; }
                    else {
                        int n = w*48 + nt*8 + g;
                        b0 = __ldg(blo + n*16 + ks*8 + tig);
                        b1 = __ldg(blo + n*16 + ks*8 + 4 + tig);
                    }
                    MMA16816(acc[nt], a0,a1,a2,a3, b0,b1);
                }
            }
        }
        #pragma unroll
        for (int nt = 0; nt < 6; nt++){
            int col = w*48 + nt*8 + tig*2;
            int dir = col >= 192;
            int lc = col - dir*192;
            float* base = g_xg0 + (size_t)dir*201326592;
            *(float2*)(base + (R+g)*192 + lc)   = make_float2(acc[nt][0], acc[nt][1]);
            *(float2*)(base + (R+g+8)*192 + lc) = make_float2(acc[nt][2], acc[nt][3]);
        }
    }
}

// ---- GRU layer 0 hidden recurrence via per-step MMA: 16 seqs per CTA ----
__global__ __launch_bounds__(256,2) void k_gru0m(
    const float* __restrict__ bih, const float* __restrict__ bhh)
{
    int n0 = blockIdx.x * 16, dir = blockIdx.y;
    int tid = threadIdx.x, w = tid >> 5, lane = tid & 31;
    int g = lane >> 2, tig = lane & 3;
    __shared__ uint32_t sHx[2][16*36];
    __shared__ float sH[16*64];
    __shared__ float sG[16*200];
    __shared__ float sBi[192], sBh[192];

    uint32_t bhi[3][4][2], blo_[3][4][2];
    #pragma unroll
    for (int nt = 0; nt < 3; nt++){
        int n = dir*192 + w*24 + nt*8 + g;
        const uint32_t* wp = (const uint32_t*)g_Wh0hi + n*32;
        const uint32_t* wq = (const uint32_t*)g_Wh0lo + n*32;
        #pragma unroll
        for (int kt = 0; kt < 4; kt++){
            bhi[nt][kt][0] = wp[kt*8 + tig];  bhi[nt][kt][1] = wp[kt*8 + 4 + tig];
            blo_[nt][kt][0] = wq[kt*8 + tig]; blo_[nt][kt][1] = wq[kt*8 + 4 + tig];
        }
    }
    if (tid < 192){ sBi[tid] = bih[dir*192 + tid]; sBh[tid] = bhh[dir*192 + tid]; }
    for (int i = tid; i < 16*36; i += 256){ sHx[0][i] = 0u; sHx[1][i] = 0u; }
    for (int i = tid; i < 1024; i += 256) sH[i] = 0.f;
    __syncthreads();

    int q = tid >> 4, pp = tid & 15;
    const float* xgb = g_xg0 + (size_t)dir*201326592 + (size_t)(n0 + q)*256*192;
    int t0 = dir ? 255 : 0;
    float2 xr0, xr1, xr2, xr3, xr4, xr5;
    {
        const float* xp = xgb + (size_t)t0*192;
        xr0 = *(const float2*)(xp + 2*pp);        xr1 = *(const float2*)(xp + 64 + 2*pp);
        xr2 = *(const float2*)(xp + 128 + 2*pp);  xr3 = *(const float2*)(xp + 32 + 2*pp);
        xr4 = *(const float2*)(xp + 96 + 2*pp);   xr5 = *(const float2*)(xp + 160 + 2*pp);
    }
    uint32_t* h0Hu = (uint32_t*)g_h0H;
    uint32_t* h0Lu = (uint32_t*)g_h0L;

    for (int s = 0; s < 256; s++){
        int t = dir ? 255 - s : s;
        float acc[3][4];
        #pragma unroll
        for (int nt=0;nt<3;nt++){ acc[nt][0]=0.f; acc[nt][1]=0.f; acc[nt][2]=0.f; acc[nt][3]=0.f; }
        #pragma unroll
        for (int kt = 0; kt < 4; kt++){
            uint32_t ah0 = sHx[0][g*36 + kt*8 + tig],     ah1 = sHx[0][(g+8)*36 + kt*8 + tig];
            uint32_t ah2 = sHx[0][g*36 + kt*8 + 4 + tig], ah3 = sHx[0][(g+8)*36 + kt*8 + 4 + tig];
            uint32_t al0 = sHx[1][g*36 + kt*8 + tig],     al1 = sHx[1][(g+8)*36 + kt*8 + tig];
            uint32_t al2 = sHx[1][g*36 + kt*8 + 4 + tig], al3 = sHx[1][(g+8)*36 + kt*8 + 4 + tig];
            #pragma unroll
            for (int nt = 0; nt < 3; nt++){
                MMA16816(acc[nt], ah0,ah1,ah2,ah3, bhi[nt][kt][0], bhi[nt][kt][1]);
                MMA16816(acc[nt], al0,al1,al2,al3, bhi[nt][kt][0], bhi[nt][kt][1]);
                MMA16816(acc[nt], ah0,ah1,ah2,ah3, blo_[nt][kt][0], blo_[nt][kt][1]);
            }
        }
        #pragma unroll
        for (int nt = 0; nt < 3; nt++){
            int col = w*24 + nt*8 + tig*2;
            *(float2*)(sG + g*200 + col)     = make_float2(acc[nt][0], acc[nt][1]);
            *(float2*)(sG + (g+8)*200 + col) = make_float2(acc[nt][2], acc[nt][3]);
        }
        __syncthreads();
        // activation for (q, hh=2pp..2pp+1) and (q, hh=2pp+32..2pp+33)
        #pragma unroll
        for (int half = 0; half < 2; half++){
            int hb = 2*pp + half*32;
            float2 xrr = half ? xr3 : xr0;
            float2 xrz = half ? xr4 : xr1;
            float2 xrn = half ? xr5 : xr2;
            float hn[2];
            #pragma unroll
            for (int e = 0; e < 2; e++){
                int hh = hb + e;
                float Gr = sG[q*200 + hh], Gz = sG[q*200 + 64 + hh], Gn = sG[q*200 + 128 + hh];
                float xv_r = e ? xrr.y : xrr.x;
                float xv_z = e ? xrz.y : xrz.x;
                float xv_n = e ? xrn.y : xrn.x;
                float r  = sigf(xv_r + sBi[hh] + Gr + sBh[hh]);
                float z  = sigf(xv_z + sBi[64+hh] + Gz + sBh[64+hh]);
                float nn = tanf_(xv_n + sBi[128+hh] + r*(Gn + sBh[128+hh]));
                hn[e] = (1.f - z)*nn + z*sH[q*64 + hh];
                sH[q*64 + hh] = hn[e];
            }
            __nv_bfloat16 h0h = __float2bfloat16(hn[0]);
            __nv_bfloat16 h1h = __float2bfloat16(hn[1]);
            __nv_bfloat16 h0l = __float2bfloat16(hn[0] - __bfloat162float(h0h));
            __nv_bfloat16 h1l = __float2bfloat16(hn[1] - __bfloat162float(h1h));
            uint32_t hip, lop;
            asm("mov.b32 %0, {%1,%2};" : "=r"(hip) : "h"(*(unsigned short*)&h0h), "h"(*(unsigned short*)&h1h));
            asm("mov.b32 %0, {%1,%2};" : "=r"(lop) : "h"(*(unsigned short*)&h0l), "h"(*(unsigned short*)&h1l));
            int pcol = pp + half*16;
            sHx[0][q*36 + pcol] = hip;
            sHx[1][q*36 + pcol] = lop;
            size_t oidx = ((size_t)(n0+q)*256 + t)*64 + dir*32 + pcol;
            h0Hu[oidx] = hip; h0Lu[oidx] = lop;
        }
        if (s < 255){
            int tn = dir ? 254 - s : s + 1;
            const float* xp = xgb + (size_t)tn*192;
            xr0 = *(const float2*)(xp + 2*pp);        xr1 = *(const float2*)(xp + 64 + 2*pp);
            xr2 = *(const float2*)(xp + 128 + 2*pp);  xr3 = *(const float2*)(xp + 32 + 2*pp);
            xr4 = *(const float2*)(xp + 96 + 2*pp);   xr5 = *(const float2*)(xp + 160 + 2*pp);
        }
        __syncthreads();
    }
}

// ---- mma GEMM: xg1 = h0 @ Wih1^T, double-buffered ----
__global__ __launch_bounds__(256,2) void k_xproj1(){
    __shared__ uint32_t sA[2][16*68];
    int tid = threadIdx.x;
    int w = tid >> 5, lane = tid & 31;
    int g = lane >> 2, tig = lane & 3;
    size_t Rbase = (size_t)blockIdx.x * 1024;

    uint32_t bh[3][8][2];
    #pragma unroll
    for (int nt = 0; nt < 3; nt++){
        int n = w*24 + nt*8 + g;
        const uint32_t* wp = (const uint32_t*)g_W1hi + n*64;
        #pragma unroll
        for (int ks = 0; ks < 8; ks++){
            bh[nt][ks][0] = wp[ks*8 + tig];
            bh[nt][ks][1] = wp[ks*8 + 4 + tig];
        }
    }
    const uint32_t* blo = (const uint32_t*)g_W1lo;
    const uint4* h0Hu = (const uint4*)g_h0H;
    const uint4* h0Lu = (const uint4*)g_h0L;

    int prow = tid >> 4, pc4 = tid & 15;
    uint4 rh = h0Hu[(Rbase + prow)*16 + pc4];
    uint4 rl = h0Lu[(Rbase + prow)*16 + pc4];

    for (int mt = 0; mt < 64; mt++){
        size_t R = Rbase + mt*16;
        __syncthreads();
        {
            int c0 = pc4*4;
            sA[0][prow*68 + c0]   = rh.x; sA[0][prow*68 + c0+1] = rh.y;
            sA[0][prow*68 + c0+2] = rh.z; sA[0][prow*68 + c0+3] = rh.w;
            sA[1][prow*68 + c0]   = rl.x; sA[1][prow*68 + c0+1] = rl.y;
            sA[1][prow*68 + c0+2] = rl.z; sA[1][prow*68 + c0+3] = rl.w;
        }
        __syncthreads();
        if (mt < 63){
            rh = h0Hu[(R + 16 + prow)*16 + pc4];
            rl = h0Lu[(R + 16 + prow)*16 + pc4];
        }
        float acc[3][4];
        #pragma unroll
        for (int nt=0;nt<3;nt++){ acc[nt][0]=0.f; acc[nt][1]=0.f; acc[nt][2]=0.f; acc[nt][3]=0.f; }
        #pragma unroll
        for (int term = 0; term < 3; term++){
            const uint32_t* As = sA[term == 1 ? 1 : 0];
            #pragma unroll
            for (int ks = 0; ks < 8; ks++){
                uint32_t a0 = As[g*68 + ks*8 + tig];
                uint32_t a1 = As[(g+8)*68 + ks*8 + tig];
                uint32_t a2 = As[g*68 + ks*8 + 4 + tig];
                uint32_t a3 = As[(g+8)*68 + ks*8 + 4 + tig];
                #pragma unroll
                for (int nt = 0; nt < 3; nt++){
                    uint32_t b0, b1;
                    if (term < 2){ b0 = bh[nt][ks][0]; b1 = bh[nt][ks][1]; }
                    else {
                        int n = w*24 + nt*8 + g;
                        b0 = __ldg(blo + n*64 + ks*8 + tig);
                        b1 = __ldg(blo + n*64 + ks*8 + 4 + tig);
                    }
                    MMA16816(acc[nt], a0,a1,a2,a3, b0,b1);
                }
            }
        }
        #pragma unroll
        for (int nt = 0; nt < 3; nt++){
            int col = w*24 + nt*8 + tig*2;
            *(float2*)(g_xg1 + (R+g)*192 + col)   = make_float2(acc[nt][0], acc[nt][1]);
            *(float2*)(g_xg1 + (R+g+8)*192 + col) = make_float2(acc[nt][2], acc[nt][3]);
        }
    }
}

// ---- GRU layer 1 fwd hidden recurrence via per-step MMA: 16 seqs per CTA ----
__global__ __launch_bounds__(256,2) void k_gru1m(
    const float* __restrict__ bih, const float* __restrict__ bhh)
{
    int n0 = blockIdx.x * 16;
    int tid = threadIdx.x, w = tid >> 5, lane = tid & 31;
    int g = lane >> 2, tig = lane & 3;
    __shared__ uint32_t sHx[2][16*36];
    __shared__ float sH[16*64];
    __shared__ float sG[16*200];
    __shared__ float sBi[192], sBh[192];

    uint32_t bhi[3][4][2], blo_[3][4][2];
    #pragma unroll
    for (int nt = 0; nt < 3; nt++){
        int n = w*24 + nt*8 + g;
        const uint32_t* wp = (const uint32_t*)g_Wh1hi + n*32;
        const uint32_t* wq = (const uint32_t*)g_Wh1lo + n*32;
        #pragma unroll
        for (int kt = 0; kt < 4; kt++){
            bhi[nt][kt][0] = wp[kt*8 + tig];  bhi[nt][kt][1] = wp[kt*8 + 4 + tig];
            blo_[nt][kt][0] = wq[kt*8 + tig]; blo_[nt][kt][1] = wq[kt*8 + 4 + tig];
        }
    }
    if (tid < 192){ sBi[tid] = bih[tid]; sBh[tid] = bhh[tid]; }
    for (int i = tid; i < 16*36; i += 256){ sHx[0][i] = 0u; sHx[1][i] = 0u; }
    for (int i = tid; i < 1024; i += 256) sH[i] = 0.f;
    __syncthreads();

    int q = tid >> 4, pp = tid & 15;
    const float* xgb = g_xg1 + (size_t)(n0 + q)*256*192;
    float2 xr0, xr1, xr2, xr3, xr4, xr5;
    {
        const float* xp = xgb;
        xr0 = *(const float2*)(xp + 2*pp);        xr1 = *(const float2*)(xp + 64 + 2*pp);
        xr2 = *(const float2*)(xp + 128 + 2*pp);  xr3 = *(const float2*)(xp + 32 + 2*pp);
        xr4 = *(const float2*)(xp + 96 + 2*pp);   xr5 = *(const float2*)(xp + 160 + 2*pp);
    }

    for (int s = 0; s < 256; s++){
        float acc[3][4];
        #pragma unroll
        for (int nt=0;nt<3;nt++){ acc[nt][0]=0.f; acc[nt][1]=0.f; acc[nt][2]=0.f; acc[nt][3]=0.f; }
        #pragma unroll
        for (int kt = 0; kt < 4; kt++){
            uint32_t ah0 = sHx[0][g*36 + kt*8 + tig],     ah1 = sHx[0][(g+8)*36 + kt*8 + tig];
            uint32_t ah2 = sHx[0][g*36 + kt*8 + 4 + tig], ah3 = sHx[0][(g+8)*36 + kt*8 + 4 + tig];
            uint32_t al0 = sHx[1][g*36 + kt*8 + tig],     al1 = sHx[1][(g+8)*36 + kt*8 + tig];
            uint32_t al2 = sHx[1][g*36 + kt*8 + 4 + tig], al3 = sHx[1][(g+8)*36 + kt*8 + 4 + tig];
            #pragma unroll
            for (int nt = 0; nt < 3; nt++){
                MMA16816(acc[nt], ah0,ah1,ah2,ah3, bhi[nt][kt][0], bhi[nt][kt][1]);
                MMA16816(acc[nt], al0,al1,al2,al3, bhi[nt][kt][0], bhi[nt][kt][1]);
                MMA16816(acc[nt], ah0,ah1,ah2,ah3, blo_[nt][kt][0], blo_[nt][kt][1]);
            }
        }
        #pragma unroll
        for (int nt = 0; nt < 3; nt++){
            int col = w*24 + nt*8 + tig*2;
            *(float2*)(sG + g*200 + col)     = make_float2(acc[nt][0], acc[nt][1]);
            *(float2*)(sG + (g+8)*200 + col) = make_float2(acc[nt][2], acc[nt][3]);
        }
        __syncthreads();
        #pragma unroll
        for (int half = 0; half < 2; half++){
            int hb = 2*pp + half*32;
            float2 xrr = half ? xr3 : xr0;
            float2 xrz = half ? xr4 : xr1;
            float2 xrn = half ? xr5 : xr2;
            float hn[2];
            #pragma unroll
            for (int e = 0; e < 2; e++){
                int hh = hb + e;
                float Gr = sG[q*200 + hh], Gz = sG[q*200 + 64 + hh], Gn = sG[q*200 + 128 + hh];
                float xv_r = e ? xrr.y : xrr.x;
                float xv_z = e ? xrz.y : xrz.x;
                float xv_n = e ? xrn.y : xrn.x;
                float r  = sigf(xv_r + sBi[hh] + Gr + sBh[hh]);
                float z  = sigf(xv_z + sBi[64+hh] + Gz + sBh[64+hh]);
                float nn = tanf_(xv_n + sBi[128+hh] + r*(Gn + sBh[128+hh]));
                hn[e] = (1.f - z)*nn + z*sH[q*64 + hh];
                sH[q*64 + hh] = hn[e];
                if (s == 255) g_last[(n0+q)*128 + hh] = hn[e];
            }
            __nv_bfloat16 h0h = __float2bfloat16(hn[0]);
            __nv_bfloat16 h1h = __float2bfloat16(hn[1]);
            __nv_bfloat16 h0l = __float2bfloat16(hn[0] - __bfloat162float(h0h));
            __nv_bfloat16 h1l = __float2bfloat16(hn[1] - __bfloat162float(h1h));
            uint32_t hip, lop;
            asm("mov.b32 %0, {%1,%2};" : "=r"(hip) : "h"(*(unsigned short*)&h0h), "h"(*(unsigned short*)&h1h));
            asm("mov.b32 %0, {%1,%2};" : "=r"(lop) : "h"(*(unsigned short*)&h0l), "h"(*(unsigned short*)&h1l));
            int pcol = pp + half*16;
            sHx[0][q*36 + pcol] = hip;
            sHx[1][q*36 + pcol] = lop;
        }
        if (s < 255){
            const float* xp = xgb + (size_t)(s+1)*192;
            xr0 = *(const float2*)(xp + 2*pp);        xr1 = *(const float2*)(xp + 64 + 2*pp);
            xr2 = *(const float2*)(xp + 128 + 2*pp);  xr3 = *(const float2*)(xp + 32 + 2*pp);
            xr4 = *(const float2*)(xp + 96 + 2*pp);   xr5 = *(const float2*)(xp + 160 + 2*pp);
        }
        __syncthreads();
    }
}

__global__ __launch_bounds__(192,2) void k_gru1b(
    const float* __restrict__ Wih, const float* __restrict__ Whh,
    const float* __restrict__ bih, const float* __restrict__ bhh)
{
    int tid = threadIdx.x;
    __shared__ __align__(16) float sx[128];
    __shared__ float sgi[192];
    ull w[64];
    const ull* p = (const ull*)(Wih + 192UL*128 + (size_t)tid*128);
    #pragma unroll
    for (int k = 0; k < 64; k++) w[k] = p[k];
    float bias = bih[192 + tid];

    for (int it = 0; it < 64; it++){
        int n = blockIdx.x*64 + it;
        if (tid < 128){
            size_t idx = ((size_t)n*256 + 255)*128 + tid;
            sx[tid] = __bfloat162float(g_h0H[idx]) + __bfloat162float(g_h0L[idx]);
        }
        __syncthreads();
        ull a0 = 0, a1 = 0;
        const ulonglong2* v4 = (const ulonglong2*)sx;
        #pragma unroll
        for (int k = 0; k < 32; k++){ ulonglong2 v = v4[k]; fma2(a0, w[2*k], v.x); fma2(a1, w[2*k+1], v.y); }
        sgi[tid] = hsum2(a0) + hsum2(a1) + bias;
        __syncthreads();
        if (tid < 64){
            float r  = sigf(sgi[tid]      + bhh[192 + tid]);
            float z  = sigf(sgi[64 + tid] + bhh[192 + 64 + tid]);
            float nn = tanf_(sgi[128+tid] + r * bhh[192 + 128 + tid]);
            g_last[n*128 + 64 + tid] = (1.f - z)*nn;
        }
    }
}

__global__ __launch_bounds__(128) void k_head(
    const float* __restrict__ pool_W, const float* __restrict__ pool_b,
    const float* __restrict__ mu_W, const float* __restrict__ mu_b,
    const float* __restrict__ logv_W, const float* __restrict__ logv_b,
    const float* __restrict__ dec_W, const float* __restrict__ dec_b,
    const float* __restrict__ lstm_Wih, const float* __restrict__ lstm_bih,
    const float* __restrict__ lstm_bhh,
    float* __restrict__ out)
{
    int b = blockIdx.x, tid = threadIdx.x;
    __shared__ float slast[128], shp[32], smu[32], sdh[64];
    float s = 0.f;
    for (int c = 0; c < 64; c++) s += g_last[(b*64 + c)*128 + tid];
    slast[tid] = s * (1.f/64.f);
    __syncthreads();
    if (tid < 32){
        float acc = pool_b[tid];
        for (int k = 0; k < 128; k++) acc += pool_W[tid*128 + k] * slast[k];
        shp[tid] = fmaxf(acc, 0.f);
    }
    __syncthreads();
    if (tid < 32){
        float acc = mu_b[tid];
        for (int k = 0; k < 32; k++) acc += mu_W[tid*32 + k] * shp[k];
        smu[tid] = acc;
        out[64UL*256*64 + b*32 + tid] = acc;
    } else if (tid < 64){
        int j = tid - 32;
        float acc = logv_b[j];
        for (int k = 0; k < 32; k++) acc += logv_W[j*32 + k] * shp[k];
        out[64UL*256*64 + 2048 + b*32 + j] = acc;
    }
    __syncthreads();
    if (tid < 64){
        float acc = dec_b[tid];
        for (int k = 0; k < 32; k++) acc += dec_W[tid*32 + k] * smu[k];
        sdh[tid] = fmaxf(acc, 0.f);
    }
    __syncthreads();
    for (int gate = tid; gate < 256; gate += 128){
        float acc = lstm_bih[gate] + lstm_bhh[gate];
        for (int k = 0; k < 64; k++) acc += lstm_Wih[gate*64 + k] * sdh[k];
        g_dxg[b*256 + gate] = acc;
    }
}

__global__ __launch_bounds__(256,1) void k_lstm1(const float* __restrict__ Whh)
{
    int b = blockIdx.x, tid = threadIdx.x;
    __shared__ __align__(16) float sh[64];
    __shared__ float sg[256];
    ull w[32];
    const ull* p = (const ull*)(Whh + (size_t)tid*64);
    #pragma unroll
    for (int k = 0; k < 32; k++) w[k] = p[k];
    float dxg = g_dxg[b*256 + tid];
    if (tid < 64) sh[tid] = 0.f;
    float c = 0.f;
    for (int t = 0; t < 256; t++){
        __syncthreads();
        ull a0 = 0, a1 = 0;
        const ulonglong2* v4 = (const ulonglong2*)sh;
        #pragma unroll
        for (int k = 0; k < 16; k++){ ulonglong2 v = v4[k]; fma2(a0, w[2*k], v.x); fma2(a1, w[2*k+1], v.y); }
        sg[tid] = hsum2(a0) + hsum2(a1) + dxg;
        __syncthreads();
        if (tid < 64){
            float i_ = sigf(sg[tid]), f_ = sigf(sg[64+tid]);
            float gg = tanf_(sg[128+tid]), o_ = sigf(sg[192+tid]);
            c = f_*c + i_*gg;
            float h = o_*tanf_(c);
            sh[tid] = h;
            g_h1d[((size_t)b*256 + t)*64 + tid] = h;
        }
    }
}

__global__ __launch_bounds__(256,1) void k_lstm2(
    const float* __restrict__ Wih, const float* __restrict__ Whh,
    const float* __restrict__ bih, const float* __restrict__ bhh,
    const float* __restrict__ out_W, const float* __restrict__ out_b,
    float* __restrict__ out)
{
    int b = blockIdx.x, tid = threadIdx.x;
    __shared__ __align__(16) float sx[64];
    __shared__ __align__(16) float sh[64];
    __shared__ float sg[256];
    __shared__ float soW[64*64];
    for (int i = tid; i < 4096; i += 256){ int c = i >> 6, k = i & 63; soW[k*64 + c] = out_W[i]; }
    ull wi[32], wh[32];
    const ull* p = (const ull*)(Wih + 256UL*64 + (size_t)tid*64);
    const ull* q = (const ull*)(Whh + 256UL*64 + (size_t)tid*64);
    #pragma unroll
    for (int k = 0; k < 32; k++){ wi[k] = p[k]; wh[k] = q[k]; }
    float bias = bih[256 + tid] + bhh[256 + tid];
    if (tid < 64) sh[tid] = 0.f;
    float c = 0.f;
    float ob = (tid >= 64 && tid < 128) ? out_b[tid - 64] : 0.f;
    const float* xb = g_h1d + (size_t)b*256*64;
    for (int t = 0; t < 256; t++){
        if (tid < 64) sx[tid] = xb[t*64 + tid];
        __syncthreads();
        ull a0 = 0, a1 = 0;
        const ulonglong2* x4 = (const ulonglong2*)sx;
        const ulonglong2* h4 = (const ulonglong2*)sh;
        #pragma unroll
        for (int k = 0; k < 16; k++){ ulonglong2 v = x4[k]; fma2(a0, wi[2*k], v.x); fma2(a1, wi[2*k+1], v.y); }
        #pragma unroll
        for (int k = 0; k < 16; k++){ ulonglong2 v = h4[k]; fma2(a0, wh[2*k], v.x); fma2(a1, wh[2*k+1], v.y); }
        sg[tid] = hsum2(a0) + hsum2(a1) + bias;
        __syncthreads();
        if (tid < 64){
            float i_ = sigf(sg[tid]), f_ = sigf(sg[64+tid]);
            float gg = tanf_(sg[128+tid]), o_ = sigf(sg[192+tid]);
            c = f_*c + i_*gg;
            sh[tid] = o_*tanf_(c);
        }
        __syncthreads();
        if (tid >= 64 && tid < 128){
            int cc = tid - 64;
            float acc = ob;
            #pragma unroll 8
            for (int k = 0; k < 64; k++) acc += soW[k*64 + cc] * sh[k];
            out[((size_t)b*256 + t)*64 + cc] = acc;
        }
    }
}

extern "C" void kernel_launch(void* const* d_in, const int* in_sizes, int n_in,
                              void* d_out, int out_size)
{
    const float* x      = (const float*)d_in[0];
    const float* adj1   = (const float*)d_in[1];
    const float* W1     = (const float*)d_in[2];
    const float* b1     = (const float*)d_in[3];
    const float* adj2   = (const float*)d_in[4];
    const float* W2     = (const float*)d_in[5];
    const float* b2     = (const float*)d_in[6];
    const float* ln_g   = (const float*)d_in[7];
    const float* ln_b   = (const float*)d_in[8];
    const float* g0Wih  = (const float*)d_in[9];
    const float* g0Whh  = (const float*)d_in[10];
    const float* g0bih  = (const float*)d_in[11];
    const float* g0bhh  = (const float*)d_in[12];
    const float* g1Wih  = (const float*)d_in[13];
    const float* g1Whh  = (const float*)d_in[14];
    const float* g1bih  = (const float*)d_in[15];
    const float* g1bhh  = (const float*)d_in[16];
    const float* pool_W = (const float*)d_in[17];
    const float* pool_b = (const float*)d_in[18];
    const float* mu_W   = (const float*)d_in[19];
    const float* mu_b   = (const float*)d_in[20];
    const float* logv_W = (const float*)d_in[21];
    const float* logv_b = (const float*)d_in[22];
    const float* dec_W  = (const float*)d_in[23];
    const float* dec_b  = (const float*)d_in[24];
    const float* lWih   = (const float*)d_in[25];
    const float* lWhh   = (const float*)d_in[26];
    const float* lbih   = (const float*)d_in[27];
    const float* lbhh   = (const float*)d_in[28];
    const float* out_W  = (const float*)d_in[29];
    const float* out_b  = (const float*)d_in[30];
    float* out = (float*)d_out;

    k_softmax<<<1, 64>>>(adj1, adj2);
    k_prepW<<<1, 256>>>(g1Wih, g0Wih, g0Whh, g1Whh);
    k_gnn<<<16384, 256>>>(x, W1, b1, W2, b2, ln_g, ln_b);
    k_xproj0<<<1024, 256>>>();
    k_gru0m<<<dim3(256, 2), 256>>>(g0bih, g0bhh);
    k_xproj1<<<1024, 256>>>();
    k_gru1m<<<256, 256>>>(g1bih, g1bhh);
    k_gru1b<<<64, 192>>>(g1Wih, g1Whh, g1bih, g1bhh);
    k_head<<<64, 128>>>(pool_W, pool_b, mu_W, mu_b, logv_W, logv_b,
                        dec_W, dec_b, lWih, lbih, lbhh, out);
    k_lstm1<<<64, 256>>>(lWhh);
    k_lstm2<<<64, 256>>>(lWih, lWhh, lbih, lbhh, out_W, out_b, out);
}

// round 15
// speedup vs baseline: 1.8414x; 1.0671x over previous
#include <cuda_runtime.h>
#include <cuda_bf16.h>
#include <cstdint>
#include <math.h>

typedef unsigned long long ull;

__device__ float g_A1[64*64];
__device__ float g_A2[64*64];
__device__ __nv_bfloat16 g_hencH[4096UL*256*32];
__device__ __nv_bfloat16 g_hencL[4096UL*256*32];
__device__ __nv_bfloat16 g_h0H[4096UL*256*128];
__device__ __nv_bfloat16 g_h0L[4096UL*256*128];
__device__ __nv_bfloat16 g_W1hi[192*128];
__device__ __nv_bfloat16 g_W1lo[192*128];
__device__ __nv_bfloat16 g_W0hi[384*32];
__device__ __nv_bfloat16 g_W0lo[384*32];
__device__ __nv_bfloat16 g_Wh0hi[384*64];
__device__ __nv_bfloat16 g_Wh0lo[384*64];
__device__ __nv_bfloat16 g_Wh1hi[192*64];
__device__ __nv_bfloat16 g_Wh1lo[192*64];
__device__ float g_xg1[4096UL*256*192];
__device__ float g_last[4096*128];
__device__ float g_dxg[64*256];
__device__ float g_h1d[64UL*256*64];

__device__ __forceinline__ void fma2(ull &acc, ull a, ull b){
    asm("fma.rn.f32x2 %0, %1, %2, %0;" : "+l"(acc) : "l"(a), "l"(b));
}
__device__ __forceinline__ float hsum2(ull a){
    float lo, hi; asm("mov.b64 {%0,%1}, %2;" : "=f"(lo), "=f"(hi) : "l"(a));
    return lo + hi;
}
__device__ __forceinline__ float sigf(float x){
    return __fdividef(1.f, 1.f + __expf(-x));
}
__device__ __forceinline__ float tanf_(float x){
    return __fmaf_rn(2.f, __fdividef(1.f, 1.f + __expf(-2.f*x)), -1.f);
}
#define MMA16816(acc, A0,A1,A2,A3, B0,B1) \
    asm volatile("mma.sync.aligned.m16n8k16.row.col.f32.bf16.bf16.f32 " \
        "{%0,%1,%2,%3}, {%4,%5,%6,%7}, {%8,%9}, {%0,%1,%2,%3};" \
        : "+f"(acc[0]), "+f"(acc[1]), "+f"(acc[2]), "+f"(acc[3]) \
        : "r"(A0), "r"(A1), "r"(A2), "r"(A3), "r"(B0), "r"(B1))

__global__ void k_softmax(const float* __restrict__ adj1, const float* __restrict__ adj2){
    int i = threadIdx.x;
    for (int w = 0; w < 2; w++){
        const float* a = w ? adj2 : adj1;
        float* o = w ? g_A2 : g_A1;
        float mx = -1e30f;
        for (int j = 0; j < 64; j++) mx = fmaxf(mx, a[i*64+j]);
        float s = 0.f;
        for (int j = 0; j < 64; j++) s += expf(a[i*64+j] - mx);
        float inv = 1.f / s;
        for (int j = 0; j < 64; j++) o[i*64+j] = expf(a[i*64+j] - mx) * inv;
    }
}

__global__ void k_prepW(const float* __restrict__ W1, const float* __restrict__ W0,
                        const float* __restrict__ Wh0, const float* __restrict__ Wh1){
    for (int i = threadIdx.x; i < 24576; i += 256){
        float v = W1[i];
        __nv_bfloat16 hi = __float2bfloat16(v);
        g_W1hi[i] = hi; g_W1lo[i] = __float2bfloat16(v - __bfloat162float(hi));
    }
    for (int i = threadIdx.x; i < 12288; i += 256){
        float v = W0[i];
        __nv_bfloat16 hi = __float2bfloat16(v);
        g_W0hi[i] = hi; g_W0lo[i] = __float2bfloat16(v - __bfloat162float(hi));
    }
    for (int i = threadIdx.x; i < 24576; i += 256){
        float v = Wh0[i];
        __nv_bfloat16 hi = __float2bfloat16(v);
        g_Wh0hi[i] = hi; g_Wh0lo[i] = __float2bfloat16(v - __bfloat162float(hi));
    }
    for (int i = threadIdx.x; i < 12288; i += 256){
        float v = Wh1[i];
        __nv_bfloat16 hi = __float2bfloat16(v);
        g_Wh1hi[i] = hi; g_Wh1lo[i] = __float2bfloat16(v - __bfloat162float(hi));
    }
}

__global__ __launch_bounds__(256) void k_gnn(
    const float* __restrict__ x,
    const float* __restrict__ W1, const float* __restrict__ b1,
    const float* __restrict__ W2, const float* __restrict__ b2,
    const float* __restrict__ lng, const float* __restrict__ lnb)
{
    int bt = blockIdx.x;
    int b = bt >> 8, t = bt & 255;
    int tid = threadIdx.x;

    __shared__ float sA2[64*65];
    __shared__ float sW2t[1024];
    __shared__ __align__(16) float sx[64];
    __shared__ float s1[64];
    __shared__ __align__(16) float sh1[2048];
    __shared__ __align__(16) float sagg[2048];
    __shared__ float sh2[64*33];
    __shared__ float sW1[32], sb1[32], sb2[32], slg[32], slb[32];
    __shared__ float smean[64], srstd[64];

    for (int i = tid; i < 4096; i += 256) sA2[(i>>6)*65 + (i&63)] = g_A2[i];
    for (int i = tid; i < 1024; i += 256){ int gp = i>>5, k = i&31; sW2t[k*32+gp] = W2[i]; }
    if (tid < 64) sx[tid] = x[(size_t)bt*64 + tid];
    if (tid < 32){ sW1[tid]=W1[tid]; sb1[tid]=b1[tid]; sb2[tid]=b2[tid]; slg[tid]=lng[tid]; slb[tid]=lnb[tid]; }
    __syncthreads();

    if (tid < 64){
        float s = 0.f; const float* a = g_A1 + tid*64;
        #pragma unroll 8
        for (int j = 0; j < 64; j++) s += a[j]*sx[j];
        s1[tid] = s;
    }
    __syncthreads();
    for (int i = tid; i < 2048; i += 256){ int j = i>>5, g = i&31; sh1[i] = fmaxf(sW1[g]*s1[j] + sb1[g], 0.f); }
    __syncthreads();
    {
        int i = tid >> 2, g0 = (tid & 3) * 8;
        float4 a0 = {0,0,0,0}, a1 = {0,0,0,0};
        #pragma unroll 4
        for (int j = 0; j < 64; j++){
            float a = sA2[i*65 + j];
            float4 h0 = *(const float4*)(sh1 + j*32 + g0);
            float4 h1 = *(const float4*)(sh1 + j*32 + g0 + 4);
            a0.x += a*h0.x; a0.y += a*h0.y; a0.z += a*h0.z; a0.w += a*h0.w;
            a1.x += a*h1.x; a1.y += a*h1.y; a1.z += a*h1.z; a1.w += a*h1.w;
        }
        *(float4*)(sagg + i*32 + g0)     = a0;
        *(float4*)(sagg + i*32 + g0 + 4) = a1;
    }
    __syncthreads();
    #pragma unroll
    for (int q = 0; q < 8; q++){
        int idx = tid + (q << 8);
        int i = idx >> 5, gp = idx & 31;
        float acc = sb2[gp];
        #pragma unroll 8
        for (int k = 0; k < 32; k++) acc += sagg[i*32 + k] * sW2t[k*32 + gp];
        sh2[i*33 + gp] = fmaxf(acc, 0.f);
    }
    __syncthreads();
    if (tid < 64){
        float m = 0.f;
        for (int g = 0; g < 32; g++) m += sh2[tid*33 + g];
        m *= (1.f/32.f);
        float v = 0.f;
        for (int g = 0; g < 32; g++){ float d = sh2[tid*33 + g] - m; v += d*d; }
        v *= (1.f/32.f);
        smean[tid] = m; srstd[tid] = rsqrtf(v + 1e-5f);
    }
    __syncthreads();
    for (int idx = tid; idx < 2048; idx += 256){
        int i = idx >> 5, g = idx & 31;
        float val = (sh2[i*33 + g] - smean[i]) * srstd[i] * slg[g] + slb[g];
        size_t o = (((size_t)b*64 + i)*256 + t)*32 + g;
        __nv_bfloat16 hi = __float2bfloat16(val);
        g_hencH[o] = hi;
        g_hencL[o] = __float2bfloat16(val - __bfloat162float(hi));
    }
}

// ---- GRU layer 0: fused input-proj + hidden recurrence via per-step MMA ----
__global__ __launch_bounds__(256,2) void k_gru0f(
    const float* __restrict__ bih, const float* __restrict__ bhh)
{
    int n0 = blockIdx.x * 16, dir = blockIdx.y;
    int tid = threadIdx.x, w = tid >> 5, lane = tid & 31;
    int g = lane >> 2, tig = lane & 3;
    __shared__ uint32_t sHx[2][16*36];
    __shared__ uint32_t sXh[2][16*20];
    __shared__ float sH[16*64];
    __shared__ float sG[16*266];
    __shared__ float sBi[192], sBh[192];

    // hidden weight frags (hi+lo in regs, proven in gru0m)
    uint32_t bhi[3][4][2], blo_[3][4][2];
    // input weight frags: hi in regs, lo via __ldg
    uint32_t xbh[3][2][2];
    #pragma unroll
    for (int nt = 0; nt < 3; nt++){
        int n = dir*192 + w*24 + nt*8 + g;
        const uint32_t* wp = (const uint32_t*)g_Wh0hi + n*32;
        const uint32_t* wq = (const uint32_t*)g_Wh0lo + n*32;
        #pragma unroll
        for (int kt = 0; kt < 4; kt++){
            bhi[nt][kt][0] = wp[kt*8 + tig];  bhi[nt][kt][1] = wp[kt*8 + 4 + tig];
            blo_[nt][kt][0] = wq[kt*8 + tig]; blo_[nt][kt][1] = wq[kt*8 + 4 + tig];
        }
        const uint32_t* xp = (const uint32_t*)g_W0hi + n*16;
        #pragma unroll
        for (int ks = 0; ks < 2; ks++){
            xbh[nt][ks][0] = xp[ks*8 + tig]; xbh[nt][ks][1] = xp[ks*8 + 4 + tig];
        }
    }
    const uint32_t* xblo = (const uint32_t*)g_W0lo;
    if (tid < 192){ sBi[tid] = bih[dir*192 + tid]; sBh[tid] = bhh[dir*192 + tid]; }
    for (int i = tid; i < 16*36; i += 256){ sHx[0][i] = 0u; sHx[1][i] = 0u; }
    for (int i = tid; i < 1024; i += 256) sH[i] = 0.f;

    int prow = tid >> 4, pc = tid & 15;
    const uint32_t* heH = (const uint32_t*)g_hencH;
    const uint32_t* heL = (const uint32_t*)g_hencL;
    size_t hrow = (size_t)(n0 + prow)*256;
    int t0 = dir ? 255 : 0;
    uint32_t rxh = heH[(hrow + t0)*16 + pc];
    uint32_t rxl = heL[(hrow + t0)*16 + pc];
    __syncthreads();
    sXh[0][prow*20 + pc] = rxh;
    sXh[1][prow*20 + pc] = rxl;
    __syncthreads();
    {
        int t1 = dir ? 254 : 1;
        rxh = heH[(hrow + t1)*16 + pc];
        rxl = heL[(hrow + t1)*16 + pc];
    }

    int q = tid >> 4, pp = tid & 15;
    uint32_t* h0Hu = (uint32_t*)g_h0H;
    uint32_t* h0Lu = (uint32_t*)g_h0L;

    for (int s = 0; s < 256; s++){
        int t = dir ? 255 - s : s;
        float accA[3][4], accB[3][4];
        #pragma unroll
        for (int nt=0;nt<3;nt++){
            accA[nt][0]=0.f; accA[nt][1]=0.f; accA[nt][2]=0.f; accA[nt][3]=0.f;
            accB[nt][0]=0.f; accB[nt][1]=0.f; accB[nt][2]=0.f; accB[nt][3]=0.f;
        }
        // hidden MMAs
        #pragma unroll
        for (int kt = 0; kt < 4; kt++){
            uint32_t ah0 = sHx[0][g*36 + kt*8 + tig],     ah1 = sHx[0][(g+8)*36 + kt*8 + tig];
            uint32_t ah2 = sHx[0][g*36 + kt*8 + 4 + tig], ah3 = sHx[0][(g+8)*36 + kt*8 + 4 + tig];
            uint32_t al0 = sHx[1][g*36 + kt*8 + tig],     al1 = sHx[1][(g+8)*36 + kt*8 + tig];
            uint32_t al2 = sHx[1][g*36 + kt*8 + 4 + tig], al3 = sHx[1][(g+8)*36 + kt*8 + 4 + tig];
            #pragma unroll
            for (int nt = 0; nt < 3; nt++){
                MMA16816(accA[nt], ah0,ah1,ah2,ah3, bhi[nt][kt][0], bhi[nt][kt][1]);
                MMA16816(accA[nt], al0,al1,al2,al3, bhi[nt][kt][0], bhi[nt][kt][1]);
                MMA16816(accA[nt], ah0,ah1,ah2,ah3, blo_[nt][kt][0], blo_[nt][kt][1]);
            }
        }
        // input MMAs
        #pragma unroll
        for (int ks = 0; ks < 2; ks++){
            uint32_t xh0 = sXh[0][g*20 + ks*8 + tig],     xh1 = sXh[0][(g+8)*20 + ks*8 + tig];
            uint32_t xh2 = sXh[0][g*20 + ks*8 + 4 + tig], xh3 = sXh[0][(g+8)*20 + ks*8 + 4 + tig];
            uint32_t xl0 = sXh[1][g*20 + ks*8 + tig],     xl1 = sXh[1][(g+8)*20 + ks*8 + tig];
            uint32_t xl2 = sXh[1][g*20 + ks*8 + 4 + tig], xl3 = sXh[1][(g+8)*20 + ks*8 + 4 + tig];
            #pragma unroll
            for (int nt = 0; nt < 3; nt++){
                int n = dir*192 + w*24 + nt*8 + g;
                uint32_t bl0 = __ldg(xblo + n*16 + ks*8 + tig);
                uint32_t bl1 = __ldg(xblo + n*16 + ks*8 + 4 + tig);
                MMA16816(accB[nt], xh0,xh1,xh2,xh3, xbh[nt][ks][0], xbh[nt][ks][1]);
                MMA16816(accB[nt], xl0,xl1,xl2,xl3, xbh[nt][ks][0], xbh[nt][ks][1]);
                MMA16816(accB[nt], xh0,xh1,xh2,xh3, bl0, bl1);
            }
        }
        #pragma unroll
        for (int nt = 0; nt < 3; nt++){
            int col = w*24 + nt*8 + tig*2;
            if (col < 128){
                *(float2*)(sG + g*266 + col)     = make_float2(accA[nt][0]+accB[nt][0], accA[nt][1]+accB[nt][1]);
                *(float2*)(sG + (g+8)*266 + col) = make_float2(accA[nt][2]+accB[nt][2], accA[nt][3]+accB[nt][3]);
            } else {
                *(float2*)(sG + g*266 + col)          = make_float2(accA[nt][0], accA[nt][1]);
                *(float2*)(sG + (g+8)*266 + col)      = make_float2(accA[nt][2], accA[nt][3]);
                *(float2*)(sG + g*266 + col + 64)     = make_float2(accB[nt][0], accB[nt][1]);
                *(float2*)(sG + (g+8)*266 + col + 64) = make_float2(accB[nt][2], accB[nt][3]);
            }
        }
        __syncthreads();
        #pragma unroll
        for (int half = 0; half < 2; half++){
            int hb = 2*pp + half*32;
            float hn[2];
            #pragma unroll
            for (int e = 0; e < 2; e++){
                int hh = hb + e;
                float Gr  = sG[q*266 + hh];
                float Gz  = sG[q*266 + 64 + hh];
                float Gnh = sG[q*266 + 128 + hh];
                float Gnx = sG[q*266 + 192 + hh];
                float r  = sigf(Gr + sBi[hh] + sBh[hh]);
                float z  = sigf(Gz + sBi[64+hh] + sBh[64+hh]);
                float nn = tanf_(Gnx + sBi[128+hh] + r*(Gnh + sBh[128+hh]));
                hn[e] = (1.f - z)*nn + z*sH[q*64 + hh];
                sH[q*64 + hh] = hn[e];
            }
            __nv_bfloat16 h0h = __float2bfloat16(hn[0]);
            __nv_bfloat16 h1h = __float2bfloat16(hn[1]);
            __nv_bfloat16 h0l = __float2bfloat16(hn[0] - __bfloat162float(h0h));
            __nv_bfloat16 h1l = __float2bfloat16(hn[1] - __bfloat162float(h1h));
            uint32_t hip, lop;
            asm("mov.b32 %0, {%1,%2};" : "=r"(hip) : "h"(*(unsigned short*)&h0h), "h"(*(unsigned short*)&h1h));
            asm("mov.b32 %0, {%1,%2};" : "=r"(lop) : "h"(*(unsigned short*)&h0l), "h"(*(unsigned short*)&h1l));
            int pcol = pp + half*16;
            sHx[0][q*36 + pcol] = hip;
            sHx[1][q*36 + pcol] = lop;
            size_t oidx = ((size_t)(n0+q)*256 + t)*64 + dir*32 + pcol;
            h0Hu[oidx] = hip; h0Lu[oidx] = lop;
        }
        if (s < 255){
            sXh[0][prow*20 + pc] = rxh;
            sXh[1][prow*20 + pc] = rxl;
            if (s < 254){
                int tn2 = dir ? 253 - s : s + 2;
                rxh = heH[(hrow + tn2)*16 + pc];
                rxl = heL[(hrow + tn2)*16 + pc];
            }
        }
        __syncthreads();
    }
}

// ---- mma GEMM: xg1 = h0 @ Wih1^T, double-buffered ----
__global__ __launch_bounds__(256,2) void k_xproj1(){
    __shared__ uint32_t sA[2][16*68];
    int tid = threadIdx.x;
    int w = tid >> 5, lane = tid & 31;
    int g = lane >> 2, tig = lane & 3;
    size_t Rbase = (size_t)blockIdx.x * 1024;

    uint32_t bh[3][8][2];
    #pragma unroll
    for (int nt = 0; nt < 3; nt++){
        int n = w*24 + nt*8 + g;
        const uint32_t* wp = (const uint32_t*)g_W1hi + n*64;
        #pragma unroll
        for (int ks = 0; ks < 8; ks++){
            bh[nt][ks][0] = wp[ks*8 + tig];
            bh[nt][ks][1] = wp[ks*8 + 4 + tig];
        }
    }
    const uint32_t* blo = (const uint32_t*)g_W1lo;
    const uint4* h0Hu = (const uint4*)g_h0H;
    const uint4* h0Lu = (const uint4*)g_h0L;

    int prow = tid >> 4, pc4 = tid & 15;
    uint4 rh = h0Hu[(Rbase + prow)*16 + pc4];
    uint4 rl = h0Lu[(Rbase + prow)*16 + pc4];

    for (int mt = 0; mt < 64; mt++){
        size_t R = Rbase + mt*16;
        __syncthreads();
        {
            int c0 = pc4*4;
            sA[0][prow*68 + c0]   = rh.x; sA[0][prow*68 + c0+1] = rh.y;
            sA[0][prow*68 + c0+2] = rh.z; sA[0][prow*68 + c0+3] = rh.w;
            sA[1][prow*68 + c0]   = rl.x; sA[1][prow*68 + c0+1] = rl.y;
            sA[1][prow*68 + c0+2] = rl.z; sA[1][prow*68 + c0+3] = rl.w;
        }
        __syncthreads();
        if (mt < 63){
            rh = h0Hu[(R + 16 + prow)*16 + pc4];
            rl = h0Lu[(R + 16 + prow)*16 + pc4];
        }
        float acc[3][4];
        #pragma unroll
        for (int nt=0;nt<3;nt++){ acc[nt][0]=0.f; acc[nt][1]=0.f; acc[nt][2]=0.f; acc[nt][3]=0.f; }
        #pragma unroll
        for (int term = 0; term < 3; term++){
            const uint32_t* As = sA[term == 1 ? 1 : 0];
            #pragma unroll
            for (int ks = 0; ks < 8; ks++){
                uint32_t a0 = As[g*68 + ks*8 + tig];
                uint32_t a1 = As[(g+8)*68 + ks*8 + tig];
                uint32_t a2 = As[g*68 + ks*8 + 4 + tig];
                uint32_t a3 = As[(g+8)*68 + ks*8 + 4 + tig];
                #pragma unroll
                for (int nt = 0; nt < 3; nt++){
                    uint32_t b0, b1;
                    if (term < 2){ b0 = bh[nt][ks][0]; b1 = bh[nt][ks][1]; }
                    else {
                        int n = w*24 + nt*8 + g;
                        b0 = __ldg(blo + n*64 + ks*8 + tig);
                        b1 = __ldg(blo + n*64 + ks*8 + 4 + tig);
                    }
                    MMA16816(acc[nt], a0,a1,a2,a3, b0,b1);
                }
            }
        }
        #pragma unroll
        for (int nt = 0; nt < 3; nt++){
            int col = w*24 + nt*8 + tig*2;
            *(float2*)(g_xg1 + (R+g)*192 + col)   = make_float2(acc[nt][0], acc[nt][1]);
            *(float2*)(g_xg1 + (R+g+8)*192 + col) = make_float2(acc[nt][2], acc[nt][3]);
        }
    }
}

// ---- GRU layer 1 fwd hidden recurrence via per-step MMA: 16 seqs per CTA ----
__global__ __launch_bounds__(256,2) void k_gru1m(
    const float* __restrict__ bih, const float* __restrict__ bhh)
{
    int n0 = blockIdx.x * 16;
    int tid = threadIdx.x, w = tid >> 5, lane = tid & 31;
    int g = lane >> 2, tig = lane & 3;
    __shared__ uint32_t sHx[2][16*36];
    __shared__ float sH[16*64];
    __shared__ float sG[16*200];
    __shared__ float sBi[192], sBh[192];

    uint32_t bhi[3][4][2], blo_[3][4][2];
    #pragma unroll
    for (int nt = 0; nt < 3; nt++){
        int n = w*24 + nt*8 + g;
        const uint32_t* wp = (const uint32_t*)g_Wh1hi + n*32;
        const uint32_t* wq = (const uint32_t*)g_Wh1lo + n*32;
        #pragma unroll
        for (int kt = 0; kt < 4; kt++){
            bhi[nt][kt][0] = wp[kt*8 + tig];  bhi[nt][kt][1] = wp[kt*8 + 4 + tig];
            blo_[nt][kt][0] = wq[kt*8 + tig]; blo_[nt][kt][1] = wq[kt*8 + 4 + tig];
        }
    }
    if (tid < 192){ sBi[tid] = bih[tid]; sBh[tid] = bhh[tid]; }
    for (int i = tid; i < 16*36; i += 256){ sHx[0][i] = 0u; sHx[1][i] = 0u; }
    for (int i = tid; i < 1024; i += 256) sH[i] = 0.f;
    __syncthreads();

    int q = tid >> 4, pp = tid & 15;
    const float* xgb = g_xg1 + (size_t)(n0 + q)*256*192;
    float2 xr0, xr1, xr2, xr3, xr4, xr5;
    {
        const float* xp = xgb;
        xr0 = *(const float2*)(xp + 2*pp);        xr1 = *(const float2*)(xp + 64 + 2*pp);
        xr2 = *(const float2*)(xp + 128 + 2*pp);  xr3 = *(const float2*)(xp + 32 + 2*pp);
        xr4 = *(const float2*)(xp + 96 + 2*pp);   xr5 = *(const float2*)(xp + 160 + 2*pp);
    }

    for (int s = 0; s < 256; s++){
        float acc[3][4];
        #pragma unroll
        for (int nt=0;nt<3;nt++){ acc[nt][0]=0.f; acc[nt][1]=0.f; acc[nt][2]=0.f; acc[nt][3]=0.f; }
        #pragma unroll
        for (int kt = 0; kt < 4; kt++){
            uint32_t ah0 = sHx[0][g*36 + kt*8 + tig],     ah1 = sHx[0][(g+8)*36 + kt*8 + tig];
            uint32_t ah2 = sHx[0][g*36 + kt*8 + 4 + tig], ah3 = sHx[0][(g+8)*36 + kt*8 + 4 + tig];
            uint32_t al0 = sHx[1][g*36 + kt*8 + tig],     al1 = sHx[1][(g+8)*36 + kt*8 + tig];
            uint32_t al2 = sHx[1][g*36 + kt*8 + 4 + tig], al3 = sHx[1][(g+8)*36 + kt*8 + 4 + tig];
            #pragma unroll
            for (int nt = 0; nt < 3; nt++){
                MMA16816(acc[nt], ah0,ah1,ah2,ah3, bhi[nt][kt][0], bhi[nt][kt][1]);
                MMA16816(acc[nt], al0,al1,al2,al3, bhi[nt][kt][0], bhi[nt][kt][1]);
                MMA16816(acc[nt], ah0,ah1,ah2,ah3, blo_[nt][kt][0], blo_[nt][kt][1]);
            }
        }
        #pragma unroll
        for (int nt = 0; nt < 3; nt++){
            int col = w*24 + nt*8 + tig*2;
            *(float2*)(sG + g*200 + col)     = make_float2(acc[nt][0], acc[nt][1]);
            *(float2*)(sG + (g+8)*200 + col) = make_float2(acc[nt][2], acc[nt][3]);
        }
        __syncthreads();
        #pragma unroll
        for (int half = 0; half < 2; half++){
            int hb = 2*pp + half*32;
            float2 xrr = half ? xr3 : xr0;
            float2 xrz = half ? xr4 : xr1;
            float2 xrn = half ? xr5 : xr2;
            float hn[2];
            #pragma unroll
            for (int e = 0; e < 2; e++){
                int hh = hb + e;
                float Gr = sG[q*200 + hh], Gz = sG[q*200 + 64 + hh], Gn = sG[q*200 + 128 + hh];
                float xv_r = e ? xrr.y : xrr.x;
                float xv_z = e ? xrz.y : xrz.x;
                float xv_n = e ? xrn.y : xrn.x;
                float r  = sigf(xv_r + sBi[hh] + Gr + sBh[hh]);
                float z  = sigf(xv_z + sBi[64+hh] + Gz + sBh[64+hh]);
                float nn = tanf_(xv_n + sBi[128+hh] + r*(Gn + sBh[128+hh]));
                hn[e] = (1.f - z)*nn + z*sH[q*64 + hh];
                sH[q*64 + hh] = hn[e];
                if (s == 255) g_last[(n0+q)*128 + hh] = hn[e];
            }
            __nv_bfloat16 h0h = __float2bfloat16(hn[0]);
            __nv_bfloat16 h1h = __float2bfloat16(hn[1]);
            __nv_bfloat16 h0l = __float2bfloat16(hn[0] - __bfloat162float(h0h));
            __nv_bfloat16 h1l = __float2bfloat16(hn[1] - __bfloat162float(h1h));
            uint32_t hip, lop;
            asm("mov.b32 %0, {%1,%2};" : "=r"(hip) : "h"(*(unsigned short*)&h0h), "h"(*(unsigned short*)&h1h));
            asm("mov.b32 %0, {%1,%2};" : "=r"(lop) : "h"(*(unsigned short*)&h0l), "h"(*(unsigned short*)&h1l));
            int pcol = pp + half*16;
            sHx[0][q*36 + pcol] = hip;
            sHx[1][q*36 + pcol] = lop;
        }
        if (s < 255){
            const float* xp = xgb + (size_t)(s+1)*192;
            xr0 = *(const float2*)(xp + 2*pp);        xr1 = *(const float2*)(xp + 64 + 2*pp);
            xr2 = *(const float2*)(xp + 128 + 2*pp);  xr3 = *(const float2*)(xp + 32 + 2*pp);
            xr4 = *(const float2*)(xp + 96 + 2*pp);   xr5 = *(const float2*)(xp + 160 + 2*pp);
        }
        __syncthreads();
    }
}

__global__ __launch_bounds__(192,2) void k_gru1b(
    const float* __restrict__ Wih, const float* __restrict__ Whh,
    const float* __restrict__ bih, const float* __restrict__ bhh)
{
    int tid = threadIdx.x;
    __shared__ __align__(16) float sx[128];
    __shared__ float sgi[192];
    ull w[64];
    const ull* p = (const ull*)(Wih + 192UL*128 + (size_t)tid*128);
    #pragma unroll
    for (int k = 0; k < 64; k++) w[k] = p[k];
    float bias = bih[192 + tid];

    for (int it = 0; it < 64; it++){
        int n = blockIdx.x*64 + it;
        if (tid < 128){
            size_t idx = ((size_t)n*256 + 255)*128 + tid;
            sx[tid] = __bfloat162float(g_h0H[idx]) + __bfloat162float(g_h0L[idx]);
        }
        __syncthreads();
        ull a0 = 0, a1 = 0;
        const ulonglong2* v4 = (const ulonglong2*)sx;
        #pragma unroll
        for (int k = 0; k < 32; k++){ ulonglong2 v = v4[k]; fma2(a0, w[2*k], v.x); fma2(a1, w[2*k+1], v.y); }
        sgi[tid] = hsum2(a0) + hsum2(a1) + bias;
        __syncthreads();
        if (tid < 64){
            float r  = sigf(sgi[tid]      + bhh[192 + tid]);
            float z  = sigf(sgi[64 + tid] + bhh[192 + 64 + tid]);
            float nn = tanf_(sgi[128+tid] + r * bhh[192 + 128 + tid]);
            g_last[n*128 + 64 + tid] = (1.f - z)*nn;
        }
    }
}

__global__ __launch_bounds__(128) void k_head(
    const float* __restrict__ pool_W, const float* __restrict__ pool_b,
    const float* __restrict__ mu_W, const float* __restrict__ mu_b,
    const float* __restrict__ logv_W, const float* __restrict__ logv_b,
    const float* __restrict__ dec_W, const float* __restrict__ dec_b,
    const float* __restrict__ lstm_Wih, const float* __restrict__ lstm_bih,
    const float* __restrict__ lstm_bhh,
    float* __restrict__ out)
{
    int b = blockIdx.x, tid = threadIdx.x;
    __shared__ float slast[128], shp[32], smu[32], sdh[64];
    float s = 0.f;
    for (int c = 0; c < 64; c++) s += g_last[(b*64 + c)*128 + tid];
    slast[tid] = s * (1.f/64.f);
    __syncthreads();
    if (tid < 32){
        float acc = pool_b[tid];
        for (int k = 0; k < 128; k++) acc += pool_W[tid*128 + k] * slast[k];
        shp[tid] = fmaxf(acc, 0.f);
    }
    __syncthreads();
    if (tid < 32){
        float acc = mu_b[tid];
        for (int k = 0; k < 32; k++) acc += mu_W[tid*32 + k] * shp[k];
        smu[tid] = acc;
        out[64UL*256*64 + b*32 + tid] = acc;
    } else if (tid < 64){
        int j = tid - 32;
        float acc = logv_b[j];
        for (int k = 0; k < 32; k++) acc += logv_W[j*32 + k] * shp[k];
        out[64UL*256*64 + 2048 + b*32 + j] = acc;
    }
    __syncthreads();
    if (tid < 64){
        float acc = dec_b[tid];
        for (int k = 0; k < 32; k++) acc += dec_W[tid*32 + k] * smu[k];
        sdh[tid] = fmaxf(acc, 0.f);
    }
    __syncthreads();
    for (int gate = tid; gate < 256; gate += 128){
        float acc = lstm_bih[gate] + lstm_bhh[gate];
        for (int k = 0; k < 64; k++) acc += lstm_Wih[gate*64 + k] * sdh[k];
        g_dxg[b*256 + gate] = acc;
    }
}

__global__ __launch_bounds__(256,1) void k_lstm1(const float* __restrict__ Whh)
{
    int b = blockIdx.x, tid = threadIdx.x;
    __shared__ __align__(16) float sh[64];
    __shared__ float sg[256];
    ull w[32];
    const ull* p = (const ull*)(Whh + (size_t)tid*64);
    #pragma unroll
    for (int k = 0; k < 32; k++) w[k] = p[k];
    float dxg = g_dxg[b*256 + tid];
    if (tid < 64) sh[tid] = 0.f;
    float c = 0.f;
    for (int t = 0; t < 256; t++){
        __syncthreads();
        ull a0 = 0, a1 = 0;
        const ulonglong2* v4 = (const ulonglong2*)sh;
        #pragma unroll
        for (int k = 0; k < 16; k++){ ulonglong2 v = v4[k]; fma2(a0, w[2*k], v.x); fma2(a1, w[2*k+1], v.y); }
        sg[tid] = hsum2(a0) + hsum2(a1) + dxg;
        __syncthreads();
        if (tid < 64){
            float i_ = sigf(sg[tid]), f_ = sigf(sg[64+tid]);
            float gg = tanf_(sg[128+tid]), o_ = sigf(sg[192+tid]);
            c = f_*c + i_*gg;
            float h = o_*tanf_(c);
            sh[tid] = h;
            g_h1d[((size_t)b*256 + t)*64 + tid] = h;
        }
    }
}

__global__ __launch_bounds__(256,1) void k_lstm2(
    const float* __restrict__ Wih, const float* __restrict__ Whh,
    const float* __restrict__ bih, const float* __restrict__ bhh,
    const float* __restrict__ out_W, const float* __restrict__ out_b,
    float* __restrict__ out)
{
    int b = blockIdx.x, tid = threadIdx.x;
    __shared__ __align__(16) float sx[64];
    __shared__ __align__(16) float sh[64];
    __shared__ float sg[256];
    __shared__ float soW[64*64];
    for (int i = tid; i < 4096; i += 256){ int c = i >> 6, k = i & 63; soW[k*64 + c] = out_W[i]; }
    ull wi[32], wh[32];
    const ull* p = (const ull*)(Wih + 256UL*64 + (size_t)tid*64);
    const ull* q = (const ull*)(Whh + 256UL*64 + (size_t)tid*64);
    #pragma unroll
    for (int k = 0; k < 32; k++){ wi[k] = p[k]; wh[k] = q[k]; }
    float bias = bih[256 + tid] + bhh[256 + tid];
    if (tid < 64) sh[tid] = 0.f;
    float c = 0.f;
    float ob = (tid >= 64 && tid < 128) ? out_b[tid - 64] : 0.f;
    const float* xb = g_h1d + (size_t)b*256*64;
    for (int t = 0; t < 256; t++){
        if (tid < 64) sx[tid] = xb[t*64 + tid];
        __syncthreads();
        ull a0 = 0, a1 = 0;
        const ulonglong2* x4 = (const ulonglong2*)sx;
        const ulonglong2* h4 = (const ulonglong2*)sh;
        #pragma unroll
        for (int k = 0; k < 16; k++){ ulonglong2 v = x4[k]; fma2(a0, wi[2*k], v.x); fma2(a1, wi[2*k+1], v.y); }
        #pragma unroll
        for (int k = 0; k < 16; k++){ ulonglong2 v = h4[k]; fma2(a0, wh[2*k], v.x); fma2(a1, wh[2*k+1], v.y); }
        sg[tid] = hsum2(a0) + hsum2(a1) + bias;
        __syncthreads();
        if (tid < 64){
            float i_ = sigf(sg[tid]), f_ = sigf(sg[64+tid]);
            float gg = tanf_(sg[128+tid]), o_ = sigf(sg[192+tid]);
            c = f_*c + i_*gg;
            sh[tid] = o_*tanf_(c);
        }
        __syncthreads();
        if (tid >= 64 && tid < 128){
            int cc = tid - 64;
            float acc = ob;
            #pragma unroll 8
            for (int k = 0; k < 64; k++) acc += soW[k*64 + cc] * sh[k];
            out[((size_t)b*256 + t)*64 + cc] = acc;
        }
    }
}

extern "C" void kernel_launch(void* const* d_in, const int* in_sizes, int n_in,
                              void* d_out, int out_size)
{
    const float* x      = (const float*)d_in[0];
    const float* adj1   = (const float*)d_in[1];
    const float* W1     = (const float*)d_in[2];
    const float* b1     = (const float*)d_in[3];
    const float* adj2   = (const float*)d_in[4];
    const float* W2     = (const float*)d_in[5];
    const float* b2     = (const float*)d_in[6];
    const float* ln_g   = (const float*)d_in[7];
    const float* ln_b   = (const float*)d_in[8];
    const float* g0Wih  = (const float*)d_in[9];
    const float* g0Whh  = (const float*)d_in[10];
    const float* g0bih  = (const float*)d_in[11];
    const float* g0bhh  = (const float*)d_in[12];
    const float* g1Wih  = (const float*)d_in[13];
    const float* g1Whh  = (const float*)d_in[14];
    const float* g1bih  = (const float*)d_in[15];
    const float* g1bhh  = (const float*)d_in[16];
    const float* pool_W = (const float*)d_in[17];
    const float* pool_b = (const float*)d_in[18];
    const float* mu_W   = (const float*)d_in[19];
    const float* mu_b   = (const float*)d_in[20];
    const float* logv_W = (const float*)d_in[21];
    const float* logv_b = (const float*)d_in[22];
    const float* dec_W  = (const float*)d_in[23];
    const float* dec_b  = (const float*)d_in[24];
    const float* lWih   = (const float*)d_in[25];
    const float* lWhh   = (const float*)d_in[26];
    const float* lbih   = (const float*)d_in[27];
    const float* lbhh   = (const float*)d_in[28];
    const float* out_W  = (const float*)d_in[29];
    const float* out_b  = (const float*)d_in[30];
    float* out = (float*)d_out;

    k_softmax<<<1, 64>>>(adj1, adj2);
    k_prepW<<<1, 256>>>(g1Wih, g0Wih, g0Whh, g1Whh);
    k_gnn<<<16384, 256>>>(x, W1, b1, W2, b2, ln_g, ln_b);
    k_gru0f<<<dim3(256, 2), 256>>>(g0bih, g0bhh);
    k_xproj1<<<1024, 256>>>();
    k_gru1m<<<256, 256>>>(g1bih, g1bhh);
    k_gru1b<<<64, 192>>>(g1Wih, g1Whh, g1bih, g1bhh);
    k_head<<<64, 128>>>(pool_W, pool_b, mu_W, mu_b, logv_W, logv_b,
                        dec_W, dec_b, lWih, lbih, lbhh, out);
    k_lstm1<<<64, 256>>>(lWhh);
    k_lstm2<<<64, 256>>>(lWih, lWhh, lbih, lbhh, out_W, out_b, out);
}

// round 16
// speedup vs baseline: 1.8686x; 1.0148x over previous
#include <cuda_runtime.h>
#include <cuda_bf16.h>
#include <cstdint>
#include <math.h>

typedef unsigned long long ull;

__device__ float g_A1[64*64];
__device__ float g_A2[64*64];
__device__ __nv_bfloat16 g_hencH[4096UL*256*32];
__device__ __nv_bfloat16 g_hencL[4096UL*256*32];
__device__ __nv_bfloat16 g_h0H[4096UL*256*128];
__device__ __nv_bfloat16 g_h0L[4096UL*256*128];
__device__ __nv_bfloat16 g_W1hi[192*128];
__device__ __nv_bfloat16 g_W1lo[192*128];
__device__ __nv_bfloat16 g_W0hi[384*32];
__device__ __nv_bfloat16 g_W0lo[384*32];
__device__ __nv_bfloat16 g_Wh0hi[384*64];
__device__ __nv_bfloat16 g_Wh0lo[384*64];
__device__ __nv_bfloat16 g_Wh1hi[192*64];
__device__ __nv_bfloat16 g_Wh1lo[192*64];
__device__ float g_xg1[4096UL*256*192];
__device__ float g_last[4096*128];
__device__ float g_dxg[64*256];
__device__ float g_h1d[64UL*256*64];

__device__ __forceinline__ void fma2(ull &acc, ull a, ull b){
    asm("fma.rn.f32x2 %0, %1, %2, %0;" : "+l"(acc) : "l"(a), "l"(b));
}
__device__ __forceinline__ float hsum2(ull a){
    float lo, hi; asm("mov.b64 {%0,%1}, %2;" : "=f"(lo), "=f"(hi) : "l"(a));
    return lo + hi;
}
__device__ __forceinline__ float sigf(float x){
    return __fdividef(1.f, 1.f + __expf(-x));
}
__device__ __forceinline__ float tanf_(float x){
    return __fmaf_rn(2.f, __fdividef(1.f, 1.f + __expf(-2.f*x)), -1.f);
}
__device__ __forceinline__ uint32_t s_u32(const void* p){
    return (uint32_t)__cvta_generic_to_shared(p);
}
__device__ __forceinline__ void ldm4(uint32_t &r0, uint32_t &r1, uint32_t &r2, uint32_t &r3, uint32_t a){
    asm volatile("ldmatrix.sync.aligned.m8n8.x4.shared.b16 {%0,%1,%2,%3}, [%4];"
        : "=r"(r0), "=r"(r1), "=r"(r2), "=r"(r3) : "r"(a));
}
#define MMA16816(acc, A0,A1,A2,A3, B0,B1) \
    asm volatile("mma.sync.aligned.m16n8k16.row.col.f32.bf16.bf16.f32 " \
        "{%0,%1,%2,%3}, {%4,%5,%6,%7}, {%8,%9}, {%0,%1,%2,%3};" \
        : "+f"(acc[0]), "+f"(acc[1]), "+f"(acc[2]), "+f"(acc[3]) \
        : "r"(A0), "r"(A1), "r"(A2), "r"(A3), "r"(B0), "r"(B1))

__global__ void k_softmax(const float* __restrict__ adj1, const float* __restrict__ adj2){
    int i = threadIdx.x;
    for (int w = 0; w < 2; w++){
        const float* a = w ? adj2 : adj1;
        float* o = w ? g_A2 : g_A1;
        float mx = -1e30f;
        for (int j = 0; j < 64; j++) mx = fmaxf(mx, a[i*64+j]);
        float s = 0.f;
        for (int j = 0; j < 64; j++) s += expf(a[i*64+j] - mx);
        float inv = 1.f / s;
        for (int j = 0; j < 64; j++) o[i*64+j] = expf(a[i*64+j] - mx) * inv;
    }
}

__global__ void k_prepW(const float* __restrict__ W1, const float* __restrict__ W0,
                        const float* __restrict__ Wh0, const float* __restrict__ Wh1){
    for (int i = threadIdx.x; i < 24576; i += 256){
        float v = W1[i];
        __nv_bfloat16 hi = __float2bfloat16(v);
        g_W1hi[i] = hi; g_W1lo[i] = __float2bfloat16(v - __bfloat162float(hi));
    }
    for (int i = threadIdx.x; i < 12288; i += 256){
        float v = W0[i];
        __nv_bfloat16 hi = __float2bfloat16(v);
        g_W0hi[i] = hi; g_W0lo[i] = __float2bfloat16(v - __bfloat162float(hi));
    }
    for (int i = threadIdx.x; i < 24576; i += 256){
        float v = Wh0[i];
        __nv_bfloat16 hi = __float2bfloat16(v);
        g_Wh0hi[i] = hi; g_Wh0lo[i] = __float2bfloat16(v - __bfloat162float(hi));
    }
    for (int i = threadIdx.x; i < 12288; i += 256){
        float v = Wh1[i];
        __nv_bfloat16 hi = __float2bfloat16(v);
        g_Wh1hi[i] = hi; g_Wh1lo[i] = __float2bfloat16(v - __bfloat162float(hi));
    }
}

__global__ __launch_bounds__(256) void k_gnn(
    const float* __restrict__ x,
    const float* __restrict__ W1, const float* __restrict__ b1,
    const float* __restrict__ W2, const float* __restrict__ b2,
    const float* __restrict__ lng, const float* __restrict__ lnb)
{
    int bt = blockIdx.x;
    int b = bt >> 8, t = bt & 255;
    int tid = threadIdx.x;

    __shared__ float sA2[64*65];
    __shared__ float sW2t[1024];
    __shared__ __align__(16) float sx[64];
    __shared__ float s1[64];
    __shared__ __align__(16) float sh1[2048];
    __shared__ __align__(16) float sagg[2048];
    __shared__ float sh2[64*33];
    __shared__ float sW1[32], sb1[32], sb2[32], slg[32], slb[32];
    __shared__ float smean[64], srstd[64];

    for (int i = tid; i < 4096; i += 256) sA2[(i>>6)*65 + (i&63)] = g_A2[i];
    for (int i = tid; i < 1024; i += 256){ int gp = i>>5, k = i&31; sW2t[k*32+gp] = W2[i]; }
    if (tid < 64) sx[tid] = x[(size_t)bt*64 + tid];
    if (tid < 32){ sW1[tid]=W1[tid]; sb1[tid]=b1[tid]; sb2[tid]=b2[tid]; slg[tid]=lng[tid]; slb[tid]=lnb[tid]; }
    __syncthreads();

    if (tid < 64){
        float s = 0.f; const float* a = g_A1 + tid*64;
        #pragma unroll 8
        for (int j = 0; j < 64; j++) s += a[j]*sx[j];
        s1[tid] = s;
    }
    __syncthreads();
    for (int i = tid; i < 2048; i += 256){ int j = i>>5, g = i&31; sh1[i] = fmaxf(sW1[g]*s1[j] + sb1[g], 0.f); }
    __syncthreads();
    {
        int i = tid >> 2, g0 = (tid & 3) * 8;
        float4 a0 = {0,0,0,0}, a1 = {0,0,0,0};
        #pragma unroll 4
        for (int j = 0; j < 64; j++){
            float a = sA2[i*65 + j];
            float4 h0 = *(const float4*)(sh1 + j*32 + g0);
            float4 h1 = *(const float4*)(sh1 + j*32 + g0 + 4);
            a0.x += a*h0.x; a0.y += a*h0.y; a0.z += a*h0.z; a0.w += a*h0.w;
            a1.x += a*h1.x; a1.y += a*h1.y; a1.z += a*h1.z; a1.w += a*h1.w;
        }
        *(float4*)(sagg + i*32 + g0)     = a0;
        *(float4*)(sagg + i*32 + g0 + 4) = a1;
    }
    __syncthreads();
    #pragma unroll
    for (int q = 0; q < 8; q++){
        int idx = tid + (q << 8);
        int i = idx >> 5, gp = idx & 31;
        float acc = sb2[gp];
        #pragma unroll 8
        for (int k = 0; k < 32; k++) acc += sagg[i*32 + k] * sW2t[k*32 + gp];
        sh2[i*33 + gp] = fmaxf(acc, 0.f);
    }
    __syncthreads();
    if (tid < 64){
        float m = 0.f;
        for (int g = 0; g < 32; g++) m += sh2[tid*33 + g];
        m *= (1.f/32.f);
        float v = 0.f;
        for (int g = 0; g < 32; g++){ float d = sh2[tid*33 + g] - m; v += d*d; }
        v *= (1.f/32.f);
        smean[tid] = m; srstd[tid] = rsqrtf(v + 1e-5f);
    }
    __syncthreads();
    for (int idx = tid; idx < 2048; idx += 256){
        int i = idx >> 5, g = idx & 31;
        float val = (sh2[i*33 + g] - smean[i]) * srstd[i] * slg[g] + slb[g];
        size_t o = (((size_t)b*64 + i)*256 + t)*32 + g;
        __nv_bfloat16 hi = __float2bfloat16(val);
        g_hencH[o] = hi;
        g_hencL[o] = __float2bfloat16(val - __bfloat162float(hi));
    }
}

// ---- GRU layer 0: fused input-proj + hidden recurrence, ldmatrix A-frags ----
__global__ __launch_bounds__(256,2) void k_gru0f(
    const float* __restrict__ bih, const float* __restrict__ bhh)
{
    int n0 = blockIdx.x * 16, dir = blockIdx.y;
    int tid = threadIdx.x, w = tid >> 5, lane = tid & 31;
    int g = lane >> 2, tig = lane & 3;
    __shared__ uint32_t sHx[2][16*36];
    __shared__ uint32_t sXh[2][16*20];
    __shared__ float sH[16*64];
    __shared__ float sG[16*266];
    __shared__ float sBi[192], sBh[192];

    uint32_t bhi[3][4][2], blo_[3][4][2];
    uint32_t xbh[3][2][2];
    #pragma unroll
    for (int nt = 0; nt < 3; nt++){
        int n = dir*192 + w*24 + nt*8 + g;
        const uint32_t* wp = (const uint32_t*)g_Wh0hi + n*32;
        const uint32_t* wq = (const uint32_t*)g_Wh0lo + n*32;
        #pragma unroll
        for (int kt = 0; kt < 4; kt++){
            bhi[nt][kt][0] = wp[kt*8 + tig];  bhi[nt][kt][1] = wp[kt*8 + 4 + tig];
            blo_[nt][kt][0] = wq[kt*8 + tig]; blo_[nt][kt][1] = wq[kt*8 + 4 + tig];
        }
        const uint32_t* xp = (const uint32_t*)g_W0hi + n*16;
        #pragma unroll
        for (int ks = 0; ks < 2; ks++){
            xbh[nt][ks][0] = xp[ks*8 + tig]; xbh[nt][ks][1] = xp[ks*8 + 4 + tig];
        }
    }
    const uint32_t* xblo = (const uint32_t*)g_W0lo;
    if (tid < 192){ sBi[tid] = bih[dir*192 + tid]; sBh[tid] = bhh[dir*192 + tid]; }
    for (int i = tid; i < 16*36; i += 256){ sHx[0][i] = 0u; sHx[1][i] = 0u; }
    for (int i = tid; i < 1024; i += 256) sH[i] = 0.f;

    // ldmatrix lane address bases
    uint32_t lrow = lane & 15;
    uint32_t khalf = (lane >> 4) * 16;
    uint32_t aH0 = s_u32(&sHx[0][0]) + lrow*144 + khalf;
    uint32_t aH1 = s_u32(&sHx[1][0]) + lrow*144 + khalf;
    uint32_t aX0 = s_u32(&sXh[0][0]) + lrow*80 + khalf;
    uint32_t aX1 = s_u32(&sXh[1][0]) + lrow*80 + khalf;

    int prow = tid >> 4, pc = tid & 15;
    const uint32_t* heH = (const uint32_t*)g_hencH;
    const uint32_t* heL = (const uint32_t*)g_hencL;
    size_t hrow = (size_t)(n0 + prow)*256;
    int t0 = dir ? 255 : 0;
    uint32_t rxh = heH[(hrow + t0)*16 + pc];
    uint32_t rxl = heL[(hrow + t0)*16 + pc];
    __syncthreads();
    sXh[0][prow*20 + pc] = rxh;
    sXh[1][prow*20 + pc] = rxl;
    __syncthreads();
    {
        int t1 = dir ? 254 : 1;
        rxh = heH[(hrow + t1)*16 + pc];
        rxl = heL[(hrow + t1)*16 + pc];
    }

    int q = tid >> 4, pp = tid & 15;
    uint32_t* h0Hu = (uint32_t*)g_h0H;
    uint32_t* h0Lu = (uint32_t*)g_h0L;

    for (int s = 0; s < 256; s++){
        int t = dir ? 255 - s : s;
        float accA[3][4], accB[3][4];
        #pragma unroll
        for (int nt=0;nt<3;nt++){
            accA[nt][0]=0.f; accA[nt][1]=0.f; accA[nt][2]=0.f; accA[nt][3]=0.f;
            accB[nt][0]=0.f; accB[nt][1]=0.f; accB[nt][2]=0.f; accB[nt][3]=0.f;
        }
        #pragma unroll
        for (int kt = 0; kt < 4; kt++){
            uint32_t ah0,ah1,ah2,ah3, al0,al1,al2,al3;
            ldm4(ah0,ah1,ah2,ah3, aH0 + kt*32);
            ldm4(al0,al1,al2,al3, aH1 + kt*32);
            #pragma unroll
            for (int nt = 0; nt < 3; nt++){
                MMA16816(accA[nt], ah0,ah1,ah2,ah3, bhi[nt][kt][0], bhi[nt][kt][1]);
                MMA16816(accA[nt], al0,al1,al2,al3, bhi[nt][kt][0], bhi[nt][kt][1]);
                MMA16816(accA[nt], ah0,ah1,ah2,ah3, blo_[nt][kt][0], blo_[nt][kt][1]);
            }
        }
        #pragma unroll
        for (int ks = 0; ks < 2; ks++){
            uint32_t xh0,xh1,xh2,xh3, xl0,xl1,xl2,xl3;
            ldm4(xh0,xh1,xh2,xh3, aX0 + ks*32);
            ldm4(xl0,xl1,xl2,xl3, aX1 + ks*32);
            #pragma unroll
            for (int nt = 0; nt < 3; nt++){
                int n = dir*192 + w*24 + nt*8 + g;
                uint32_t bl0 = __ldg(xblo + n*16 + ks*8 + tig);
                uint32_t bl1 = __ldg(xblo + n*16 + ks*8 + 4 + tig);
                MMA16816(accB[nt], xh0,xh1,xh2,xh3, xbh[nt][ks][0], xbh[nt][ks][1]);
                MMA16816(accB[nt], xl0,xl1,xl2,xl3, xbh[nt][ks][0], xbh[nt][ks][1]);
                MMA16816(accB[nt], xh0,xh1,xh2,xh3, bl0, bl1);
            }
        }
        #pragma unroll
        for (int nt = 0; nt < 3; nt++){
            int col = w*24 + nt*8 + tig*2;
            if (col < 128){
                *(float2*)(sG + g*266 + col)     = make_float2(accA[nt][0]+accB[nt][0], accA[nt][1]+accB[nt][1]);
                *(float2*)(sG + (g+8)*266 + col) = make_float2(accA[nt][2]+accB[nt][2], accA[nt][3]+accB[nt][3]);
            } else {
                *(float2*)(sG + g*266 + col)          = make_float2(accA[nt][0], accA[nt][1]);
                *(float2*)(sG + (g+8)*266 + col)      = make_float2(accA[nt][2], accA[nt][3]);
                *(float2*)(sG + g*266 + col + 64)     = make_float2(accB[nt][0], accB[nt][1]);
                *(float2*)(sG + (g+8)*266 + col + 64) = make_float2(accB[nt][2], accB[nt][3]);
            }
        }
        __syncthreads();
        #pragma unroll
        for (int half = 0; half < 2; half++){
            int hb = 2*pp + half*32;
            float hn[2];
            #pragma unroll
            for (int e = 0; e < 2; e++){
                int hh = hb + e;
                float Gr  = sG[q*266 + hh];
                float Gz  = sG[q*266 + 64 + hh];
                float Gnh = sG[q*266 + 128 + hh];
                float Gnx = sG[q*266 + 192 + hh];
                float r  = sigf(Gr + sBi[hh] + sBh[hh]);
                float z  = sigf(Gz + sBi[64+hh] + sBh[64+hh]);
                float nn = tanf_(Gnx + sBi[128+hh] + r*(Gnh + sBh[128+hh]));
                hn[e] = (1.f - z)*nn + z*sH[q*64 + hh];
                sH[q*64 + hh] = hn[e];
            }
            __nv_bfloat16 h0h = __float2bfloat16(hn[0]);
            __nv_bfloat16 h1h = __float2bfloat16(hn[1]);
            __nv_bfloat16 h0l = __float2bfloat16(hn[0] - __bfloat162float(h0h));
            __nv_bfloat16 h1l = __float2bfloat16(hn[1] - __bfloat162float(h1h));
            uint32_t hip, lop;
            asm("mov.b32 %0, {%1,%2};" : "=r"(hip) : "h"(*(unsigned short*)&h0h), "h"(*(unsigned short*)&h1h));
            asm("mov.b32 %0, {%1,%2};" : "=r"(lop) : "h"(*(unsigned short*)&h0l), "h"(*(unsigned short*)&h1l));
            int pcol = pp + half*16;
            sHx[0][q*36 + pcol] = hip;
            sHx[1][q*36 + pcol] = lop;
            size_t oidx = ((size_t)(n0+q)*256 + t)*64 + dir*32 + pcol;
            h0Hu[oidx] = hip; h0Lu[oidx] = lop;
        }
        if (s < 255){
            sXh[0][prow*20 + pc] = rxh;
            sXh[1][prow*20 + pc] = rxl;
            if (s < 254){
                int tn2 = dir ? 253 - s : s + 2;
                rxh = heH[(hrow + tn2)*16 + pc];
                rxl = heL[(hrow + tn2)*16 + pc];
            }
        }
        __syncthreads();
    }
}

// ---- mma GEMM: xg1 = h0 @ Wih1^T, double-buffered, ldmatrix A-frags ----
__global__ __launch_bounds__(256,2) void k_xproj1(){
    __shared__ uint32_t sA[2][16*68];
    int tid = threadIdx.x;
    int w = tid >> 5, lane = tid & 31;
    int g = lane >> 2, tig = lane & 3;
    size_t Rbase = (size_t)blockIdx.x * 1024;

    uint32_t bh[3][8][2];
    #pragma unroll
    for (int nt = 0; nt < 3; nt++){
        int n = w*24 + nt*8 + g;
        const uint32_t* wp = (const uint32_t*)g_W1hi + n*64;
        #pragma unroll
        for (int ks = 0; ks < 8; ks++){
            bh[nt][ks][0] = wp[ks*8 + tig];
            bh[nt][ks][1] = wp[ks*8 + 4 + tig];
        }
    }
    const uint32_t* blo = (const uint32_t*)g_W1lo;
    const uint4* h0Hu = (const uint4*)g_h0H;
    const uint4* h0Lu = (const uint4*)g_h0L;

    uint32_t lrow = lane & 15;
    uint32_t khalf = (lane >> 4) * 16;
    uint32_t aB0 = s_u32(&sA[0][0]) + lrow*272 + khalf;
    uint32_t aB1 = s_u32(&sA[1][0]) + lrow*272 + khalf;

    int prow = tid >> 4, pc4 = tid & 15;
    uint4 rh = h0Hu[(Rbase + prow)*16 + pc4];
    uint4 rl = h0Lu[(Rbase + prow)*16 + pc4];

    for (int mt = 0; mt < 64; mt++){
        size_t R = Rbase + mt*16;
        __syncthreads();
        {
            int c0 = pc4*4;
            sA[0][prow*68 + c0]   = rh.x; sA[0][prow*68 + c0+1] = rh.y;
            sA[0][prow*68 + c0+2] = rh.z; sA[0][prow*68 + c0+3] = rh.w;
            sA[1][prow*68 + c0]   = rl.x; sA[1][prow*68 + c0+1] = rl.y;
            sA[1][prow*68 + c0+2] = rl.z; sA[1][prow*68 + c0+3] = rl.w;
        }
        __syncthreads();
        if (mt < 63){
            rh = h0Hu[(R + 16 + prow)*16 + pc4];
            rl = h0Lu[(R + 16 + prow)*16 + pc4];
        }
        float acc[3][4];
        #pragma unroll
        for (int nt=0;nt<3;nt++){ acc[nt][0]=0.f; acc[nt][1]=0.f; acc[nt][2]=0.f; acc[nt][3]=0.f; }
        #pragma unroll
        for (int term = 0; term < 3; term++){
            uint32_t abase = (term == 1) ? aB1 : aB0;
            #pragma unroll
            for (int ks = 0; ks < 8; ks++){
                uint32_t a0,a1,a2,a3;
                ldm4(a0,a1,a2,a3, abase + ks*32);
                #pragma unroll
                for (int nt = 0; nt < 3; nt++){
                    uint32_t b0, b1;
                    if (term < 2){ b0 = bh[nt][ks][0]; b1 = bh[nt][ks][1]; }
                    else {
                        int n = w*24 + nt*8 + g;
                        b0 = __ldg(blo + n*64 + ks*8 + tig);
                        b1 = __ldg(blo + n*64 + ks*8 + 4 + tig);
                    }
                    MMA16816(acc[nt], a0,a1,a2,a3, b0,b1);
                }
            }
        }
        #pragma unroll
        for (int nt = 0; nt < 3; nt++){
            int col = w*24 + nt*8 + tig*2;
            *(float2*)(g_xg1 + (R+g)*192 + col)   = make_float2(acc[nt][0], acc[nt][1]);
            *(float2*)(g_xg1 + (R+g+8)*192 + col) = make_float2(acc[nt][2], acc[nt][3]);
        }
    }
}

// ---- GRU layer 1 fwd hidden recurrence, ldmatrix A-frags ----
__global__ __launch_bounds__(256,2) void k_gru1m(
    const float* __restrict__ bih, const float* __restrict__ bhh)
{
    int n0 = blockIdx.x * 16;
    int tid = threadIdx.x, w = tid >> 5, lane = tid & 31;
    int g = lane >> 2, tig = lane & 3;
    __shared__ uint32_t sHx[2][16*36];
    __shared__ float sH[16*64];
    __shared__ float sG[16*200];
    __shared__ float sBi[192], sBh[192];

    uint32_t bhi[3][4][2], blo_[3][4][2];
    #pragma unroll
    for (int nt = 0; nt < 3; nt++){
        int n = w*24 + nt*8 + g;
        const uint32_t* wp = (const uint32_t*)g_Wh1hi + n*32;
        const uint32_t* wq = (const uint32_t*)g_Wh1lo + n*32;
        #pragma unroll
        for (int kt = 0; kt < 4; kt++){
            bhi[nt][kt][0] = wp[kt*8 + tig];  bhi[nt][kt][1] = wp[kt*8 + 4 + tig];
            blo_[nt][kt][0] = wq[kt*8 + tig]; blo_[nt][kt][1] = wq[kt*8 + 4 + tig];
        }
    }
    if (tid < 192){ sBi[tid] = bih[tid]; sBh[tid] = bhh[tid]; }
    for (int i = tid; i < 16*36; i += 256){ sHx[0][i] = 0u; sHx[1][i] = 0u; }
    for (int i = tid; i < 1024; i += 256) sH[i] = 0.f;
    __syncthreads();

    uint32_t lrow = lane & 15;
    uint32_t khalf = (lane >> 4) * 16;
    uint32_t aH0 = s_u32(&sHx[0][0]) + lrow*144 + khalf;
    uint32_t aH1 = s_u32(&sHx[1][0]) + lrow*144 + khalf;

    int q = tid >> 4, pp = tid & 15;
    const float* xgb = g_xg1 + (size_t)(n0 + q)*256*192;
    float2 xr0, xr1, xr2, xr3, xr4, xr5;
    {
        const float* xp = xgb;
        xr0 = *(const float2*)(xp + 2*pp);        xr1 = *(const float2*)(xp + 64 + 2*pp);
        xr2 = *(const float2*)(xp + 128 + 2*pp);  xr3 = *(const float2*)(xp + 32 + 2*pp);
        xr4 = *(const float2*)(xp + 96 + 2*pp);   xr5 = *(const float2*)(xp + 160 + 2*pp);
    }

    for (int s = 0; s < 256; s++){
        float acc[3][4];
        #pragma unroll
        for (int nt=0;nt<3;nt++){ acc[nt][0]=0.f; acc[nt][1]=0.f; acc[nt][2]=0.f; acc[nt][3]=0.f; }
        #pragma unroll
        for (int kt = 0; kt < 4; kt++){
            uint32_t ah0,ah1,ah2,ah3, al0,al1,al2,al3;
            ldm4(ah0,ah1,ah2,ah3, aH0 + kt*32);
            ldm4(al0,al1,al2,al3, aH1 + kt*32);
            #pragma unroll
            for (int nt = 0; nt < 3; nt++){
                MMA16816(acc[nt], ah0,ah1,ah2,ah3, bhi[nt][kt][0], bhi[nt][kt][1]);
                MMA16816(acc[nt], al0,al1,al2,al3, bhi[nt][kt][0], bhi[nt][kt][1]);
                MMA16816(acc[nt], ah0,ah1,ah2,ah3, blo_[nt][kt][0], blo_[nt][kt][1]);
            }
        }
        #pragma unroll
        for (int nt = 0; nt < 3; nt++){
            int col = w*24 + nt*8 + tig*2;
            *(float2*)(sG + g*200 + col)     = make_float2(acc[nt][0], acc[nt][1]);
            *(float2*)(sG + (g+8)*200 + col) = make_float2(acc[nt][2], acc[nt][3]);
        }
        __syncthreads();
        #pragma unroll
        for (int half = 0; half < 2; half++){
            int hb = 2*pp + half*32;
            float2 xrr = half ? xr3 : xr0;
            float2 xrz = half ? xr4 : xr1;
            float2 xrn = half ? xr5 : xr2;
            float hn[2];
            #pragma unroll
            for (int e = 0; e < 2; e++){
                int hh = hb + e;
                float Gr = sG[q*200 + hh], Gz = sG[q*200 + 64 + hh], Gn = sG[q*200 + 128 + hh];
                float xv_r = e ? xrr.y : xrr.x;
                float xv_z = e ? xrz.y : xrz.x;
                float xv_n = e ? xrn.y : xrn.x;
                float r  = sigf(xv_r + sBi[hh] + Gr + sBh[hh]);
                float z  = sigf(xv_z + sBi[64+hh] + Gz + sBh[64+hh]);
                float nn = tanf_(xv_n + sBi[128+hh] + r*(Gn + sBh[128+hh]));
                hn[e] = (1.f - z)*nn + z*sH[q*64 + hh];
                sH[q*64 + hh] = hn[e];
                if (s == 255) g_last[(n0+q)*128 + hh] = hn[e];
            }
            __nv_bfloat16 h0h = __float2bfloat16(hn[0]);
            __nv_bfloat16 h1h = __float2bfloat16(hn[1]);
            __nv_bfloat16 h0l = __float2bfloat16(hn[0] - __bfloat162float(h0h));
            __nv_bfloat16 h1l = __float2bfloat16(hn[1] - __bfloat162float(h1h));
            uint32_t hip, lop;
            asm("mov.b32 %0, {%1,%2};" : "=r"(hip) : "h"(*(unsigned short*)&h0h), "h"(*(unsigned short*)&h1h));
            asm("mov.b32 %0, {%1,%2};" : "=r"(lop) : "h"(*(unsigned short*)&h0l), "h"(*(unsigned short*)&h1l));
            int pcol = pp + half*16;
            sHx[0][q*36 + pcol] = hip;
            sHx[1][q*36 + pcol] = lop;
        }
        if (s < 255){
            const float* xp = xgb + (size_t)(s+1)*192;
            xr0 = *(const float2*)(xp + 2*pp);        xr1 = *(const float2*)(xp + 64 + 2*pp);
            xr2 = *(const float2*)(xp + 128 + 2*pp);  xr3 = *(const float2*)(xp + 32 + 2*pp);
            xr4 = *(const float2*)(xp + 96 + 2*pp);   xr5 = *(const float2*)(xp + 160 + 2*pp);
        }
        __syncthreads();
    }
}

__global__ __launch_bounds__(192,2) void k_gru1b(
    const float* __restrict__ Wih, const float* __restrict__ Whh,
    const float* __restrict__ bih, const float* __restrict__ bhh)
{
    int tid = threadIdx.x;
    __shared__ __align__(16) float sx[128];
    __shared__ float sgi[192];
    ull w[64];
    const ull* p = (const ull*)(Wih + 192UL*128 + (size_t)tid*128);
    #pragma unroll
    for (int k = 0; k < 64; k++) w[k] = p[k];
    float bias = bih[192 + tid];

    for (int it = 0; it < 64; it++){
        int n = blockIdx.x*64 + it;
        if (tid < 128){
            size_t idx = ((size_t)n*256 + 255)*128 + tid;
            sx[tid] = __bfloat162float(g_h0H[idx]) + __bfloat162float(g_h0L[idx]);
        }
        __syncthreads();
        ull a0 = 0, a1 = 0;
        const ulonglong2* v4 = (const ulonglong2*)sx;
        #pragma unroll
        for (int k = 0; k < 32; k++){ ulonglong2 v = v4[k]; fma2(a0, w[2*k], v.x); fma2(a1, w[2*k+1], v.y); }
        sgi[tid] = hsum2(a0) + hsum2(a1) + bias;
        __syncthreads();
        if (tid < 64){
            float r  = sigf(sgi[tid]      + bhh[192 + tid]);
            float z  = sigf(sgi[64 + tid] + bhh[192 + 64 + tid]);
            float nn = tanf_(sgi[128+tid] + r * bhh[192 + 128 + tid]);
            g_last[n*128 + 64 + tid] = (1.f - z)*nn;
        }
    }
}

__global__ __launch_bounds__(128) void k_head(
    const float* __restrict__ pool_W, const float* __restrict__ pool_b,
    const float* __restrict__ mu_W, const float* __restrict__ mu_b,
    const float* __restrict__ logv_W, const float* __restrict__ logv_b,
    const float* __restrict__ dec_W, const float* __restrict__ dec_b,
    const float* __restrict__ lstm_Wih, const float* __restrict__ lstm_bih,
    const float* __restrict__ lstm_bhh,
    float* __restrict__ out)
{
    int b = blockIdx.x, tid = threadIdx.x;
    __shared__ float slast[128], shp[32], smu[32], sdh[64];
    float s = 0.f;
    for (int c = 0; c < 64; c++) s += g_last[(b*64 + c)*128 + tid];
    slast[tid] = s * (1.f/64.f);
    __syncthreads();
    if (tid < 32){
        float acc = pool_b[tid];
        for (int k = 0; k < 128; k++) acc += pool_W[tid*128 + k] * slast[k];
        shp[tid] = fmaxf(acc, 0.f);
    }
    __syncthreads();
    if (tid < 32){
        float acc = mu_b[tid];
        for (int k = 0; k < 32; k++) acc += mu_W[tid*32 + k] * shp[k];
        smu[tid] = acc;
        out[64UL*256*64 + b*32 + tid] = acc;
    } else if (tid < 64){
        int j = tid - 32;
        float acc = logv_b[j];
        for (int k = 0; k < 32; k++) acc += logv_W[j*32 + k] * shp[k];
        out[64UL*256*64 + 2048 + b*32 + j] = acc;
    }
    __syncthreads();
    if (tid < 64){
        float acc = dec_b[tid];
        for (int k = 0; k < 32; k++) acc += dec_W[tid*32 + k] * smu[k];
        sdh[tid] = fmaxf(acc, 0.f);
    }
    __syncthreads();
    for (int gate = tid; gate < 256; gate += 128){
        float acc = lstm_bih[gate] + lstm_bhh[gate];
        for (int k = 0; k < 64; k++) acc += lstm_Wih[gate*64 + k] * sdh[k];
        g_dxg[b*256 + gate] = acc;
    }
}

__global__ __launch_bounds__(256,1) void k_lstm1(const float* __restrict__ Whh)
{
    int b = blockIdx.x, tid = threadIdx.x;
    __shared__ __align__(16) float sh[64];
    __shared__ float sg[256];
    ull w[32];
    const ull* p = (const ull*)(Whh + (size_t)tid*64);
    #pragma unroll
    for (int k = 0; k < 32; k++) w[k] = p[k];
    float dxg = g_dxg[b*256 + tid];
    if (tid < 64) sh[tid] = 0.f;
    float c = 0.f;
    for (int t = 0; t < 256; t++){
        __syncthreads();
        ull a0 = 0, a1 = 0;
        const ulonglong2* v4 = (const ulonglong2*)sh;
        #pragma unroll
        for (int k = 0; k < 16; k++){ ulonglong2 v = v4[k]; fma2(a0, w[2*k], v.x); fma2(a1, w[2*k+1], v.y); }
        sg[tid] = hsum2(a0) + hsum2(a1) + dxg;
        __syncthreads();
        if (tid < 64){
            float i_ = sigf(sg[tid]), f_ = sigf(sg[64+tid]);
            float gg = tanf_(sg[128+tid]), o_ = sigf(sg[192+tid]);
            c = f_*c + i_*gg;
            float h = o_*tanf_(c);
            sh[tid] = h;
            g_h1d[((size_t)b*256 + t)*64 + tid] = h;
        }
    }
}

__global__ __launch_bounds__(256,1) void k_lstm2(
    const float* __restrict__ Wih, const float* __restrict__ Whh,
    const float* __restrict__ bih, const float* __restrict__ bhh,
    const float* __restrict__ out_W, const float* __restrict__ out_b,
    float* __restrict__ out)
{
    int b = blockIdx.x, tid = threadIdx.x;
    __shared__ __align__(16) float sx[64];
    __shared__ __align__(16) float sh[64];
    __shared__ float sg[256];
    __shared__ float soW[64*64];
    for (int i = tid; i < 4096; i += 256){ int c = i >> 6, k = i & 63; soW[k*64 + c] = out_W[i]; }
    ull wi[32], wh[32];
    const ull* p = (const ull*)(Wih + 256UL*64 + (size_t)tid*64);
    const ull* q = (const ull*)(Whh + 256UL*64 + (size_t)tid*64);
    #pragma unroll
    for (int k = 0; k < 32; k++){ wi[k] = p[k]; wh[k] = q[k]; }
    float bias = bih[256 + tid] + bhh[256 + tid];
    if (tid < 64) sh[tid] = 0.f;
    float c = 0.f;
    float ob = (tid >= 64 && tid < 128) ? out_b[tid - 64] : 0.f;
    const float* xb = g_h1d + (size_t)b*256*64;
    for (int t = 0; t < 256; t++){
        if (tid < 64) sx[tid] = xb[t*64 + tid];
        __syncthreads();
        ull a0 = 0, a1 = 0;
        const ulonglong2* x4 = (const ulonglong2*)sx;
        const ulonglong2* h4 = (const ulonglong2*)sh;
        #pragma unroll
        for (int k = 0; k < 16; k++){ ulonglong2 v = x4[k]; fma2(a0, wi[2*k], v.x); fma2(a1, wi[2*k+1], v.y); }
        #pragma unroll
        for (int k = 0; k < 16; k++){ ulonglong2 v = h4[k]; fma2(a0, wh[2*k], v.x); fma2(a1, wh[2*k+1], v.y); }
        sg[tid] = hsum2(a0) + hsum2(a1) + bias;
        __syncthreads();
        if (tid < 64){
            float i_ = sigf(sg[tid]), f_ = sigf(sg[64+tid]);
            float gg = tanf_(sg[128+tid]), o_ = sigf(sg[192+tid]);
            c = f_*c + i_*gg;
            sh[tid] = o_*tanf_(c);
        }
        __syncthreads();
        if (tid >= 64 && tid < 128){
            int cc = tid - 64;
            float acc = ob;
            #pragma unroll 8
            for (int k = 0; k < 64; k++) acc += soW[k*64 + cc] * sh[k];
            out[((size_t)b*256 + t)*64 + cc] = acc;
        }
    }
}

extern "C" void kernel_launch(void* const* d_in, const int* in_sizes, int n_in,
                              void* d_out, int out_size)
{
    const float* x      = (const float*)d_in[0];
    const float* adj1   = (const float*)d_in[1];
    const float* W1     = (const float*)d_in[2];
    const float* b1     = (const float*)d_in[3];
    const float* adj2   = (const float*)d_in[4];
    const float* W2     = (const float*)d_in[5];
    const float* b2     = (const float*)d_in[6];
    const float* ln_g   = (const float*)d_in[7];
    const float* ln_b   = (const float*)d_in[8];
    const float* g0Wih  = (const float*)d_in[9];
    const float* g0Whh  = (const float*)d_in[10];
    const float* g0bih  = (const float*)d_in[11];
    const float* g0bhh  = (const float*)d_in[12];
    const float* g1Wih  = (const float*)d_in[13];
    const float* g1Whh  = (const float*)d_in[14];
    const float* g1bih  = (const float*)d_in[15];
    const float* g1bhh  = (const float*)d_in[16];
    const float* pool_W = (const float*)d_in[17];
    const float* pool_b = (const float*)d_in[18];
    const float* mu_W   = (const float*)d_in[19];
    const float* mu_b   = (const float*)d_in[20];
    const float* logv_W = (const float*)d_in[21];
    const float* logv_b = (const float*)d_in[22];
    const float* dec_W  = (const float*)d_in[23];
    const float* dec_b  = (const float*)d_in[24];
    const float* lWih   = (const float*)d_in[25];
    const float* lWhh   = (const float*)d_in[26];
    const float* lbih   = (const float*)d_in[27];
    const float* lbhh   = (const float*)d_in[28];
    const float* out_W  = (const float*)d_in[29];
    const float* out_b  = (const float*)d_in[30];
    float* out = (float*)d_out;

    k_softmax<<<1, 64>>>(adj1, adj2);
    k_prepW<<<1, 256>>>(g1Wih, g0Wih, g0Whh, g1Whh);
    k_gnn<<<16384, 256>>>(x, W1, b1, W2, b2, ln_g, ln_b);
    k_gru0f<<<dim3(256, 2), 256>>>(g0bih, g0bhh);
    k_xproj1<<<1024, 256>>>();
    k_gru1m<<<256, 256>>>(g1bih, g1bhh);
    k_gru1b<<<64, 192>>>(g1Wih, g1Whh, g1bih, g1bhh);
    k_head<<<64, 128>>>(pool_W, pool_b, mu_W, mu_b, logv_W, logv_b,
                        dec_W, dec_b, lWih, lbih, lbhh, out);
    k_lstm1<<<64, 256>>>(lWhh);
    k_lstm2<<<64, 256>>>(lWih, lWhh, lbih, lbhh, out_W, out_b, out);
}

// round 17
// speedup vs baseline: 2.1895x; 1.1717x over previous
#include <cuda_runtime.h>
#include <cuda_bf16.h>
#include <cstdint>
#include <math.h>

typedef unsigned long long ull;

__device__ float g_A1[64*64];
__device__ float g_A2[64*64];
__device__ __nv_bfloat16 g_hencH[4096UL*256*32];
__device__ __nv_bfloat16 g_hencL[4096UL*256*32];
__device__ __nv_bfloat16 g_h0H[4096UL*256*128];
__device__ __nv_bfloat16 g_h0L[4096UL*256*128];
__device__ __nv_bfloat16 g_W1hi[192*128];
__device__ __nv_bfloat16 g_W1lo[192*128];
__device__ __nv_bfloat16 g_W0hi[384*32];
__device__ __nv_bfloat16 g_W0lo[384*32];
__device__ __nv_bfloat16 g_Wh0hi[384*64];
__device__ __nv_bfloat16 g_Wh0lo[384*64];
__device__ __nv_bfloat16 g_Wh1hi[192*64];
__device__ __nv_bfloat16 g_Wh1lo[192*64];
__device__ float g_xg1[4096UL*256*192];
__device__ float g_last[4096*128];
__device__ float g_dxg[64*256];
__device__ float g_h1d[64UL*256*64];

__device__ __forceinline__ void fma2(ull &acc, ull a, ull b){
    asm("fma.rn.f32x2 %0, %1, %2, %0;" : "+l"(acc) : "l"(a), "l"(b));
}
__device__ __forceinline__ float hsum2(ull a){
    float lo, hi; asm("mov.b64 {%0,%1}, %2;" : "=f"(lo), "=f"(hi) : "l"(a));
    return lo + hi;
}
__device__ __forceinline__ float sigf(float x){
    return __fdividef(1.f, 1.f + __expf(-x));
}
__device__ __forceinline__ float tanf_(float x){
    return __fmaf_rn(2.f, __fdividef(1.f, 1.f + __expf(-2.f*x)), -1.f);
}
__device__ __forceinline__ uint32_t s_u32(const void* p){
    return (uint32_t)__cvta_generic_to_shared(p);
}
__device__ __forceinline__ void ldm4(uint32_t &r0, uint32_t &r1, uint32_t &r2, uint32_t &r3, uint32_t a){
    asm volatile("ldmatrix.sync.aligned.m8n8.x4.shared.b16 {%0,%1,%2,%3}, [%4];"
        : "=r"(r0), "=r"(r1), "=r"(r2), "=r"(r3) : "r"(a));
}
#define MMA16816(acc, A0,A1,A2,A3, B0,B1) \
    asm volatile("mma.sync.aligned.m16n8k16.row.col.f32.bf16.bf16.f32 " \
        "{%0,%1,%2,%3}, {%4,%5,%6,%7}, {%8,%9}, {%0,%1,%2,%3};" \
        : "+f"(acc[0]), "+f"(acc[1]), "+f"(acc[2]), "+f"(acc[3]) \
        : "r"(A0), "r"(A1), "r"(A2), "r"(A3), "r"(B0), "r"(B1))

__global__ void k_softmax(const float* __restrict__ adj1, const float* __restrict__ adj2){
    int i = threadIdx.x;
    for (int w = 0; w < 2; w++){
        const float* a = w ? adj2 : adj1;
        float* o = w ? g_A2 : g_A1;
        float mx = -1e30f;
        for (int j = 0; j < 64; j++) mx = fmaxf(mx, a[i*64+j]);
        float s = 0.f;
        for (int j = 0; j < 64; j++) s += expf(a[i*64+j] - mx);
        float inv = 1.f / s;
        for (int j = 0; j < 64; j++) o[i*64+j] = expf(a[i*64+j] - mx) * inv;
    }
}

__global__ void k_prepW(const float* __restrict__ W1, const float* __restrict__ W0,
                        const float* __restrict__ Wh0, const float* __restrict__ Wh1){
    for (int i = threadIdx.x; i < 24576; i += 256){
        float v = W1[i];
        __nv_bfloat16 hi = __float2bfloat16(v);
        g_W1hi[i] = hi; g_W1lo[i] = __float2bfloat16(v - __bfloat162float(hi));
    }
    for (int i = threadIdx.x; i < 12288; i += 256){
        float v = W0[i];
        __nv_bfloat16 hi = __float2bfloat16(v);
        g_W0hi[i] = hi; g_W0lo[i] = __float2bfloat16(v - __bfloat162float(hi));
    }
    for (int i = threadIdx.x; i < 24576; i += 256){
        float v = Wh0[i];
        __nv_bfloat16 hi = __float2bfloat16(v);
        g_Wh0hi[i] = hi; g_Wh0lo[i] = __float2bfloat16(v - __bfloat162float(hi));
    }
    for (int i = threadIdx.x; i < 12288; i += 256){
        float v = Wh1[i];
        __nv_bfloat16 hi = __float2bfloat16(v);
        g_Wh1hi[i] = hi; g_Wh1lo[i] = __float2bfloat16(v - __bfloat162float(hi));
    }
}

__global__ __launch_bounds__(256) void k_gnn(
    const float* __restrict__ x,
    const float* __restrict__ W1, const float* __restrict__ b1,
    const float* __restrict__ W2, const float* __restrict__ b2,
    const float* __restrict__ lng, const float* __restrict__ lnb)
{
    int bt = blockIdx.x;
    int b = bt >> 8, t = bt & 255;
    int tid = threadIdx.x;

    __shared__ float sA2[64*65];
    __shared__ float sW2t[1024];
    __shared__ __align__(16) float sx[64];
    __shared__ float s1[64];
    __shared__ __align__(16) float sh1[2048];
    __shared__ __align__(16) float sagg[2048];
    __shared__ float sh2[64*33];
    __shared__ float sW1[32], sb1[32], sb2[32], slg[32], slb[32];
    __shared__ float smean[64], srstd[64];

    for (int i = tid; i < 4096; i += 256) sA2[(i>>6)*65 + (i&63)] = g_A2[i];
    for (int i = tid; i < 1024; i += 256){ int gp = i>>5, k = i&31; sW2t[k*32+gp] = W2[i]; }
    if (tid < 64) sx[tid] = x[(size_t)bt*64 + tid];
    if (tid < 32){ sW1[tid]=W1[tid]; sb1[tid]=b1[tid]; sb2[tid]=b2[tid]; slg[tid]=lng[tid]; slb[tid]=lnb[tid]; }
    __syncthreads();

    if (tid < 64){
        float s = 0.f; const float* a = g_A1 + tid*64;
        #pragma unroll 8
        for (int j = 0; j < 64; j++) s += a[j]*sx[j];
        s1[tid] = s;
    }
    __syncthreads();
    for (int i = tid; i < 2048; i += 256){ int j = i>>5, g = i&31; sh1[i] = fmaxf(sW1[g]*s1[j] + sb1[g], 0.f); }
    __syncthreads();
    {
        int i = tid >> 2, g0 = (tid & 3) * 8;
        float4 a0 = {0,0,0,0}, a1 = {0,0,0,0};
        #pragma unroll 4
        for (int j = 0; j < 64; j++){
            float a = sA2[i*65 + j];
            float4 h0 = *(const float4*)(sh1 + j*32 + g0);
            float4 h1 = *(const float4*)(sh1 + j*32 + g0 + 4);
            a0.x += a*h0.x; a0.y += a*h0.y; a0.z += a*h0.z; a0.w += a*h0.w;
            a1.x += a*h1.x; a1.y += a*h1.y; a1.z += a*h1.z; a1.w += a*h1.w;
        }
        *(float4*)(sagg + i*32 + g0)     = a0;
        *(float4*)(sagg + i*32 + g0 + 4) = a1;
    }
    __syncthreads();
    #pragma unroll
    for (int q = 0; q < 8; q++){
        int idx = tid + (q << 8);
        int i = idx >> 5, gp = idx & 31;
        float acc = sb2[gp];
        #pragma unroll 8
        for (int k = 0; k < 32; k++) acc += sagg[i*32 + k] * sW2t[k*32 + gp];
        sh2[i*33 + gp] = fmaxf(acc, 0.f);
    }
    __syncthreads();
    if (tid < 64){
        float m = 0.f;
        for (int g = 0; g < 32; g++) m += sh2[tid*33 + g];
        m *= (1.f/32.f);
        float v = 0.f;
        for (int g = 0; g < 32; g++){ float d = sh2[tid*33 + g] - m; v += d*d; }
        v *= (1.f/32.f);
        smean[tid] = m; srstd[tid] = rsqrtf(v + 1e-5f);
    }
    __syncthreads();
    for (int idx = tid; idx < 2048; idx += 256){
        int i = idx >> 5, g = idx & 31;
        float val = (sh2[i*33 + g] - smean[i]) * srstd[i] * slg[g] + slb[g];
        size_t o = (((size_t)b*64 + i)*256 + t)*32 + g;
        __nv_bfloat16 hi = __float2bfloat16(val);
        g_hencH[o] = hi;
        g_hencL[o] = __float2bfloat16(val - __bfloat162float(hi));
    }
}

// ---- GRU layer 0: fused input-proj + hidden recurrence; W0-lo in smem ----
__global__ __launch_bounds__(256,2) void k_gru0f(
    const float* __restrict__ bih, const float* __restrict__ bhh)
{
    int n0 = blockIdx.x * 16, dir = blockIdx.y;
    int tid = threadIdx.x, w = tid >> 5, lane = tid & 31;
    int g = lane >> 2, tig = lane & 3;
    __shared__ uint32_t sHx[2][16*36];
    __shared__ uint32_t sXh[2][16*20];
    __shared__ uint32_t sW0loT[16*200];   // [kword][n], stride 200: conflict-free
    __shared__ float sH[16*64];
    __shared__ float sG[16*266];
    __shared__ float sBi[192], sBh[192];

    uint32_t bhi[3][4][2], blo_[3][4][2];
    uint32_t xbh[3][2][2];
    #pragma unroll
    for (int nt = 0; nt < 3; nt++){
        int n = dir*192 + w*24 + nt*8 + g;
        const uint32_t* wp = (const uint32_t*)g_Wh0hi + n*32;
        const uint32_t* wq = (const uint32_t*)g_Wh0lo + n*32;
        #pragma unroll
        for (int kt = 0; kt < 4; kt++){
            bhi[nt][kt][0] = wp[kt*8 + tig];  bhi[nt][kt][1] = wp[kt*8 + 4 + tig];
            blo_[nt][kt][0] = wq[kt*8 + tig]; blo_[nt][kt][1] = wq[kt*8 + 4 + tig];
        }
        const uint32_t* xp = (const uint32_t*)g_W0hi + n*16;
        #pragma unroll
        for (int ks = 0; ks < 2; ks++){
            xbh[nt][ks][0] = xp[ks*8 + tig]; xbh[nt][ks][1] = xp[ks*8 + 4 + tig];
        }
    }
    {
        const uint32_t* xblo = (const uint32_t*)g_W0lo;
        for (int i = tid; i < 3072; i += 256){
            int n = i >> 4, c = i & 15;
            sW0loT[c*200 + n] = xblo[(dir*192 + n)*16 + c];
        }
    }
    if (tid < 192){ sBi[tid] = bih[dir*192 + tid]; sBh[tid] = bhh[dir*192 + tid]; }
    for (int i = tid; i < 16*36; i += 256){ sHx[0][i] = 0u; sHx[1][i] = 0u; }
    for (int i = tid; i < 1024; i += 256) sH[i] = 0.f;

    uint32_t lrow = lane & 15;
    uint32_t khalf = (lane >> 4) * 16;
    uint32_t aH0 = s_u32(&sHx[0][0]) + lrow*144 + khalf;
    uint32_t aH1 = s_u32(&sHx[1][0]) + lrow*144 + khalf;
    uint32_t aX0 = s_u32(&sXh[0][0]) + lrow*80 + khalf;
    uint32_t aX1 = s_u32(&sXh[1][0]) + lrow*80 + khalf;

    int prow = tid >> 4, pc = tid & 15;
    const uint32_t* heH = (const uint32_t*)g_hencH;
    const uint32_t* heL = (const uint32_t*)g_hencL;
    size_t hrow = (size_t)(n0 + prow)*256;
    int t0 = dir ? 255 : 0;
    uint32_t rxh = heH[(hrow + t0)*16 + pc];
    uint32_t rxl = heL[(hrow + t0)*16 + pc];
    __syncthreads();
    sXh[0][prow*20 + pc] = rxh;
    sXh[1][prow*20 + pc] = rxl;
    __syncthreads();
    {
        int t1 = dir ? 254 : 1;
        rxh = heH[(hrow + t1)*16 + pc];
        rxl = heL[(hrow + t1)*16 + pc];
    }

    int q = tid >> 4, pp = tid & 15;
    uint32_t* h0Hu = (uint32_t*)g_h0H;
    uint32_t* h0Lu = (uint32_t*)g_h0L;

    for (int s = 0; s < 256; s++){
        int t = dir ? 255 - s : s;
        float accA[3][4], accB[3][4];
        #pragma unroll
        for (int nt=0;nt<3;nt++){
            accA[nt][0]=0.f; accA[nt][1]=0.f; accA[nt][2]=0.f; accA[nt][3]=0.f;
            accB[nt][0]=0.f; accB[nt][1]=0.f; accB[nt][2]=0.f; accB[nt][3]=0.f;
        }
        #pragma unroll
        for (int kt = 0; kt < 4; kt++){
            uint32_t ah0,ah1,ah2,ah3, al0,al1,al2,al3;
            ldm4(ah0,ah1,ah2,ah3, aH0 + kt*32);
            ldm4(al0,al1,al2,al3, aH1 + kt*32);
            #pragma unroll
            for (int nt = 0; nt < 3; nt++){
                MMA16816(accA[nt], ah0,ah1,ah2,ah3, bhi[nt][kt][0], bhi[nt][kt][1]);
                MMA16816(accA[nt], al0,al1,al2,al3, bhi[nt][kt][0], bhi[nt][kt][1]);
                MMA16816(accA[nt], ah0,ah1,ah2,ah3, blo_[nt][kt][0], blo_[nt][kt][1]);
            }
        }
        #pragma unroll
        for (int ks = 0; ks < 2; ks++){
            uint32_t xh0,xh1,xh2,xh3, xl0,xl1,xl2,xl3;
            ldm4(xh0,xh1,xh2,xh3, aX0 + ks*32);
            ldm4(xl0,xl1,xl2,xl3, aX1 + ks*32);
            #pragma unroll
            for (int nt = 0; nt < 3; nt++){
                int nn = w*24 + nt*8 + g;
                uint32_t bl0 = sW0loT[(ks*8 + tig)*200 + nn];
                uint32_t bl1 = sW0loT[(ks*8 + 4 + tig)*200 + nn];
                MMA16816(accB[nt], xh0,xh1,xh2,xh3, xbh[nt][ks][0], xbh[nt][ks][1]);
                MMA16816(accB[nt], xl0,xl1,xl2,xl3, xbh[nt][ks][0], xbh[nt][ks][1]);
                MMA16816(accB[nt], xh0,xh1,xh2,xh3, bl0, bl1);
            }
        }
        #pragma unroll
        for (int nt = 0; nt < 3; nt++){
            int col = w*24 + nt*8 + tig*2;
            if (col < 128){
                *(float2*)(sG + g*266 + col)     = make_float2(accA[nt][0]+accB[nt][0], accA[nt][1]+accB[nt][1]);
                *(float2*)(sG + (g+8)*266 + col) = make_float2(accA[nt][2]+accB[nt][2], accA[nt][3]+accB[nt][3]);
            } else {
                *(float2*)(sG + g*266 + col)          = make_float2(accA[nt][0], accA[nt][1]);
                *(float2*)(sG + (g+8)*266 + col)      = make_float2(accA[nt][2], accA[nt][3]);
                *(float2*)(sG + g*266 + col + 64)     = make_float2(accB[nt][0], accB[nt][1]);
                *(float2*)(sG + (g+8)*266 + col + 64) = make_float2(accB[nt][2], accB[nt][3]);
            }
        }
        __syncthreads();
        #pragma unroll
        for (int half = 0; half < 2; half++){
            int hb = 2*pp + half*32;
            float hn[2];
            #pragma unroll
            for (int e = 0; e < 2; e++){
                int hh = hb + e;
                float Gr  = sG[q*266 + hh];
                float Gz  = sG[q*266 + 64 + hh];
                float Gnh = sG[q*266 + 128 + hh];
                float Gnx = sG[q*266 + 192 + hh];
                float r  = sigf(Gr + sBi[hh] + sBh[hh]);
                float z  = sigf(Gz + sBi[64+hh] + sBh[64+hh]);
                float nn = tanf_(Gnx + sBi[128+hh] + r*(Gnh + sBh[128+hh]));
                hn[e] = (1.f - z)*nn + z*sH[q*64 + hh];
                sH[q*64 + hh] = hn[e];
            }
            __nv_bfloat16 h0h = __float2bfloat16(hn[0]);
            __nv_bfloat16 h1h = __float2bfloat16(hn[1]);
            __nv_bfloat16 h0l = __float2bfloat16(hn[0] - __bfloat162float(h0h));
            __nv_bfloat16 h1l = __float2bfloat16(hn[1] - __bfloat162float(h1h));
            uint32_t hip, lop;
            asm("mov.b32 %0, {%1,%2};" : "=r"(hip) : "h"(*(unsigned short*)&h0h), "h"(*(unsigned short*)&h1h));
            asm("mov.b32 %0, {%1,%2};" : "=r"(lop) : "h"(*(unsigned short*)&h0l), "h"(*(unsigned short*)&h1l));
            int pcol = pp + half*16;
            sHx[0][q*36 + pcol] = hip;
            sHx[1][q*36 + pcol] = lop;
            size_t oidx = ((size_t)(n0+q)*256 + t)*64 + dir*32 + pcol;
            h0Hu[oidx] = hip; h0Lu[oidx] = lop;
        }
        if (s < 255){
            sXh[0][prow*20 + pc] = rxh;
            sXh[1][prow*20 + pc] = rxl;
            if (s < 254){
                int tn2 = dir ? 253 - s : s + 2;
                rxh = heH[(hrow + tn2)*16 + pc];
                rxl = heL[(hrow + tn2)*16 + pc];
            }
        }
        __syncthreads();
    }
}

// ---- mma GEMM: xg1 = h0 @ Wih1^T; A double-buffered, B-lo in smem ----
__global__ __launch_bounds__(256,2) void k_xproj1(){
    extern __shared__ uint32_t dynx[];
    uint32_t* sA0 = dynx;                 // 16*68
    uint32_t* sA1 = dynx + 1088;          // 16*68
    uint32_t* sBloT = dynx + 2176;        // [kword 0..63][n 0..191], stride 200

    int tid = threadIdx.x;
    int w = tid >> 5, lane = tid & 31;
    int g = lane >> 2, tig = lane & 3;
    size_t Rbase = (size_t)blockIdx.x * 1024;

    uint32_t bh[3][8][2];
    #pragma unroll
    for (int nt = 0; nt < 3; nt++){
        int n = w*24 + nt*8 + g;
        const uint32_t* wp = (const uint32_t*)g_W1hi + n*64;
        #pragma unroll
        for (int ks = 0; ks < 8; ks++){
            bh[nt][ks][0] = wp[ks*8 + tig];
            bh[nt][ks][1] = wp[ks*8 + 4 + tig];
        }
    }
    {
        const uint32_t* blo = (const uint32_t*)g_W1lo;
        for (int i = tid; i < 12288; i += 256){
            int n = i >> 6, c = i & 63;
            sBloT[c*200 + n] = blo[i];
        }
    }
    const uint4* h0Hu = (const uint4*)g_h0H;
    const uint4* h0Lu = (const uint4*)g_h0L;

    uint32_t lrow = lane & 15;
    uint32_t khalf = (lane >> 4) * 16;
    uint32_t aB0 = s_u32(sA0) + lrow*272 + khalf;
    uint32_t aB1 = s_u32(sA1) + lrow*272 + khalf;

    int prow = tid >> 4, pc4 = tid & 15;
    uint4 rh = h0Hu[(Rbase + prow)*16 + pc4];
    uint4 rl = h0Lu[(Rbase + prow)*16 + pc4];

    for (int mt = 0; mt < 64; mt++){
        size_t R = Rbase + mt*16;
        __syncthreads();
        {
            int c0 = pc4*4;
            sA0[prow*68 + c0]   = rh.x; sA0[prow*68 + c0+1] = rh.y;
            sA0[prow*68 + c0+2] = rh.z; sA0[prow*68 + c0+3] = rh.w;
            sA1[prow*68 + c0]   = rl.x; sA1[prow*68 + c0+1] = rl.y;
            sA1[prow*68 + c0+2] = rl.z; sA1[prow*68 + c0+3] = rl.w;
        }
        __syncthreads();
        if (mt < 63){
            rh = h0Hu[(R + 16 + prow)*16 + pc4];
            rl = h0Lu[(R + 16 + prow)*16 + pc4];
        }
        float acc[3][4];
        #pragma unroll
        for (int nt=0;nt<3;nt++){ acc[nt][0]=0.f; acc[nt][1]=0.f; acc[nt][2]=0.f; acc[nt][3]=0.f; }
        #pragma unroll
        for (int term = 0; term < 3; term++){
            uint32_t abase = (term == 1) ? aB1 : aB0;
            #pragma unroll
            for (int ks = 0; ks < 8; ks++){
                uint32_t a0,a1,a2,a3;
                ldm4(a0,a1,a2,a3, abase + ks*32);
                #pragma unroll
                for (int nt = 0; nt < 3; nt++){
                    uint32_t b0, b1;
                    if (term < 2){ b0 = bh[nt][ks][0]; b1 = bh[nt][ks][1]; }
                    else {
                        int n = w*24 + nt*8 + g;
                        b0 = sBloT[(ks*8 + tig)*200 + n];
                        b1 = sBloT[(ks*8 + 4 + tig)*200 + n];
                    }
                    MMA16816(acc[nt], a0,a1,a2,a3, b0,b1);
                }
            }
        }
        #pragma unroll
        for (int nt = 0; nt < 3; nt++){
            int col = w*24 + nt*8 + tig*2;
            *(float2*)(g_xg1 + (R+g)*192 + col)   = make_float2(acc[nt][0], acc[nt][1]);
            *(float2*)(g_xg1 + (R+g+8)*192 + col) = make_float2(acc[nt][2], acc[nt][3]);
        }
    }
}

// ---- GRU layer 1 fwd hidden recurrence, ldmatrix A-frags ----
__global__ __launch_bounds__(256,2) void k_gru1m(
    const float* __restrict__ bih, const float* __restrict__ bhh)
{
    int n0 = blockIdx.x * 16;
    int tid = threadIdx.x, w = tid >> 5, lane = tid & 31;
    int g = lane >> 2, tig = lane & 3;
    __shared__ uint32_t sHx[2][16*36];
    __shared__ float sH[16*64];
    __shared__ float sG[16*200];
    __shared__ float sBi[192], sBh[192];

    uint32_t bhi[3][4][2], blo_[3][4][2];
    #pragma unroll
    for (int nt = 0; nt < 3; nt++){
        int n = w*24 + nt*8 + g;
        const uint32_t* wp = (const uint32_t*)g_Wh1hi + n*32;
        const uint32_t* wq = (const uint32_t*)g_Wh1lo + n*32;
        #pragma unroll
        for (int kt = 0; kt < 4; kt++){
            bhi[nt][kt][0] = wp[kt*8 + tig];  bhi[nt][kt][1] = wp[kt*8 + 4 + tig];
            blo_[nt][kt][0] = wq[kt*8 + tig]; blo_[nt][kt][1] = wq[kt*8 + 4 + tig];
        }
    }
    if (tid < 192){ sBi[tid] = bih[tid]; sBh[tid] = bhh[tid]; }
    for (int i = tid; i < 16*36; i += 256){ sHx[0][i] = 0u; sHx[1][i] = 0u; }
    for (int i = tid; i < 1024; i += 256) sH[i] = 0.f;
    __syncthreads();

    uint32_t lrow = lane & 15;
    uint32_t khalf = (lane >> 4) * 16;
    uint32_t aH0 = s_u32(&sHx[0][0]) + lrow*144 + khalf;
    uint32_t aH1 = s_u32(&sHx[1][0]) + lrow*144 + khalf;

    int q = tid >> 4, pp = tid & 15;
    const float* xgb = g_xg1 + (size_t)(n0 + q)*256*192;
    float2 xr0, xr1, xr2, xr3, xr4, xr5;
    {
        const float* xp = xgb;
        xr0 = *(const float2*)(xp + 2*pp);        xr1 = *(const float2*)(xp + 64 + 2*pp);
        xr2 = *(const float2*)(xp + 128 + 2*pp);  xr3 = *(const float2*)(xp + 32 + 2*pp);
        xr4 = *(const float2*)(xp + 96 + 2*pp);   xr5 = *(const float2*)(xp + 160 + 2*pp);
    }

    for (int s = 0; s < 256; s++){
        float acc[3][4];
        #pragma unroll
        for (int nt=0;nt<3;nt++){ acc[nt][0]=0.f; acc[nt][1]=0.f; acc[nt][2]=0.f; acc[nt][3]=0.f; }
        #pragma unroll
        for (int kt = 0; kt < 4; kt++){
            uint32_t ah0,ah1,ah2,ah3, al0,al1,al2,al3;
            ldm4(ah0,ah1,ah2,ah3, aH0 + kt*32);
            ldm4(al0,al1,al2,al3, aH1 + kt*32);
            #pragma unroll
            for (int nt = 0; nt < 3; nt++){
                MMA16816(acc[nt], ah0,ah1,ah2,ah3, bhi[nt][kt][0], bhi[nt][kt][1]);
                MMA16816(acc[nt], al0,al1,al2,al3, bhi[nt][kt][0], bhi[nt][kt][1]);
                MMA16816(acc[nt], ah0,ah1,ah2,ah3, blo_[nt][kt][0], blo_[nt][kt][1]);
            }
        }
        #pragma unroll
        for (int nt = 0; nt < 3; nt++){
            int col = w*24 + nt*8 + tig*2;
            *(float2*)(sG + g*200 + col)     = make_float2(acc[nt][0], acc[nt][1]);
            *(float2*)(sG + (g+8)*200 + col) = make_float2(acc[nt][2], acc[nt][3]);
        }
        __syncthreads();
        #pragma unroll
        for (int half = 0; half < 2; half++){
            int hb = 2*pp + half*32;
            float2 xrr = half ? xr3 : xr0;
            float2 xrz = half ? xr4 : xr1;
            float2 xrn = half ? xr5 : xr2;
            float hn[2];
            #pragma unroll
            for (int e = 0; e < 2; e++){
                int hh = hb + e;
                float Gr = sG[q*200 + hh], Gz = sG[q*200 + 64 + hh], Gn = sG[q*200 + 128 + hh];
                float xv_r = e ? xrr.y : xrr.x;
                float xv_z = e ? xrz.y : xrz.x;
                float xv_n = e ? xrn.y : xrn.x;
                float r  = sigf(xv_r + sBi[hh] + Gr + sBh[hh]);
                float z  = sigf(xv_z + sBi[64+hh] + Gz + sBh[64+hh]);
                float nn = tanf_(xv_n + sBi[128+hh] + r*(Gn + sBh[128+hh]));
                hn[e] = (1.f - z)*nn + z*sH[q*64 + hh];
                sH[q*64 + hh] = hn[e];
                if (s == 255) g_last[(n0+q)*128 + hh] = hn[e];
            }
            __nv_bfloat16 h0h = __float2bfloat16(hn[0]);
            __nv_bfloat16 h1h = __float2bfloat16(hn[1]);
            __nv_bfloat16 h0l = __float2bfloat16(hn[0] - __bfloat162float(h0h));
            __nv_bfloat16 h1l = __float2bfloat16(hn[1] - __bfloat162float(h1h));
            uint32_t hip, lop;
            asm("mov.b32 %0, {%1,%2};" : "=r"(hip) : "h"(*(unsigned short*)&h0h), "h"(*(unsigned short*)&h1h));
            asm("mov.b32 %0, {%1,%2};" : "=r"(lop) : "h"(*(unsigned short*)&h0l), "h"(*(unsigned short*)&h1l));
            int pcol = pp + half*16;
            sHx[0][q*36 + pcol] = hip;
            sHx[1][q*36 + pcol] = lop;
        }
        if (s < 255){
            const float* xp = xgb + (size_t)(s+1)*192;
            xr0 = *(const float2*)(xp + 2*pp);        xr1 = *(const float2*)(xp + 64 + 2*pp);
            xr2 = *(const float2*)(xp + 128 + 2*pp);  xr3 = *(const float2*)(xp + 32 + 2*pp);
            xr4 = *(const float2*)(xp + 96 + 2*pp);   xr5 = *(const float2*)(xp + 160 + 2*pp);
        }
        __syncthreads();
    }
}

__global__ __launch_bounds__(192,2) void k_gru1b(
    const float* __restrict__ Wih, const float* __restrict__ Whh,
    const float* __restrict__ bih, const float* __restrict__ bhh)
{
    int tid = threadIdx.x;
    __shared__ __align__(16) float sx[128];
    __shared__ float sgi[192];
    ull w[64];
    const ull* p = (const ull*)(Wih + 192UL*128 + (size_t)tid*128);
    #pragma unroll
    for (int k = 0; k < 64; k++) w[k] = p[k];
    float bias = bih[192 + tid];

    for (int it = 0; it < 64; it++){
        int n = blockIdx.x*64 + it;
        if (tid < 128){
            size_t idx = ((size_t)n*256 + 255)*128 + tid;
            sx[tid] = __bfloat162float(g_h0H[idx]) + __bfloat162float(g_h0L[idx]);
        }
        __syncthreads();
        ull a0 = 0, a1 = 0;
        const ulonglong2* v4 = (const ulonglong2*)sx;
        #pragma unroll
        for (int k = 0; k < 32; k++){ ulonglong2 v = v4[k]; fma2(a0, w[2*k], v.x); fma2(a1, w[2*k+1], v.y); }
        sgi[tid] = hsum2(a0) + hsum2(a1) + bias;
        __syncthreads();
        if (tid < 64){
            float r  = sigf(sgi[tid]      + bhh[192 + tid]);
            float z  = sigf(sgi[64 + tid] + bhh[192 + 64 + tid]);
            float nn = tanf_(sgi[128+tid] + r * bhh[192 + 128 + tid]);
            g_last[n*128 + 64 + tid] = (1.f - z)*nn;
        }
    }
}

__global__ __launch_bounds__(128) void k_head(
    const float* __restrict__ pool_W, const float* __restrict__ pool_b,
    const float* __restrict__ mu_W, const float* __restrict__ mu_b,
    const float* __restrict__ logv_W, const float* __restrict__ logv_b,
    const float* __restrict__ dec_W, const float* __restrict__ dec_b,
    const float* __restrict__ lstm_Wih, const float* __restrict__ lstm_bih,
    const float* __restrict__ lstm_bhh,
    float* __restrict__ out)
{
    int b = blockIdx.x, tid = threadIdx.x;
    __shared__ float slast[128], shp[32], smu[32], sdh[64];
    float s = 0.f;
    for (int c = 0; c < 64; c++) s += g_last[(b*64 + c)*128 + tid];
    slast[tid] = s * (1.f/64.f);
    __syncthreads();
    if (tid < 32){
        float acc = pool_b[tid];
        for (int k = 0; k < 128; k++) acc += pool_W[tid*128 + k] * slast[k];
        shp[tid] = fmaxf(acc, 0.f);
    }
    __syncthreads();
    if (tid < 32){
        float acc = mu_b[tid];
        for (int k = 0; k < 32; k++) acc += mu_W[tid*32 + k] * shp[k];
        smu[tid] = acc;
        out[64UL*256*64 + b*32 + tid] = acc;
    } else if (tid < 64){
        int j = tid - 32;
        float acc = logv_b[j];
        for (int k = 0; k < 32; k++) acc += logv_W[j*32 + k] * shp[k];
        out[64UL*256*64 + 2048 + b*32 + j] = acc;
    }
    __syncthreads();
    if (tid < 64){
        float acc = dec_b[tid];
        for (int k = 0; k < 32; k++) acc += dec_W[tid*32 + k] * smu[k];
        sdh[tid] = fmaxf(acc, 0.f);
    }
    __syncthreads();
    for (int gate = tid; gate < 256; gate += 128){
        float acc = lstm_bih[gate] + lstm_bhh[gate];
        for (int k = 0; k < 64; k++) acc += lstm_Wih[gate*64 + k] * sdh[k];
        g_dxg[b*256 + gate] = acc;
    }
}

__global__ __launch_bounds__(256,1) void k_lstm1(const float* __restrict__ Whh)
{
    int b = blockIdx.x, tid = threadIdx.x;
    __shared__ __align__(16) float sh[64];
    __shared__ float sg[256];
    ull w[32];
    const ull* p = (const ull*)(Whh + (size_t)tid*64);
    #pragma unroll
    for (int k = 0; k < 32; k++) w[k] = p[k];
    float dxg = g_dxg[b*256 + tid];
    if (tid < 64) sh[tid] = 0.f;
    float c = 0.f;
    for (int t = 0; t < 256; t++){
        __syncthreads();
        ull a0 = 0, a1 = 0;
        const ulonglong2* v4 = (const ulonglong2*)sh;
        #pragma unroll
        for (int k = 0; k < 16; k++){ ulonglong2 v = v4[k]; fma2(a0, w[2*k], v.x); fma2(a1, w[2*k+1], v.y); }
        sg[tid] = hsum2(a0) + hsum2(a1) + dxg;
        __syncthreads();
        if (tid < 64){
            float i_ = sigf(sg[tid]), f_ = sigf(sg[64+tid]);
            float gg = tanf_(sg[128+tid]), o_ = sigf(sg[192+tid]);
            c = f_*c + i_*gg;
            float h = o_*tanf_(c);
            sh[tid] = h;
            g_h1d[((size_t)b*256 + t)*64 + tid] = h;
        }
    }
}

__global__ __launch_bounds__(256,1) void k_lstm2(
    const float* __restrict__ Wih, const float* __restrict__ Whh,
    const float* __restrict__ bih, const float* __restrict__ bhh,
    const float* __restrict__ out_W, const float* __restrict__ out_b,
    float* __restrict__ out)
{
    int b = blockIdx.x, tid = threadIdx.x;
    __shared__ __align__(16) float sx[64];
    __shared__ __align__(16) float sh[64];
    __shared__ float sg[256];
    __shared__ float soW[64*64];
    for (int i = tid; i < 4096; i += 256){ int c = i >> 6, k = i & 63; soW[k*64 + c] = out_W[i]; }
    ull wi[32], wh[32];
    const ull* p = (const ull*)(Wih + 256UL*64 + (size_t)tid*64);
    const ull* q = (const ull*)(Whh + 256UL*64 + (size_t)tid*64);
    #pragma unroll
    for (int k = 0; k < 32; k++){ wi[k] = p[k]; wh[k] = q[k]; }
    float bias = bih[256 + tid] + bhh[256 + tid];
    if (tid < 64) sh[tid] = 0.f;
    float c = 0.f;
    float ob = (tid >= 64 && tid < 128) ? out_b[tid - 64] : 0.f;
    const float* xb = g_h1d + (size_t)b*256*64;
    for (int t = 0; t < 256; t++){
        if (tid < 64) sx[tid] = xb[t*64 + tid];
        __syncthreads();
        ull a0 = 0, a1 = 0;
        const ulonglong2* x4 = (const ulonglong2*)sx;
        const ulonglong2* h4 = (const ulonglong2*)sh;
        #pragma unroll
        for (int k = 0; k < 16; k++){ ulonglong2 v = x4[k]; fma2(a0, wi[2*k], v.x); fma2(a1, wi[2*k+1], v.y); }
        #pragma unroll
        for (int k = 0; k < 16; k++){ ulonglong2 v = h4[k]; fma2(a0, wh[2*k], v.x); fma2(a1, wh[2*k+1], v.y); }
        sg[tid] = hsum2(a0) + hsum2(a1) + bias;
        __syncthreads();
        if (tid < 64){
            float i_ = sigf(sg[tid]), f_ = sigf(sg[64+tid]);
            float gg = tanf_(sg[128+tid]), o_ = sigf(sg[192+tid]);
            c = f_*c + i_*gg;
            sh[tid] = o_*tanf_(c);
        }
        __syncthreads();
        if (tid >= 64 && tid < 128){
            int cc = tid - 64;
            float acc = ob;
            #pragma unroll 8
            for (int k = 0; k < 64; k++) acc += soW[k*64 + cc] * sh[k];
            out[((size_t)b*256 + t)*64 + cc] = acc;
        }
    }
}

extern "C" void kernel_launch(void* const* d_in, const int* in_sizes, int n_in,
                              void* d_out, int out_size)
{
    const float* x      = (const float*)d_in[0];
    const float* adj1   = (const float*)d_in[1];
    const float* W1     = (const float*)d_in[2];
    const float* b1     = (const float*)d_in[3];
    const float* adj2   = (const float*)d_in[4];
    const float* W2     = (const float*)d_in[5];
    const float* b2     = (const float*)d_in[6];
    const float* ln_g   = (const float*)d_in[7];
    const float* ln_b   = (const float*)d_in[8];
    const float* g0Wih  = (const float*)d_in[9];
    const float* g0Whh  = (const float*)d_in[10];
    const float* g0bih  = (const float*)d_in[11];
    const float* g0bhh  = (const float*)d_in[12];
    const float* g1Wih  = (const float*)d_in[13];
    const float* g1Whh  = (const float*)d_in[14];
    const float* g1bih  = (const float*)d_in[15];
    const float* g1bhh  = (const float*)d_in[16];
    const float* pool_W = (const float*)d_in[17];
    const float* pool_b = (const float*)d_in[18];
    const float* mu_W   = (const float*)d_in[19];
    const float* mu_b   = (const float*)d_in[20];
    const float* logv_W = (const float*)d_in[21];
    const float* logv_b = (const float*)d_in[22];
    const float* dec_W  = (const float*)d_in[23];
    const float* dec_b  = (const float*)d_in[24];
    const float* lWih   = (const float*)d_in[25];
    const float* lWhh   = (const float*)d_in[26];
    const float* lbih   = (const float*)d_in[27];
    const float* lbhh   = (const float*)d_in[28];
    const float* out_W  = (const float*)d_in[29];
    const float* out_b  = (const float*)d_in[30];
    float* out = (float*)d_out;

    cudaFuncSetAttribute(k_xproj1, cudaFuncAttributeMaxDynamicSharedMemorySize, 59904);

    k_softmax<<<1, 64>>>(adj1, adj2);
    k_prepW<<<1, 256>>>(g1Wih, g0Wih, g0Whh, g1Whh);
    k_gnn<<<16384, 256>>>(x, W1, b1, W2, b2, ln_g, ln_b);
    k_gru0f<<<dim3(256, 2), 256>>>(g0bih, g0bhh);
    k_xproj1<<<1024, 256, 59904>>>();
    k_gru1m<<<256, 256>>>(g1bih, g1bhh);
    k_gru1b<<<64, 192>>>(g1Wih, g1Whh, g1bih, g1bhh);
    k_head<<<64, 128>>>(pool_W, pool_b, mu_W, mu_b, logv_W, logv_b,
                        dec_W, dec_b, lWih, lbih, lbhh, out);
    k_lstm1<<<64, 256>>>(lWhh);
    k_lstm2<<<64, 256>>>(lWih, lWhh, lbih, lbhh, out_W, out_b, out);
}